// round 7
// baseline (speedup 1.0000x reference)
#include <cuda_runtime.h>
#include <cuda_bf16.h>
#include <math.h>
#include <stdint.h>

// ---------------------------------------------------------------------------
// TransformerBlock  B=2, L=2048, D=2048, H=16, DH=128, DFF=8192
// Round 6: fused QKV GEMM (one launch, 768 CTAs), 3-pass independent-MMA
// ordering in all split GEMMs, reversed attention CTA order.
// ---------------------------------------------------------------------------

#define KB   2
#define KL   2048
#define KD   2048
#define KH   16
#define KDH  128
#define KDFF 8192
#define KM   (KB * KL)   // 4096 rows

// ----------------------------- PTX helpers --------------------------------
__device__ __forceinline__ uint32_t smem_u32(const void* p) {
    uint32_t a;
    asm("{ .reg .u64 t; cvta.to.shared.u64 t, %1; cvt.u32.u64 %0, t; }"
        : "=r"(a) : "l"(p));
    return a;
}

#define SWZ64(off)  ((off) ^ (((off) >> 3) & 0x30))   // 64B rows
#define SWZ128(off) ((off) ^ (((off) >> 3) & 0x70))   // 128B rows
#define SWZ256(off) ((off) ^ (((off) >> 4) & 0x70))   // 256B rows

#define CP_ASYNC16(smem, gptr) \
    asm volatile("cp.async.cg.shared.global [%0], [%1], 16;" \
        :: "r"((uint32_t)(smem)), "l"(gptr) : "memory")
#define CP_COMMIT() asm volatile("cp.async.commit_group;" ::: "memory")
#define CP_WAIT2()  asm volatile("cp.async.wait_group 2;" ::: "memory")

#define LDSM_X4(r, addr) \
    asm volatile("ldmatrix.sync.aligned.m8n8.x4.shared.b16 {%0,%1,%2,%3}, [%4];" \
        : "=r"((r)[0]), "=r"((r)[1]), "=r"((r)[2]), "=r"((r)[3]) \
        : "r"((uint32_t)(addr)))

__device__ __forceinline__ void mma_bf16(float* c, const uint32_t* a,
                                         uint32_t b0, uint32_t b1) {
    asm volatile(
        "mma.sync.aligned.m16n8k16.row.col.f32.bf16.bf16.f32 "
        "{%0,%1,%2,%3}, {%4,%5,%6,%7}, {%8,%9}, {%0,%1,%2,%3};"
        : "+f"(c[0]), "+f"(c[1]), "+f"(c[2]), "+f"(c[3])
        : "r"(a[0]), "r"(a[1]), "r"(a[2]), "r"(a[3]), "r"(b0), "r"(b1));
}

__device__ __forceinline__ void split2(float v, __nv_bfloat16& h, __nv_bfloat16& l) {
    h = __float2bfloat16(v);
    l = __float2bfloat16(v - __bfloat162float(h));
}
__device__ __forceinline__ uint32_t pack_bf16(float a, float b) {
    __nv_bfloat162 t = __floats2bfloat162_rn(a, b);
    return *(uint32_t*)&t;
}

// ------------------------------- scratch ----------------------------------
__device__ __nv_bfloat16 g_wq_h[(size_t)KD * KD];
__device__ __nv_bfloat16 g_wq_l[(size_t)KD * KD];
__device__ __nv_bfloat16 g_wk_h[(size_t)KD * KD];
__device__ __nv_bfloat16 g_wk_l[(size_t)KD * KD];
__device__ __nv_bfloat16 g_wv_h[(size_t)KD * KD];
__device__ __nv_bfloat16 g_wv_l[(size_t)KD * KD];
__device__ __nv_bfloat16 g_wo_h[(size_t)KD * KD];
__device__ __nv_bfloat16 g_wo_l[(size_t)KD * KD];
__device__ __nv_bfloat16 g_wu_h[(size_t)KDFF * KD];
__device__ __nv_bfloat16 g_wu_l[(size_t)KDFF * KD];
__device__ __nv_bfloat16 g_wd_h[(size_t)KD * KDFF];
__device__ __nv_bfloat16 g_wd_l[(size_t)KD * KDFF];
__device__ __nv_bfloat16 g_h_h[(size_t)KM * KD];
__device__ __nv_bfloat16 g_h_l[(size_t)KM * KD];
__device__ __nv_bfloat16 g_q_h[(size_t)KM * KD];
__device__ __nv_bfloat16 g_q_l[(size_t)KM * KD];
__device__ __nv_bfloat16 g_k_h[(size_t)KM * KD];
__device__ __nv_bfloat16 g_k_l[(size_t)KM * KD];
__device__ __nv_bfloat16 g_v_h[(size_t)KM * KD];
__device__ __nv_bfloat16 g_v_l[(size_t)KM * KD];
__device__ __nv_bfloat16 g_o_h[(size_t)KM * KD];
__device__ __nv_bfloat16 g_o_l[(size_t)KM * KD];
__device__ __nv_bfloat16 g_u_h[(size_t)KM * KDFF];
__device__ __nv_bfloat16 g_u_l[(size_t)KM * KDFF];

// ---------------------------------------------------------------------------
// weight split
// ---------------------------------------------------------------------------
__global__ __launch_bounds__(256) void split_kernel(
    const float* __restrict__ src, __nv_bfloat16* __restrict__ hi,
    __nv_bfloat16* __restrict__ lo, int n4)
{
    int i = blockIdx.x * 256 + threadIdx.x;
    if (i >= n4) return;
    float4 v = ((const float4*)src)[i];
    __nv_bfloat16 h[4], l[4];
    split2(v.x, h[0], l[0]); split2(v.y, h[1], l[1]);
    split2(v.z, h[2], l[2]); split2(v.w, h[3], l[3]);
    ((uint2*)hi)[i] = *(uint2*)h;
    ((uint2*)lo)[i] = *(uint2*)l;
}

// ---------------------------------------------------------------------------
// RMSNorm with fused hi/lo split output
// ---------------------------------------------------------------------------
__global__ __launch_bounds__(256) void rmsnorm_split_kernel(
    const float* __restrict__ x, const float* __restrict__ w,
    __nv_bfloat16* __restrict__ yh, __nv_bfloat16* __restrict__ yl)
{
    int row = blockIdx.x;
    const float* xr = x + (size_t)row * KD;
    float s = 0.f;
    #pragma unroll
    for (int i = threadIdx.x; i < KD; i += 256) { float v = xr[i]; s += v * v; }
    __shared__ float red[256];
    red[threadIdx.x] = s;
    __syncthreads();
    #pragma unroll
    for (int st = 128; st > 0; st >>= 1) {
        if (threadIdx.x < st) red[threadIdx.x] += red[threadIdx.x + st];
        __syncthreads();
    }
    float inv = rsqrtf(red[0] * (1.0f / KD) + 1e-8f);
    #pragma unroll
    for (int i = threadIdx.x; i < KD; i += 256) {
        float v = xr[i] * inv * w[i];
        __nv_bfloat16 h, l;
        split2(v, h, l);
        yh[(size_t)row * KD + i] = h;
        yl[(size_t)row * KD + i] = l;
    }
}

// ---------------------------------------------------------------------------
// GEMM tiles / pipeline constants
// ---------------------------------------------------------------------------
#define TM 128
#define TN 256
#define TKC 32
#define ASPLIT 8192u
#define BSPLIT 16384u
#define STAGE  (2u*ASPLIT + 2u*BSPLIT)   // 49152
#define NSTAGE 4
#define GEMM_SMEM (NSTAGE * STAGE)       // 196608

// mainloop body shared by both GEMM kernels ---------------------------------
#define GEMM_MAINLOOP(AhP, AlP, BhP, BlP, bmE, bnE, KE, NCE)                    \
    auto load_stage = [&](int c, int s) {                                       \
        const int kc = c * TKC;                                                 \
        const uint32_t base = sb + (uint32_t)s * STAGE;                         \
        _Pragma("unroll")                                                       \
        for (int i = 0; i < 2; i++) {                                           \
            int chunk = i * 256 + tid;                                          \
            int r = chunk >> 2, cc = chunk & 3;                                 \
            uint32_t so = SWZ64((uint32_t)(r * 64 + cc * 16));                  \
            size_t go = (size_t)((bmE) + r) * (KE) + kc + cc * 8;               \
            CP_ASYNC16(base + so,           (AhP) + go);                        \
            CP_ASYNC16(base + ASPLIT + so,  (AlP) + go);                        \
        }                                                                       \
        _Pragma("unroll")                                                       \
        for (int i = 0; i < 4; i++) {                                           \
            int chunk = i * 256 + tid;                                          \
            int r = chunk >> 2, cc = chunk & 3;                                 \
            uint32_t so = SWZ64((uint32_t)(r * 64 + cc * 16));                  \
            size_t go = (size_t)((bnE) + r) * (KE) + kc + cc * 8;               \
            CP_ASYNC16(base + 2u*ASPLIT + so,          (BhP) + go);             \
            CP_ASYNC16(base + 2u*ASPLIT + BSPLIT + so, (BlP) + go);             \
        }                                                                       \
        CP_COMMIT();                                                            \
    };                                                                          \
    load_stage(0, 0);                                                           \
    load_stage(1, 1);                                                           \
    load_stage(2, 2);                                                           \
    _Pragma("unroll 1")                                                         \
    for (int c = 0; c < (NCE); c++) {                                           \
        const int s = c & 3;                                                    \
        CP_WAIT2();                                                             \
        __syncthreads();                                                        \
        if (c + 3 < (NCE)) load_stage(c + 3, (c + 3) & 3);                      \
        const uint32_t sAh = sb + (uint32_t)s * STAGE;                          \
        const uint32_t sAl = sAh + ASPLIT;                                      \
        const uint32_t sBh = sAl + ASPLIT;                                      \
        const uint32_t sBl = sBh + BSPLIT;                                      \
        _Pragma("unroll")                                                       \
        for (int h = 0; h < 2; h++) {                                           \
            uint32_t afh[4][4], afl[4][4], bfh[4][4], bfl[4][4];                \
            _Pragma("unroll")                                                   \
            for (int mi = 0; mi < 4; mi++) {                                    \
                int m = wm * 64 + mi * 16 + rowA;                               \
                uint32_t off = SWZ64((uint32_t)(m * 64 + (h * 2 + kA) * 16));   \
                LDSM_X4(afh[mi], sAh + off);                                    \
                LDSM_X4(afl[mi], sAl + off);                                    \
            }                                                                   \
            _Pragma("unroll")                                                   \
            for (int nj = 0; nj < 4; nj++) {                                    \
                int n = wn * 64 + nj * 16 + rowB;                               \
                uint32_t off = SWZ64((uint32_t)(n * 64 + (h * 2 + kB) * 16));   \
                LDSM_X4(bfh[nj], sBh + off);                                    \
                LDSM_X4(bfl[nj], sBl + off);                                    \
            }                                                                   \
            /* pass 1: Ah*Bh — 32 independent MMAs */                           \
            _Pragma("unroll")                                                   \
            for (int mi = 0; mi < 4; mi++)                                      \
                _Pragma("unroll")                                               \
                for (int nj = 0; nj < 4; nj++)                                  \
                    _Pragma("unroll")                                           \
                    for (int hf = 0; hf < 2; hf++)                              \
                        mma_bf16(acc[mi][nj*2+hf], afh[mi],                     \
                                 bfh[nj][hf*2], bfh[nj][hf*2+1]);               \
            /* pass 2: Ah*Bl */                                                 \
            _Pragma("unroll")                                                   \
            for (int mi = 0; mi < 4; mi++)                                      \
                _Pragma("unroll")                                               \
                for (int nj = 0; nj < 4; nj++)                                  \
                    _Pragma("unroll")                                           \
                    for (int hf = 0; hf < 2; hf++)                              \
                        mma_bf16(acc[mi][nj*2+hf], afh[mi],                     \
                                 bfl[nj][hf*2], bfl[nj][hf*2+1]);               \
            /* pass 3: Al*Bh */                                                 \
            _Pragma("unroll")                                                   \
            for (int mi = 0; mi < 4; mi++)                                      \
                _Pragma("unroll")                                               \
                for (int nj = 0; nj < 4; nj++)                                  \
                    _Pragma("unroll")                                           \
                    for (int hf = 0; hf < 2; hf++)                              \
                        mma_bf16(acc[mi][nj*2+hf], afl[mi],                     \
                                 bfh[nj][hf*2], bfh[nj][hf*2+1]);               \
        }                                                                       \
    }

// ---------------------------------------------------------------------------
// General split GEMM.  EPI: 0 fp32 C, 1 GELU->hi/lo, 2 C=R+acc, 3 hi/lo
// ---------------------------------------------------------------------------
template<int EPI>
__global__ __launch_bounds__(256, 1) void gemm_mma_kernel(
    const __nv_bfloat16* __restrict__ Ah, const __nv_bfloat16* __restrict__ Al,
    const __nv_bfloat16* __restrict__ Bh, const __nv_bfloat16* __restrict__ Bl,
    float* __restrict__ C, const float* __restrict__ R,
    __nv_bfloat16* __restrict__ Chi, __nv_bfloat16* __restrict__ Clo,
    int N, int K)
{
    extern __shared__ char smem[];
    const uint32_t sb = smem_u32(smem);
    const int tid  = threadIdx.x;
    const int wid  = tid >> 5;
    const int lane = tid & 31;
    const int wm   = wid & 1;
    const int wn   = wid >> 1;
    const int bm   = blockIdx.y * TM;
    const int bn   = blockIdx.x * TN;
    const int NC   = K / TKC;

    const int mat  = lane >> 3;
    const int rin  = lane & 7;
    const int rowA = (mat & 1) * 8 + rin;
    const int kA   = mat >> 1;
    const int rowB = (mat >> 1) * 8 + rin;
    const int kB   = mat & 1;

    float acc[4][8][4];
    #pragma unroll
    for (int i = 0; i < 4; i++)
        #pragma unroll
        for (int j = 0; j < 8; j++)
            #pragma unroll
            for (int t = 0; t < 4; t++) acc[i][j][t] = 0.f;

    GEMM_MAINLOOP(Ah, Al, Bh, Bl, bm, bn, K, NC)

    #pragma unroll
    for (int mi = 0; mi < 4; mi++) {
        const int row0 = bm + wm * 64 + mi * 16 + (lane >> 2);
        #pragma unroll
        for (int f = 0; f < 8; f++) {
            const int n0 = bn + wn * 64 + f * 8 + (lane & 3) * 2;
            float* cc = acc[mi][f];
            #pragma unroll
            for (int hrow = 0; hrow < 2; hrow++) {
                const int row = row0 + hrow * 8;
                float v0 = cc[hrow * 2 + 0];
                float v1 = cc[hrow * 2 + 1];
                const size_t idx = (size_t)row * N + n0;
                if (EPI == 1 || EPI == 3) {
                    if (EPI == 1) {
                        v0 = 0.5f * v0 * (1.0f + erff(v0 * 0.70710678118654752f));
                        v1 = 0.5f * v1 * (1.0f + erff(v1 * 0.70710678118654752f));
                    }
                    __nv_bfloat16 h0, l0, h1, l1;
                    split2(v0, h0, l0); split2(v1, h1, l1);
                    __nv_bfloat162 hp; hp.x = h0; hp.y = h1;
                    __nv_bfloat162 lp; lp.x = l0; lp.y = l1;
                    *(__nv_bfloat162*)(Chi + idx) = hp;
                    *(__nv_bfloat162*)(Clo + idx) = lp;
                } else {
                    if (EPI == 2) {
                        float2 rv = *(const float2*)(R + idx);
                        v0 += rv.x; v1 += rv.y;
                    }
                    float2 ov; ov.x = v0; ov.y = v1;
                    *(float2*)(C + idx) = ov;
                }
            }
        }
    }
}

// ---------------------------------------------------------------------------
// Fused QKV GEMM: blockIdx.x selects (weight, output) — 768 CTAs in one wavefront.
// ---------------------------------------------------------------------------
struct QKVPtrs {
    const __nv_bfloat16* bh[3];
    const __nv_bfloat16* bl[3];
    __nv_bfloat16* ch[3];
    __nv_bfloat16* cl[3];
};

__global__ __launch_bounds__(256, 1) void gemm_qkv_kernel(
    const __nv_bfloat16* __restrict__ Ah, const __nv_bfloat16* __restrict__ Al,
    QKVPtrs p)
{
    extern __shared__ char smem[];
    const uint32_t sb = smem_u32(smem);
    const int tid  = threadIdx.x;
    const int wid  = tid >> 5;
    const int lane = tid & 31;
    const int wm   = wid & 1;
    const int wn   = wid >> 1;
    const int which = blockIdx.x >> 3;            // 0=q 1=k 2=v
    const int bm   = blockIdx.y * TM;
    const int bn   = (blockIdx.x & 7) * TN;
    const int NC   = KD / TKC;

    const __nv_bfloat16* __restrict__ Bh = p.bh[which];
    const __nv_bfloat16* __restrict__ Bl = p.bl[which];
    __nv_bfloat16* __restrict__ Chi = p.ch[which];
    __nv_bfloat16* __restrict__ Clo = p.cl[which];

    const int mat  = lane >> 3;
    const int rin  = lane & 7;
    const int rowA = (mat & 1) * 8 + rin;
    const int kA   = mat >> 1;
    const int rowB = (mat >> 1) * 8 + rin;
    const int kB   = mat & 1;

    float acc[4][8][4];
    #pragma unroll
    for (int i = 0; i < 4; i++)
        #pragma unroll
        for (int j = 0; j < 8; j++)
            #pragma unroll
            for (int t = 0; t < 4; t++) acc[i][j][t] = 0.f;

    GEMM_MAINLOOP(Ah, Al, Bh, Bl, bm, bn, KD, NC)

    #pragma unroll
    for (int mi = 0; mi < 4; mi++) {
        const int row0 = bm + wm * 64 + mi * 16 + (lane >> 2);
        #pragma unroll
        for (int f = 0; f < 8; f++) {
            const int n0 = bn + wn * 64 + f * 8 + (lane & 3) * 2;
            float* cc = acc[mi][f];
            #pragma unroll
            for (int hrow = 0; hrow < 2; hrow++) {
                const int row = row0 + hrow * 8;
                float v0 = cc[hrow * 2 + 0];
                float v1 = cc[hrow * 2 + 1];
                const size_t idx = (size_t)row * KD + n0;
                __nv_bfloat16 h0, l0, h1, l1;
                split2(v0, h0, l0); split2(v1, h1, l1);
                __nv_bfloat162 hp; hp.x = h0; hp.y = h1;
                __nv_bfloat162 lp; lp.x = l0; lp.y = l1;
                *(__nv_bfloat162*)(Chi + idx) = hp;
                *(__nv_bfloat162*)(Clo + idx) = lp;
            }
        }
    }
}

// ---------------------------------------------------------------------------
// Tensor-core causal flash attention, hi/lo split, reversed CTA order.
// ---------------------------------------------------------------------------
#define AT_QH 0u
#define AT_QL 16384u
#define AT_KH 32768u
#define AT_KL 49152u
#define AT_VH 65536u
#define AT_VL 81920u
#define ATT_SMEM 98304u

__global__ __launch_bounds__(128, 1) void attn_mma_kernel(
    const __nv_bfloat16* __restrict__ Qh, const __nv_bfloat16* __restrict__ Ql,
    const __nv_bfloat16* __restrict__ Kh, const __nv_bfloat16* __restrict__ Kl,
    const __nv_bfloat16* __restrict__ Vh, const __nv_bfloat16* __restrict__ Vl,
    __nv_bfloat16* __restrict__ Oh, __nv_bfloat16* __restrict__ Ol)
{
    extern __shared__ char smem[];
    const uint32_t sb = smem_u32(smem);
    const int tid  = threadIdx.x;
    const int wid  = tid >> 5;
    const int lane = tid & 31;
    const int bh   = blockIdx.y;
    const int b    = bh >> 4;
    const int h    = bh & 15;
    const int qt   = gridDim.x - 1 - blockIdx.x;   // longest rows first
    const int q0   = qt * 64;

    const int mat  = lane >> 3;
    const int rin  = lane & 7;
    const int rowA = (mat & 1) * 8 + rin;
    const int kA   = mat >> 1;
    const int rowB = (mat >> 1) * 8 + rin;
    const int kB   = mat & 1;

    const size_t hoff = (size_t)h * KDH;

    #pragma unroll
    for (int i = 0; i < 8; i++) {
        int idx = tid + i * 128;
        int r = idx >> 4, cc = idx & 15;
        uint32_t so = SWZ256((uint32_t)(r * 256 + cc * 16));
        size_t go = ((size_t)(b * KL + q0 + r)) * KD + hoff + cc * 8;
        *(uint4*)(smem + AT_QH + so) = *(const uint4*)(Qh + go);
        *(uint4*)(smem + AT_QL + so) = *(const uint4*)(Ql + go);
    }

    float ofrag[16][4];
    #pragma unroll
    for (int g = 0; g < 16; g++)
        #pragma unroll
        for (int t = 0; t < 4; t++) ofrag[g][t] = 0.f;

    float mrow0 = -1e30f, mrow1 = -1e30f;
    float lrow0 = 0.f, lrow1 = 0.f;

    const float scale = 0.08838834764831845f;

    for (int kt = 0; kt <= qt; kt++) {
        const int k0 = kt * 64;
        __syncthreads();
        #pragma unroll
        for (int i = 0; i < 8; i++) {
            int idx = tid + i * 128;
            int r = idx >> 4, cc = idx & 15;
            uint32_t so = SWZ256((uint32_t)(r * 256 + cc * 16));
            size_t go = ((size_t)(b * KL + k0 + r)) * KD + hoff + cc * 8;
            *(uint4*)(smem + AT_KH + so) = *(const uint4*)(Kh + go);
            *(uint4*)(smem + AT_KL + so) = *(const uint4*)(Kl + go);
        }
        #pragma unroll
        for (int i = 0; i < 16; i++) {
            int idx = tid + i * 128;
            int key = idx >> 5, d0 = (idx & 31) * 4;
            size_t go = ((size_t)(b * KL + k0 + key)) * KD + hoff + d0;
            uint2 vh4 = *(const uint2*)(Vh + go);
            uint2 vl4 = *(const uint2*)(Vl + go);
            const __nv_bfloat16* ph = (const __nv_bfloat16*)&vh4;
            const __nv_bfloat16* pl = (const __nv_bfloat16*)&vl4;
            #pragma unroll
            for (int d = 0; d < 4; d++) {
                uint32_t so = SWZ128((uint32_t)((d0 + d) * 128 + key * 2));
                *(__nv_bfloat16*)(smem + AT_VH + so) = ph[d];
                *(__nv_bfloat16*)(smem + AT_VL + so) = pl[d];
            }
        }
        __syncthreads();

        float sf[8][4];
        #pragma unroll
        for (int f = 0; f < 8; f++)
            #pragma unroll
            for (int t = 0; t < 4; t++) sf[f][t] = 0.f;

        #pragma unroll
        for (int ks = 0; ks < 8; ks++) {
            uint32_t qh[4], ql[4], kh[4][4], kl[4][4];
            {
                uint32_t off = SWZ256((uint32_t)((wid * 16 + rowA) * 256 + ks * 32 + kA * 16));
                LDSM_X4(qh, sb + AT_QH + off);
                LDSM_X4(ql, sb + AT_QL + off);
            }
            #pragma unroll
            for (int nj = 0; nj < 4; nj++) {
                uint32_t off = SWZ256((uint32_t)((nj * 16 + rowB) * 256 + ks * 32 + kB * 16));
                LDSM_X4(kh[nj], sb + AT_KH + off);
                LDSM_X4(kl[nj], sb + AT_KL + off);
            }
            #pragma unroll
            for (int nj = 0; nj < 4; nj++)
                #pragma unroll
                for (int hf = 0; hf < 2; hf++)
                    mma_bf16(sf[nj*2+hf], qh, kh[nj][hf*2], kh[nj][hf*2+1]);
            #pragma unroll
            for (int nj = 0; nj < 4; nj++)
                #pragma unroll
                for (int hf = 0; hf < 2; hf++)
                    mma_bf16(sf[nj*2+hf], qh, kl[nj][hf*2], kl[nj][hf*2+1]);
            #pragma unroll
            for (int nj = 0; nj < 4; nj++)
                #pragma unroll
                for (int hf = 0; hf < 2; hf++)
                    mma_bf16(sf[nj*2+hf], ql, kh[nj][hf*2], kh[nj][hf*2+1]);
        }

        const int myrow = q0 + wid * 16 + (lane >> 2);
        #pragma unroll
        for (int f = 0; f < 8; f++) {
            #pragma unroll
            for (int t = 0; t < 4; t++) sf[f][t] *= scale;
            if (kt == qt) {
                int col = k0 + f * 8 + (lane & 3) * 2;
                if (col > myrow)     sf[f][0] = -1e30f;
                if (col + 1 > myrow) sf[f][1] = -1e30f;
                if (col > myrow + 8)     sf[f][2] = -1e30f;
                if (col + 1 > myrow + 8) sf[f][3] = -1e30f;
            }
        }

        float mx0 = -1e30f, mx1 = -1e30f;
        #pragma unroll
        for (int f = 0; f < 8; f++) {
            mx0 = fmaxf(mx0, fmaxf(sf[f][0], sf[f][1]));
            mx1 = fmaxf(mx1, fmaxf(sf[f][2], sf[f][3]));
        }
        #pragma unroll
        for (int d = 1; d <= 2; d <<= 1) {
            mx0 = fmaxf(mx0, __shfl_xor_sync(0xFFFFFFFFu, mx0, d));
            mx1 = fmaxf(mx1, __shfl_xor_sync(0xFFFFFFFFu, mx1, d));
        }
        float mnew0 = fmaxf(mrow0, mx0);
        float mnew1 = fmaxf(mrow1, mx1);
        float alpha0 = __expf(mrow0 - mnew0);
        float alpha1 = __expf(mrow1 - mnew1);
        mrow0 = mnew0; mrow1 = mnew1;

        float rs0 = 0.f, rs1 = 0.f;
        uint32_t pha[8][2], pla[8][2];
        #pragma unroll
        for (int f = 0; f < 8; f++) {
            float p0 = __expf(sf[f][0] - mnew0);
            float p1 = __expf(sf[f][1] - mnew0);
            float p2 = __expf(sf[f][2] - mnew1);
            float p3 = __expf(sf[f][3] - mnew1);
            rs0 += p0 + p1; rs1 += p2 + p3;
            __nv_bfloat16 h0, l0, h1, l1, h2, l2, h3, l3;
            split2(p0, h0, l0); split2(p1, h1, l1);
            split2(p2, h2, l2); split2(p3, h3, l3);
            pha[f][0] = pack_bf16(__bfloat162float(h0), __bfloat162float(h1));
            pha[f][1] = pack_bf16(__bfloat162float(h2), __bfloat162float(h3));
            pla[f][0] = pack_bf16(__bfloat162float(l0), __bfloat162float(l1));
            pla[f][1] = pack_bf16(__bfloat162float(l2), __bfloat162float(l3));
        }
        #pragma unroll
        for (int d = 1; d <= 2; d <<= 1) {
            rs0 += __shfl_xor_sync(0xFFFFFFFFu, rs0, d);
            rs1 += __shfl_xor_sync(0xFFFFFFFFu, rs1, d);
        }
        lrow0 = lrow0 * alpha0 + rs0;
        lrow1 = lrow1 * alpha1 + rs1;

        #pragma unroll
        for (int g = 0; g < 16; g++) {
            ofrag[g][0] *= alpha0; ofrag[g][1] *= alpha0;
            ofrag[g][2] *= alpha1; ofrag[g][3] *= alpha1;
        }

        #pragma unroll
        for (int kk = 0; kk < 4; kk++) {
            uint32_t pa[4] = {pha[2*kk][0], pha[2*kk][1], pha[2*kk+1][0], pha[2*kk+1][1]};
            uint32_t pb[4] = {pla[2*kk][0], pla[2*kk][1], pla[2*kk+1][0], pla[2*kk+1][1]};
            #pragma unroll
            for (int g = 0; g < 8; g++) {
                uint32_t vh[4], vl[4];
                uint32_t off = SWZ128((uint32_t)((g * 16 + rowB) * 128 + kk * 32 + kB * 16));
                LDSM_X4(vh, sb + AT_VH + off);
                LDSM_X4(vl, sb + AT_VL + off);
                mma_bf16(ofrag[g*2+0], pa, vh[0], vh[1]);
                mma_bf16(ofrag[g*2+1], pa, vh[2], vh[3]);
                mma_bf16(ofrag[g*2+0], pa, vl[0], vl[1]);
                mma_bf16(ofrag[g*2+1], pa, vl[2], vl[3]);
                mma_bf16(ofrag[g*2+0], pb, vh[0], vh[1]);
                mma_bf16(ofrag[g*2+1], pb, vh[2], vh[3]);
            }
        }
    }

    float inv0 = 1.0f / lrow0;
    float inv1 = 1.0f / lrow1;
    const int r0 = q0 + wid * 16 + (lane >> 2);
    #pragma unroll
    for (int g = 0; g < 16; g++) {
        int col = h * KDH + g * 8 + (lane & 3) * 2;
        float v0 = ofrag[g][0] * inv0, v1 = ofrag[g][1] * inv0;
        float v2 = ofrag[g][2] * inv1, v3 = ofrag[g][3] * inv1;
        __nv_bfloat16 h0,l0,h1,l1,h2,l2,h3,l3;
        split2(v0,h0,l0); split2(v1,h1,l1); split2(v2,h2,l2); split2(v3,h3,l3);
        size_t i0 = (size_t)(b * KL + r0) * KD + col;
        size_t i1 = (size_t)(b * KL + r0 + 8) * KD + col;
        __nv_bfloat162 t;
        t.x = h0; t.y = h1; *(__nv_bfloat162*)(Oh + i0) = t;
        t.x = l0; t.y = l1; *(__nv_bfloat162*)(Ol + i0) = t;
        t.x = h2; t.y = h3; *(__nv_bfloat162*)(Oh + i1) = t;
        t.x = l2; t.y = l3; *(__nv_bfloat162*)(Ol + i1) = t;
    }
}

// ---------------------------------------------------------------------------
// kernel_launch
// ---------------------------------------------------------------------------
extern "C" void kernel_launch(void* const* d_in, const int* in_sizes, int n_in,
                              void* d_out, int out_size)
{
    const float* x    = (const float*)d_in[0];
    const float* ln1  = (const float*)d_in[2];
    const float* wq   = (const float*)d_in[3];
    const float* wk   = (const float*)d_in[4];
    const float* wv   = (const float*)d_in[5];
    const float* wo   = (const float*)d_in[6];
    const float* ln2  = (const float*)d_in[7];
    const float* wup  = (const float*)d_in[8];
    const float* wdn  = (const float*)d_in[9];
    float* out = (float*)d_out;

    __nv_bfloat16 *wq_h,*wq_l,*wk_h,*wk_l,*wv_h,*wv_l,*wo_h,*wo_l;
    __nv_bfloat16 *wu_h,*wu_l,*wd_h,*wd_l,*h_h,*h_l,*o_h,*o_l,*u_h,*u_l;
    __nv_bfloat16 *q_h,*q_l,*k_h,*k_l,*v_h,*v_l;
    cudaGetSymbolAddress((void**)&wq_h, g_wq_h);
    cudaGetSymbolAddress((void**)&wq_l, g_wq_l);
    cudaGetSymbolAddress((void**)&wk_h, g_wk_h);
    cudaGetSymbolAddress((void**)&wk_l, g_wk_l);
    cudaGetSymbolAddress((void**)&wv_h, g_wv_h);
    cudaGetSymbolAddress((void**)&wv_l, g_wv_l);
    cudaGetSymbolAddress((void**)&wo_h, g_wo_h);
    cudaGetSymbolAddress((void**)&wo_l, g_wo_l);
    cudaGetSymbolAddress((void**)&wu_h, g_wu_h);
    cudaGetSymbolAddress((void**)&wu_l, g_wu_l);
    cudaGetSymbolAddress((void**)&wd_h, g_wd_h);
    cudaGetSymbolAddress((void**)&wd_l, g_wd_l);
    cudaGetSymbolAddress((void**)&h_h, g_h_h);
    cudaGetSymbolAddress((void**)&h_l, g_h_l);
    cudaGetSymbolAddress((void**)&o_h, g_o_h);
    cudaGetSymbolAddress((void**)&o_l, g_o_l);
    cudaGetSymbolAddress((void**)&u_h, g_u_h);
    cudaGetSymbolAddress((void**)&u_l, g_u_l);
    cudaGetSymbolAddress((void**)&q_h, g_q_h);
    cudaGetSymbolAddress((void**)&q_l, g_q_l);
    cudaGetSymbolAddress((void**)&k_h, g_k_h);
    cudaGetSymbolAddress((void**)&k_l, g_k_l);
    cudaGetSymbolAddress((void**)&v_h, g_v_h);
    cudaGetSymbolAddress((void**)&v_l, g_v_l);

    cudaFuncSetAttribute(gemm_mma_kernel<0>, cudaFuncAttributeMaxDynamicSharedMemorySize, GEMM_SMEM);
    cudaFuncSetAttribute(gemm_mma_kernel<1>, cudaFuncAttributeMaxDynamicSharedMemorySize, GEMM_SMEM);
    cudaFuncSetAttribute(gemm_mma_kernel<2>, cudaFuncAttributeMaxDynamicSharedMemorySize, GEMM_SMEM);
    cudaFuncSetAttribute(gemm_mma_kernel<3>, cudaFuncAttributeMaxDynamicSharedMemorySize, GEMM_SMEM);
    cudaFuncSetAttribute(gemm_qkv_kernel, cudaFuncAttributeMaxDynamicSharedMemorySize, GEMM_SMEM);
    cudaFuncSetAttribute(attn_mma_kernel, cudaFuncAttributeMaxDynamicSharedMemorySize, ATT_SMEM);

    dim3 blk(256);
    dim3 gqkv3(3 * (KD / TN), KM / TM);   // 24 x 32 = 768 CTAs
    dim3 gd(KD / TN, KM / TM);
    dim3 gup(KDFF / TN, KM / TM);

    const int n4  = KD * KD / 4;
    const int g4  = (n4 + 255) / 256;
    const int n4f = KDFF * KD / 4;
    const int g4f = (n4f + 255) / 256;

    QKVPtrs p;
    p.bh[0] = wq_h; p.bh[1] = wk_h; p.bh[2] = wv_h;
    p.bl[0] = wq_l; p.bl[1] = wk_l; p.bl[2] = wv_l;
    p.ch[0] = q_h;  p.ch[1] = k_h;  p.ch[2] = v_h;
    p.cl[0] = q_l;  p.cl[1] = k_l;  p.cl[2] = v_l;

    // 0: rmsnorm, 1-3: qkv weight splits
    rmsnorm_split_kernel<<<KM, blk>>>(x, ln1, h_h, h_l);
    split_kernel<<<g4, blk>>>(wq, wq_h, wq_l, n4);
    split_kernel<<<g4, blk>>>(wk, wk_h, wk_l, n4);
    split_kernel<<<g4, blk>>>(wv, wv_h, wv_l, n4);

    // 4: fused QKV GEMM ; 5: attention  (ncu -s 5 window covers these)
    gemm_qkv_kernel<<<gqkv3, blk, GEMM_SMEM>>>(h_h, h_l, p);
    dim3 gattn(KL / 64, KB * KH);
    attn_mma_kernel<<<gattn, dim3(128), ATT_SMEM>>>(q_h, q_l, k_h, k_l, v_h, v_l, o_h, o_l);

    // remaining weight splits
    split_kernel<<<g4, blk>>>(wo, wo_h, wo_l, n4);
    split_kernel<<<g4f, blk>>>(wup, wu_h, wu_l, n4f);
    split_kernel<<<g4f, blk>>>(wdn, wd_h, wd_l, n4f);

    // out = x + o @ wo^T
    gemm_mma_kernel<2><<<gd, blk, GEMM_SMEM>>>(o_h, o_l, wo_h, wo_l, out, x, nullptr, nullptr, KD, KD);

    // h = rmsnorm(out, ln2)
    rmsnorm_split_kernel<<<KM, blk>>>(out, ln2, h_h, h_l);

    // u = gelu(h @ wup^T)
    gemm_mma_kernel<1><<<gup, blk, GEMM_SMEM>>>(h_h, h_l, wu_h, wu_l, nullptr, nullptr, u_h, u_l, KDFF, KD);

    // out = out + u @ wdn^T
    gemm_mma_kernel<2><<<gd, blk, GEMM_SMEM>>>(u_h, u_l, wd_h, wd_l, out, out, nullptr, nullptr, KD, KDFF);
}

// round 8
// speedup vs baseline: 1.0289x; 1.0289x over previous
#include <cuda_runtime.h>
#include <cuda_bf16.h>
#include <math.h>
#include <stdint.h>

// ---------------------------------------------------------------------------
// TransformerBlock  B=2, L=2048, D=2048, H=16, DH=128, DFF=8192
// Round 7: 128x128 CTA tiles, 3-stage cp.async, 2 CTAs/SM (16 warps/SM) to
// hide per-chunk barrier/LDSM latency; fixed cp.async group-count race.
// ---------------------------------------------------------------------------

#define KB   2
#define KL   2048
#define KD   2048
#define KH   16
#define KDH  128
#define KDFF 8192
#define KM   (KB * KL)   // 4096 rows

// ----------------------------- PTX helpers --------------------------------
__device__ __forceinline__ uint32_t smem_u32(const void* p) {
    uint32_t a;
    asm("{ .reg .u64 t; cvta.to.shared.u64 t, %1; cvt.u32.u64 %0, t; }"
        : "=r"(a) : "l"(p));
    return a;
}

#define SWZ64(off)  ((off) ^ (((off) >> 3) & 0x30))   // 64B rows
#define SWZ128(off) ((off) ^ (((off) >> 3) & 0x70))   // 128B rows
#define SWZ256(off) ((off) ^ (((off) >> 4) & 0x70))   // 256B rows

#define CP_ASYNC16(smem, gptr) \
    asm volatile("cp.async.cg.shared.global [%0], [%1], 16;" \
        :: "r"((uint32_t)(smem)), "l"(gptr) : "memory")
#define CP_COMMIT() asm volatile("cp.async.commit_group;" ::: "memory")
#define CP_WAIT2()  asm volatile("cp.async.wait_group 2;" ::: "memory")

#define LDSM_X4(r, addr) \
    asm volatile("ldmatrix.sync.aligned.m8n8.x4.shared.b16 {%0,%1,%2,%3}, [%4];" \
        : "=r"((r)[0]), "=r"((r)[1]), "=r"((r)[2]), "=r"((r)[3]) \
        : "r"((uint32_t)(addr)))

__device__ __forceinline__ void mma_bf16(float* c, const uint32_t* a,
                                         uint32_t b0, uint32_t b1) {
    asm volatile(
        "mma.sync.aligned.m16n8k16.row.col.f32.bf16.bf16.f32 "
        "{%0,%1,%2,%3}, {%4,%5,%6,%7}, {%8,%9}, {%0,%1,%2,%3};"
        : "+f"(c[0]), "+f"(c[1]), "+f"(c[2]), "+f"(c[3])
        : "r"(a[0]), "r"(a[1]), "r"(a[2]), "r"(a[3]), "r"(b0), "r"(b1));
}

__device__ __forceinline__ void split2(float v, __nv_bfloat16& h, __nv_bfloat16& l) {
    h = __float2bfloat16(v);
    l = __float2bfloat16(v - __bfloat162float(h));
}
__device__ __forceinline__ uint32_t pack_bf16(float a, float b) {
    __nv_bfloat162 t = __floats2bfloat162_rn(a, b);
    return *(uint32_t*)&t;
}

// ------------------------------- scratch ----------------------------------
__device__ __nv_bfloat16 g_wq_h[(size_t)KD * KD];
__device__ __nv_bfloat16 g_wq_l[(size_t)KD * KD];
__device__ __nv_bfloat16 g_wk_h[(size_t)KD * KD];
__device__ __nv_bfloat16 g_wk_l[(size_t)KD * KD];
__device__ __nv_bfloat16 g_wv_h[(size_t)KD * KD];
__device__ __nv_bfloat16 g_wv_l[(size_t)KD * KD];
__device__ __nv_bfloat16 g_wo_h[(size_t)KD * KD];
__device__ __nv_bfloat16 g_wo_l[(size_t)KD * KD];
__device__ __nv_bfloat16 g_wu_h[(size_t)KDFF * KD];
__device__ __nv_bfloat16 g_wu_l[(size_t)KDFF * KD];
__device__ __nv_bfloat16 g_wd_h[(size_t)KD * KDFF];
__device__ __nv_bfloat16 g_wd_l[(size_t)KD * KDFF];
__device__ __nv_bfloat16 g_h_h[(size_t)KM * KD];
__device__ __nv_bfloat16 g_h_l[(size_t)KM * KD];
__device__ __nv_bfloat16 g_q_h[(size_t)KM * KD];
__device__ __nv_bfloat16 g_q_l[(size_t)KM * KD];
__device__ __nv_bfloat16 g_k_h[(size_t)KM * KD];
__device__ __nv_bfloat16 g_k_l[(size_t)KM * KD];
__device__ __nv_bfloat16 g_v_h[(size_t)KM * KD];
__device__ __nv_bfloat16 g_v_l[(size_t)KM * KD];
__device__ __nv_bfloat16 g_o_h[(size_t)KM * KD];
__device__ __nv_bfloat16 g_o_l[(size_t)KM * KD];
__device__ __nv_bfloat16 g_u_h[(size_t)KM * KDFF];
__device__ __nv_bfloat16 g_u_l[(size_t)KM * KDFF];

// ---------------------------------------------------------------------------
// weight split
// ---------------------------------------------------------------------------
__global__ __launch_bounds__(256) void split_kernel(
    const float* __restrict__ src, __nv_bfloat16* __restrict__ hi,
    __nv_bfloat16* __restrict__ lo, int n4)
{
    int i = blockIdx.x * 256 + threadIdx.x;
    if (i >= n4) return;
    float4 v = ((const float4*)src)[i];
    __nv_bfloat16 h[4], l[4];
    split2(v.x, h[0], l[0]); split2(v.y, h[1], l[1]);
    split2(v.z, h[2], l[2]); split2(v.w, h[3], l[3]);
    ((uint2*)hi)[i] = *(uint2*)h;
    ((uint2*)lo)[i] = *(uint2*)l;
}

// ---------------------------------------------------------------------------
// RMSNorm with fused hi/lo split output
// ---------------------------------------------------------------------------
__global__ __launch_bounds__(256) void rmsnorm_split_kernel(
    const float* __restrict__ x, const float* __restrict__ w,
    __nv_bfloat16* __restrict__ yh, __nv_bfloat16* __restrict__ yl)
{
    int row = blockIdx.x;
    const float* xr = x + (size_t)row * KD;
    float s = 0.f;
    #pragma unroll
    for (int i = threadIdx.x; i < KD; i += 256) { float v = xr[i]; s += v * v; }
    __shared__ float red[256];
    red[threadIdx.x] = s;
    __syncthreads();
    #pragma unroll
    for (int st = 128; st > 0; st >>= 1) {
        if (threadIdx.x < st) red[threadIdx.x] += red[threadIdx.x + st];
        __syncthreads();
    }
    float inv = rsqrtf(red[0] * (1.0f / KD) + 1e-8f);
    #pragma unroll
    for (int i = threadIdx.x; i < KD; i += 256) {
        float v = xr[i] * inv * w[i];
        __nv_bfloat16 h, l;
        split2(v, h, l);
        yh[(size_t)row * KD + i] = h;
        yl[(size_t)row * KD + i] = l;
    }
}

// ---------------------------------------------------------------------------
// GEMM: 128x128 CTA tile, 8 warps (2x4), warp tile 64x32, K-chunk 32,
// 3-stage cp.async (96KB smem), 2 CTAs/SM.
// ---------------------------------------------------------------------------
#define TM 128
#define TN 128
#define TKC 32
#define ASPLIT 8192u
#define BSPLIT 8192u
#define STAGE  (2u*ASPLIT + 2u*BSPLIT)   // 32768
#define NSTAGE 3
#define GEMM_SMEM (NSTAGE * STAGE)       // 98304

// mainloop body (correct group-count: empty commit when no load issued)
#define GEMM_MAINLOOP(AhP, AlP, BhP, BlP, bmE, bnE, KE, NCE)                    \
    auto load_stage = [&](int c, int s) {                                       \
        const int kc = c * TKC;                                                 \
        const uint32_t base = sb + (uint32_t)s * STAGE;                         \
        _Pragma("unroll")                                                       \
        for (int i = 0; i < 2; i++) {                                           \
            int chunk = i * 256 + tid;                                          \
            int r = chunk >> 2, cc = chunk & 3;                                 \
            uint32_t so = SWZ64((uint32_t)(r * 64 + cc * 16));                  \
            size_t go = (size_t)((bmE) + r) * (KE) + kc + cc * 8;               \
            CP_ASYNC16(base + so,           (AhP) + go);                        \
            CP_ASYNC16(base + ASPLIT + so,  (AlP) + go);                        \
        }                                                                       \
        _Pragma("unroll")                                                       \
        for (int i = 0; i < 2; i++) {                                           \
            int chunk = i * 256 + tid;                                          \
            int r = chunk >> 2, cc = chunk & 3;                                 \
            uint32_t so = SWZ64((uint32_t)(r * 64 + cc * 16));                  \
            size_t go = (size_t)((bnE) + r) * (KE) + kc + cc * 8;               \
            CP_ASYNC16(base + 2u*ASPLIT + so,          (BhP) + go);             \
            CP_ASYNC16(base + 2u*ASPLIT + BSPLIT + so, (BlP) + go);             \
        }                                                                       \
        CP_COMMIT();                                                            \
    };                                                                          \
    load_stage(0, 0);                                                           \
    load_stage(1, 1);                                                           \
    _Pragma("unroll 1")                                                         \
    for (int c = 0; c < (NCE); c++) {                                           \
        const int s = c % 3;                                                    \
        __syncthreads();   /* all warps done with compute(c-1) */               \
        if (c + 2 < (NCE)) load_stage(c + 2, (c + 2) % 3);                      \
        else               CP_COMMIT();   /* keep group-count invariant */      \
        CP_WAIT2();        /* groups <= {c+1, c+2} pending => chunk c ready */  \
        __syncthreads();   /* writes of stage s visible to all warps */         \
        const uint32_t sAh = sb + (uint32_t)s * STAGE;                          \
        const uint32_t sAl = sAh + ASPLIT;                                      \
        const uint32_t sBh = sAl + ASPLIT;                                      \
        const uint32_t sBl = sBh + BSPLIT;                                      \
        _Pragma("unroll")                                                       \
        for (int h = 0; h < 2; h++) {                                           \
            uint32_t afh[4][4], afl[4][4], bfh[2][4], bfl[2][4];                \
            _Pragma("unroll")                                                   \
            for (int mi = 0; mi < 4; mi++) {                                    \
                int m = wm * 64 + mi * 16 + rowA;                               \
                uint32_t off = SWZ64((uint32_t)(m * 64 + (h * 2 + kA) * 16));   \
                LDSM_X4(afh[mi], sAh + off);                                    \
                LDSM_X4(afl[mi], sAl + off);                                    \
            }                                                                   \
            _Pragma("unroll")                                                   \
            for (int nj = 0; nj < 2; nj++) {                                    \
                int n = wn * 32 + nj * 16 + rowB;                               \
                uint32_t off = SWZ64((uint32_t)(n * 64 + (h * 2 + kB) * 16));   \
                LDSM_X4(bfh[nj], sBh + off);                                    \
                LDSM_X4(bfl[nj], sBl + off);                                    \
            }                                                                   \
            _Pragma("unroll")                                                   \
            for (int mi = 0; mi < 4; mi++)                                      \
                _Pragma("unroll")                                               \
                for (int nj = 0; nj < 2; nj++)                                  \
                    _Pragma("unroll")                                           \
                    for (int hf = 0; hf < 2; hf++)                              \
                        mma_bf16(acc[mi][nj*2+hf], afh[mi],                     \
                                 bfh[nj][hf*2], bfh[nj][hf*2+1]);               \
            _Pragma("unroll")                                                   \
            for (int mi = 0; mi < 4; mi++)                                      \
                _Pragma("unroll")                                               \
                for (int nj = 0; nj < 2; nj++)                                  \
                    _Pragma("unroll")                                           \
                    for (int hf = 0; hf < 2; hf++)                              \
                        mma_bf16(acc[mi][nj*2+hf], afh[mi],                     \
                                 bfl[nj][hf*2], bfl[nj][hf*2+1]);               \
            _Pragma("unroll")                                                   \
            for (int mi = 0; mi < 4; mi++)                                      \
                _Pragma("unroll")                                               \
                for (int nj = 0; nj < 2; nj++)                                  \
                    _Pragma("unroll")                                           \
                    for (int hf = 0; hf < 2; hf++)                              \
                        mma_bf16(acc[mi][nj*2+hf], afl[mi],                     \
                                 bfh[nj][hf*2], bfh[nj][hf*2+1]);               \
        }                                                                       \
    }

// ---------------------------------------------------------------------------
// General split GEMM.  EPI: 0 fp32 C, 1 GELU->hi/lo, 2 C=R+acc, 3 hi/lo
// ---------------------------------------------------------------------------
template<int EPI>
__global__ __launch_bounds__(256, 2) void gemm_mma_kernel(
    const __nv_bfloat16* __restrict__ Ah, const __nv_bfloat16* __restrict__ Al,
    const __nv_bfloat16* __restrict__ Bh, const __nv_bfloat16* __restrict__ Bl,
    float* __restrict__ C, const float* __restrict__ R,
    __nv_bfloat16* __restrict__ Chi, __nv_bfloat16* __restrict__ Clo,
    int N, int K)
{
    extern __shared__ char smem[];
    const uint32_t sb = smem_u32(smem);
    const int tid  = threadIdx.x;
    const int wid  = tid >> 5;
    const int lane = tid & 31;
    const int wm   = wid & 1;
    const int wn   = wid >> 1;       // 0..3
    const int bm   = blockIdx.y * TM;
    const int bn   = blockIdx.x * TN;
    const int NC   = K / TKC;

    const int mat  = lane >> 3;
    const int rin  = lane & 7;
    const int rowA = (mat & 1) * 8 + rin;
    const int kA   = mat >> 1;
    const int rowB = (mat >> 1) * 8 + rin;
    const int kB   = mat & 1;

    float acc[4][4][4];
    #pragma unroll
    for (int i = 0; i < 4; i++)
        #pragma unroll
        for (int j = 0; j < 4; j++)
            #pragma unroll
            for (int t = 0; t < 4; t++) acc[i][j][t] = 0.f;

    GEMM_MAINLOOP(Ah, Al, Bh, Bl, bm, bn, K, NC)

    #pragma unroll
    for (int mi = 0; mi < 4; mi++) {
        const int row0 = bm + wm * 64 + mi * 16 + (lane >> 2);
        #pragma unroll
        for (int f = 0; f < 4; f++) {
            const int n0 = bn + wn * 32 + f * 8 + (lane & 3) * 2;
            float* cc = acc[mi][f];
            #pragma unroll
            for (int hrow = 0; hrow < 2; hrow++) {
                const int row = row0 + hrow * 8;
                float v0 = cc[hrow * 2 + 0];
                float v1 = cc[hrow * 2 + 1];
                const size_t idx = (size_t)row * N + n0;
                if (EPI == 1 || EPI == 3) {
                    if (EPI == 1) {
                        v0 = 0.5f * v0 * (1.0f + erff(v0 * 0.70710678118654752f));
                        v1 = 0.5f * v1 * (1.0f + erff(v1 * 0.70710678118654752f));
                    }
                    __nv_bfloat16 h0, l0, h1, l1;
                    split2(v0, h0, l0); split2(v1, h1, l1);
                    __nv_bfloat162 hp; hp.x = h0; hp.y = h1;
                    __nv_bfloat162 lp; lp.x = l0; lp.y = l1;
                    *(__nv_bfloat162*)(Chi + idx) = hp;
                    *(__nv_bfloat162*)(Clo + idx) = lp;
                } else {
                    if (EPI == 2) {
                        float2 rv = *(const float2*)(R + idx);
                        v0 += rv.x; v1 += rv.y;
                    }
                    float2 ov; ov.x = v0; ov.y = v1;
                    *(float2*)(C + idx) = ov;
                }
            }
        }
    }
}

// ---------------------------------------------------------------------------
// Fused QKV GEMM: blockIdx.x = which*16 + n-tile
// ---------------------------------------------------------------------------
struct QKVPtrs {
    const __nv_bfloat16* bh[3];
    const __nv_bfloat16* bl[3];
    __nv_bfloat16* ch[3];
    __nv_bfloat16* cl[3];
};

__global__ __launch_bounds__(256, 2) void gemm_qkv_kernel(
    const __nv_bfloat16* __restrict__ Ah, const __nv_bfloat16* __restrict__ Al,
    QKVPtrs p)
{
    extern __shared__ char smem[];
    const uint32_t sb = smem_u32(smem);
    const int tid  = threadIdx.x;
    const int wid  = tid >> 5;
    const int lane = tid & 31;
    const int wm   = wid & 1;
    const int wn   = wid >> 1;
    const int which = blockIdx.x >> 4;            // 0=q 1=k 2=v
    const int bm   = blockIdx.y * TM;
    const int bn   = (blockIdx.x & 15) * TN;
    const int NC   = KD / TKC;

    const __nv_bfloat16* __restrict__ Bh = p.bh[which];
    const __nv_bfloat16* __restrict__ Bl = p.bl[which];
    __nv_bfloat16* __restrict__ Chi = p.ch[which];
    __nv_bfloat16* __restrict__ Clo = p.cl[which];

    const int mat  = lane >> 3;
    const int rin  = lane & 7;
    const int rowA = (mat & 1) * 8 + rin;
    const int kA   = mat >> 1;
    const int rowB = (mat >> 1) * 8 + rin;
    const int kB   = mat & 1;

    float acc[4][4][4];
    #pragma unroll
    for (int i = 0; i < 4; i++)
        #pragma unroll
        for (int j = 0; j < 4; j++)
            #pragma unroll
            for (int t = 0; t < 4; t++) acc[i][j][t] = 0.f;

    GEMM_MAINLOOP(Ah, Al, Bh, Bl, bm, bn, KD, NC)

    #pragma unroll
    for (int mi = 0; mi < 4; mi++) {
        const int row0 = bm + wm * 64 + mi * 16 + (lane >> 2);
        #pragma unroll
        for (int f = 0; f < 4; f++) {
            const int n0 = bn + wn * 32 + f * 8 + (lane & 3) * 2;
            float* cc = acc[mi][f];
            #pragma unroll
            for (int hrow = 0; hrow < 2; hrow++) {
                const int row = row0 + hrow * 8;
                float v0 = cc[hrow * 2 + 0];
                float v1 = cc[hrow * 2 + 1];
                const size_t idx = (size_t)row * KD + n0;
                __nv_bfloat16 h0, l0, h1, l1;
                split2(v0, h0, l0); split2(v1, h1, l1);
                __nv_bfloat162 hp; hp.x = h0; hp.y = h1;
                __nv_bfloat162 lp; lp.x = l0; lp.y = l1;
                *(__nv_bfloat162*)(Chi + idx) = hp;
                *(__nv_bfloat162*)(Clo + idx) = lp;
            }
        }
    }
}

// ---------------------------------------------------------------------------
// Tensor-core causal flash attention, hi/lo split, reversed CTA order.
// ---------------------------------------------------------------------------
#define AT_QH 0u
#define AT_QL 16384u
#define AT_KH 32768u
#define AT_KL 49152u
#define AT_VH 65536u
#define AT_VL 81920u
#define ATT_SMEM 98304u

__global__ __launch_bounds__(128, 1) void attn_mma_kernel(
    const __nv_bfloat16* __restrict__ Qh, const __nv_bfloat16* __restrict__ Ql,
    const __nv_bfloat16* __restrict__ Kh, const __nv_bfloat16* __restrict__ Kl,
    const __nv_bfloat16* __restrict__ Vh, const __nv_bfloat16* __restrict__ Vl,
    __nv_bfloat16* __restrict__ Oh, __nv_bfloat16* __restrict__ Ol)
{
    extern __shared__ char smem[];
    const uint32_t sb = smem_u32(smem);
    const int tid  = threadIdx.x;
    const int wid  = tid >> 5;
    const int lane = tid & 31;
    const int bh   = blockIdx.y;
    const int b    = bh >> 4;
    const int h    = bh & 15;
    const int qt   = gridDim.x - 1 - blockIdx.x;
    const int q0   = qt * 64;

    const int mat  = lane >> 3;
    const int rin  = lane & 7;
    const int rowA = (mat & 1) * 8 + rin;
    const int kA   = mat >> 1;
    const int rowB = (mat >> 1) * 8 + rin;
    const int kB   = mat & 1;

    const size_t hoff = (size_t)h * KDH;

    #pragma unroll
    for (int i = 0; i < 8; i++) {
        int idx = tid + i * 128;
        int r = idx >> 4, cc = idx & 15;
        uint32_t so = SWZ256((uint32_t)(r * 256 + cc * 16));
        size_t go = ((size_t)(b * KL + q0 + r)) * KD + hoff + cc * 8;
        *(uint4*)(smem + AT_QH + so) = *(const uint4*)(Qh + go);
        *(uint4*)(smem + AT_QL + so) = *(const uint4*)(Ql + go);
    }

    float ofrag[16][4];
    #pragma unroll
    for (int g = 0; g < 16; g++)
        #pragma unroll
        for (int t = 0; t < 4; t++) ofrag[g][t] = 0.f;

    float mrow0 = -1e30f, mrow1 = -1e30f;
    float lrow0 = 0.f, lrow1 = 0.f;

    const float scale = 0.08838834764831845f;

    for (int kt = 0; kt <= qt; kt++) {
        const int k0 = kt * 64;
        __syncthreads();
        #pragma unroll
        for (int i = 0; i < 8; i++) {
            int idx = tid + i * 128;
            int r = idx >> 4, cc = idx & 15;
            uint32_t so = SWZ256((uint32_t)(r * 256 + cc * 16));
            size_t go = ((size_t)(b * KL + k0 + r)) * KD + hoff + cc * 8;
            *(uint4*)(smem + AT_KH + so) = *(const uint4*)(Kh + go);
            *(uint4*)(smem + AT_KL + so) = *(const uint4*)(Kl + go);
        }
        #pragma unroll
        for (int i = 0; i < 16; i++) {
            int idx = tid + i * 128;
            int key = idx >> 5, d0 = (idx & 31) * 4;
            size_t go = ((size_t)(b * KL + k0 + key)) * KD + hoff + d0;
            uint2 vh4 = *(const uint2*)(Vh + go);
            uint2 vl4 = *(const uint2*)(Vl + go);
            const __nv_bfloat16* ph = (const __nv_bfloat16*)&vh4;
            const __nv_bfloat16* pl = (const __nv_bfloat16*)&vl4;
            #pragma unroll
            for (int d = 0; d < 4; d++) {
                uint32_t so = SWZ128((uint32_t)((d0 + d) * 128 + key * 2));
                *(__nv_bfloat16*)(smem + AT_VH + so) = ph[d];
                *(__nv_bfloat16*)(smem + AT_VL + so) = pl[d];
            }
        }
        __syncthreads();

        float sf[8][4];
        #pragma unroll
        for (int f = 0; f < 8; f++)
            #pragma unroll
            for (int t = 0; t < 4; t++) sf[f][t] = 0.f;

        #pragma unroll
        for (int ks = 0; ks < 8; ks++) {
            uint32_t qh[4], ql[4], kh[4][4], kl[4][4];
            {
                uint32_t off = SWZ256((uint32_t)((wid * 16 + rowA) * 256 + ks * 32 + kA * 16));
                LDSM_X4(qh, sb + AT_QH + off);
                LDSM_X4(ql, sb + AT_QL + off);
            }
            #pragma unroll
            for (int nj = 0; nj < 4; nj++) {
                uint32_t off = SWZ256((uint32_t)((nj * 16 + rowB) * 256 + ks * 32 + kB * 16));
                LDSM_X4(kh[nj], sb + AT_KH + off);
                LDSM_X4(kl[nj], sb + AT_KL + off);
            }
            #pragma unroll
            for (int nj = 0; nj < 4; nj++)
                #pragma unroll
                for (int hf = 0; hf < 2; hf++)
                    mma_bf16(sf[nj*2+hf], qh, kh[nj][hf*2], kh[nj][hf*2+1]);
            #pragma unroll
            for (int nj = 0; nj < 4; nj++)
                #pragma unroll
                for (int hf = 0; hf < 2; hf++)
                    mma_bf16(sf[nj*2+hf], qh, kl[nj][hf*2], kl[nj][hf*2+1]);
            #pragma unroll
            for (int nj = 0; nj < 4; nj++)
                #pragma unroll
                for (int hf = 0; hf < 2; hf++)
                    mma_bf16(sf[nj*2+hf], ql, kh[nj][hf*2], kh[nj][hf*2+1]);
        }

        const int myrow = q0 + wid * 16 + (lane >> 2);
        #pragma unroll
        for (int f = 0; f < 8; f++) {
            #pragma unroll
            for (int t = 0; t < 4; t++) sf[f][t] *= scale;
            if (kt == qt) {
                int col = k0 + f * 8 + (lane & 3) * 2;
                if (col > myrow)     sf[f][0] = -1e30f;
                if (col + 1 > myrow) sf[f][1] = -1e30f;
                if (col > myrow + 8)     sf[f][2] = -1e30f;
                if (col + 1 > myrow + 8) sf[f][3] = -1e30f;
            }
        }

        float mx0 = -1e30f, mx1 = -1e30f;
        #pragma unroll
        for (int f = 0; f < 8; f++) {
            mx0 = fmaxf(mx0, fmaxf(sf[f][0], sf[f][1]));
            mx1 = fmaxf(mx1, fmaxf(sf[f][2], sf[f][3]));
        }
        #pragma unroll
        for (int d = 1; d <= 2; d <<= 1) {
            mx0 = fmaxf(mx0, __shfl_xor_sync(0xFFFFFFFFu, mx0, d));
            mx1 = fmaxf(mx1, __shfl_xor_sync(0xFFFFFFFFu, mx1, d));
        }
        float mnew0 = fmaxf(mrow0, mx0);
        float mnew1 = fmaxf(mrow1, mx1);
        float alpha0 = __expf(mrow0 - mnew0);
        float alpha1 = __expf(mrow1 - mnew1);
        mrow0 = mnew0; mrow1 = mnew1;

        float rs0 = 0.f, rs1 = 0.f;
        uint32_t pha[8][2], pla[8][2];
        #pragma unroll
        for (int f = 0; f < 8; f++) {
            float p0 = __expf(sf[f][0] - mnew0);
            float p1 = __expf(sf[f][1] - mnew0);
            float p2 = __expf(sf[f][2] - mnew1);
            float p3 = __expf(sf[f][3] - mnew1);
            rs0 += p0 + p1; rs1 += p2 + p3;
            __nv_bfloat16 h0, l0, h1, l1, h2, l2, h3, l3;
            split2(p0, h0, l0); split2(p1, h1, l1);
            split2(p2, h2, l2); split2(p3, h3, l3);
            pha[f][0] = pack_bf16(__bfloat162float(h0), __bfloat162float(h1));
            pha[f][1] = pack_bf16(__bfloat162float(h2), __bfloat162float(h3));
            pla[f][0] = pack_bf16(__bfloat162float(l0), __bfloat162float(l1));
            pla[f][1] = pack_bf16(__bfloat162float(l2), __bfloat162float(l3));
        }
        #pragma unroll
        for (int d = 1; d <= 2; d <<= 1) {
            rs0 += __shfl_xor_sync(0xFFFFFFFFu, rs0, d);
            rs1 += __shfl_xor_sync(0xFFFFFFFFu, rs1, d);
        }
        lrow0 = lrow0 * alpha0 + rs0;
        lrow1 = lrow1 * alpha1 + rs1;

        #pragma unroll
        for (int g = 0; g < 16; g++) {
            ofrag[g][0] *= alpha0; ofrag[g][1] *= alpha0;
            ofrag[g][2] *= alpha1; ofrag[g][3] *= alpha1;
        }

        #pragma unroll
        for (int kk = 0; kk < 4; kk++) {
            uint32_t pa[4] = {pha[2*kk][0], pha[2*kk][1], pha[2*kk+1][0], pha[2*kk+1][1]};
            uint32_t pb[4] = {pla[2*kk][0], pla[2*kk][1], pla[2*kk+1][0], pla[2*kk+1][1]};
            #pragma unroll
            for (int g = 0; g < 8; g++) {
                uint32_t vh[4], vl[4];
                uint32_t off = SWZ128((uint32_t)((g * 16 + rowB) * 128 + kk * 32 + kB * 16));
                LDSM_X4(vh, sb + AT_VH + off);
                LDSM_X4(vl, sb + AT_VL + off);
                mma_bf16(ofrag[g*2+0], pa, vh[0], vh[1]);
                mma_bf16(ofrag[g*2+1], pa, vh[2], vh[3]);
                mma_bf16(ofrag[g*2+0], pa, vl[0], vl[1]);
                mma_bf16(ofrag[g*2+1], pa, vl[2], vl[3]);
                mma_bf16(ofrag[g*2+0], pb, vh[0], vh[1]);
                mma_bf16(ofrag[g*2+1], pb, vh[2], vh[3]);
            }
        }
    }

    float inv0 = 1.0f / lrow0;
    float inv1 = 1.0f / lrow1;
    const int r0 = q0 + wid * 16 + (lane >> 2);
    #pragma unroll
    for (int g = 0; g < 16; g++) {
        int col = h * KDH + g * 8 + (lane & 3) * 2;
        float v0 = ofrag[g][0] * inv0, v1 = ofrag[g][1] * inv0;
        float v2 = ofrag[g][2] * inv1, v3 = ofrag[g][3] * inv1;
        __nv_bfloat16 h0,l0,h1,l1,h2,l2,h3,l3;
        split2(v0,h0,l0); split2(v1,h1,l1); split2(v2,h2,l2); split2(v3,h3,l3);
        size_t i0 = (size_t)(b * KL + r0) * KD + col;
        size_t i1 = (size_t)(b * KL + r0 + 8) * KD + col;
        __nv_bfloat162 t;
        t.x = h0; t.y = h1; *(__nv_bfloat162*)(Oh + i0) = t;
        t.x = l0; t.y = l1; *(__nv_bfloat162*)(Ol + i0) = t;
        t.x = h2; t.y = h3; *(__nv_bfloat162*)(Oh + i1) = t;
        t.x = l2; t.y = l3; *(__nv_bfloat162*)(Ol + i1) = t;
    }
}

// ---------------------------------------------------------------------------
// kernel_launch
// ---------------------------------------------------------------------------
extern "C" void kernel_launch(void* const* d_in, const int* in_sizes, int n_in,
                              void* d_out, int out_size)
{
    const float* x    = (const float*)d_in[0];
    const float* ln1  = (const float*)d_in[2];
    const float* wq   = (const float*)d_in[3];
    const float* wk   = (const float*)d_in[4];
    const float* wv   = (const float*)d_in[5];
    const float* wo   = (const float*)d_in[6];
    const float* ln2  = (const float*)d_in[7];
    const float* wup  = (const float*)d_in[8];
    const float* wdn  = (const float*)d_in[9];
    float* out = (float*)d_out;

    __nv_bfloat16 *wq_h,*wq_l,*wk_h,*wk_l,*wv_h,*wv_l,*wo_h,*wo_l;
    __nv_bfloat16 *wu_h,*wu_l,*wd_h,*wd_l,*h_h,*h_l,*o_h,*o_l,*u_h,*u_l;
    __nv_bfloat16 *q_h,*q_l,*k_h,*k_l,*v_h,*v_l;
    cudaGetSymbolAddress((void**)&wq_h, g_wq_h);
    cudaGetSymbolAddress((void**)&wq_l, g_wq_l);
    cudaGetSymbolAddress((void**)&wk_h, g_wk_h);
    cudaGetSymbolAddress((void**)&wk_l, g_wk_l);
    cudaGetSymbolAddress((void**)&wv_h, g_wv_h);
    cudaGetSymbolAddress((void**)&wv_l, g_wv_l);
    cudaGetSymbolAddress((void**)&wo_h, g_wo_h);
    cudaGetSymbolAddress((void**)&wo_l, g_wo_l);
    cudaGetSymbolAddress((void**)&wu_h, g_wu_h);
    cudaGetSymbolAddress((void**)&wu_l, g_wu_l);
    cudaGetSymbolAddress((void**)&wd_h, g_wd_h);
    cudaGetSymbolAddress((void**)&wd_l, g_wd_l);
    cudaGetSymbolAddress((void**)&h_h, g_h_h);
    cudaGetSymbolAddress((void**)&h_l, g_h_l);
    cudaGetSymbolAddress((void**)&o_h, g_o_h);
    cudaGetSymbolAddress((void**)&o_l, g_o_l);
    cudaGetSymbolAddress((void**)&u_h, g_u_h);
    cudaGetSymbolAddress((void**)&u_l, g_u_l);
    cudaGetSymbolAddress((void**)&q_h, g_q_h);
    cudaGetSymbolAddress((void**)&q_l, g_q_l);
    cudaGetSymbolAddress((void**)&k_h, g_k_h);
    cudaGetSymbolAddress((void**)&k_l, g_k_l);
    cudaGetSymbolAddress((void**)&v_h, g_v_h);
    cudaGetSymbolAddress((void**)&v_l, g_v_l);

    cudaFuncSetAttribute(gemm_mma_kernel<0>, cudaFuncAttributeMaxDynamicSharedMemorySize, GEMM_SMEM);
    cudaFuncSetAttribute(gemm_mma_kernel<1>, cudaFuncAttributeMaxDynamicSharedMemorySize, GEMM_SMEM);
    cudaFuncSetAttribute(gemm_mma_kernel<2>, cudaFuncAttributeMaxDynamicSharedMemorySize, GEMM_SMEM);
    cudaFuncSetAttribute(gemm_mma_kernel<3>, cudaFuncAttributeMaxDynamicSharedMemorySize, GEMM_SMEM);
    cudaFuncSetAttribute(gemm_qkv_kernel, cudaFuncAttributeMaxDynamicSharedMemorySize, GEMM_SMEM);
    cudaFuncSetAttribute(attn_mma_kernel, cudaFuncAttributeMaxDynamicSharedMemorySize, ATT_SMEM);

    dim3 blk(256);
    dim3 gqkv3(3 * (KD / TN), KM / TM);   // 48 x 32 = 1536 CTAs
    dim3 gd(KD / TN, KM / TM);            // 16 x 32
    dim3 gup(KDFF / TN, KM / TM);         // 64 x 32

    const int n4  = KD * KD / 4;
    const int g4  = (n4 + 255) / 256;
    const int n4f = KDFF * KD / 4;
    const int g4f = (n4f + 255) / 256;

    QKVPtrs p;
    p.bh[0] = wq_h; p.bh[1] = wk_h; p.bh[2] = wv_h;
    p.bl[0] = wq_l; p.bl[1] = wk_l; p.bl[2] = wv_l;
    p.ch[0] = q_h;  p.ch[1] = k_h;  p.ch[2] = v_h;
    p.cl[0] = q_l;  p.cl[1] = k_l;  p.cl[2] = v_l;

    rmsnorm_split_kernel<<<KM, blk>>>(x, ln1, h_h, h_l);
    split_kernel<<<g4, blk>>>(wq, wq_h, wq_l, n4);
    split_kernel<<<g4, blk>>>(wk, wk_h, wk_l, n4);
    split_kernel<<<g4, blk>>>(wv, wv_h, wv_l, n4);

    gemm_qkv_kernel<<<gqkv3, blk, GEMM_SMEM>>>(h_h, h_l, p);
    dim3 gattn(KL / 64, KB * KH);
    attn_mma_kernel<<<gattn, dim3(128), ATT_SMEM>>>(q_h, q_l, k_h, k_l, v_h, v_l, o_h, o_l);

    split_kernel<<<g4, blk>>>(wo, wo_h, wo_l, n4);
    split_kernel<<<g4f, blk>>>(wup, wu_h, wu_l, n4f);
    split_kernel<<<g4f, blk>>>(wdn, wd_h, wd_l, n4f);

    gemm_mma_kernel<2><<<gd, blk, GEMM_SMEM>>>(o_h, o_l, wo_h, wo_l, out, x, nullptr, nullptr, KD, KD);

    rmsnorm_split_kernel<<<KM, blk>>>(out, ln2, h_h, h_l);

    gemm_mma_kernel<1><<<gup, blk, GEMM_SMEM>>>(h_h, h_l, wu_h, wu_l, nullptr, nullptr, u_h, u_l, KDFF, KD);

    gemm_mma_kernel<2><<<gd, blk, GEMM_SMEM>>>(u_h, u_l, wd_h, wd_l, out, out, nullptr, nullptr, KD, KDFF);
}

// round 9
// speedup vs baseline: 2.4463x; 2.3777x over previous
#include <cuda_runtime.h>
#include <cuda_fp16.h>
#include <math.h>
#include <stdint.h>

// ---------------------------------------------------------------------------
// TransformerBlock  B=2, L=2048, D=2048, H=16, DH=128, DFF=8192
// Round 8: single-product fp16 HMMA everywhere (3x less tensor work than the
// hi/lo-split scheme; fp32 accumulate keeps rel_err ~2-5e-4 < 1e-3).
// 128x128 CTA tiles, 3-stage cp.async, 2 CTAs/SM.
// ---------------------------------------------------------------------------

#define KB   2
#define KL   2048
#define KD   2048
#define KH   16
#define KDH  128
#define KDFF 8192
#define KM   (KB * KL)   // 4096 rows

// ----------------------------- PTX helpers --------------------------------
__device__ __forceinline__ uint32_t smem_u32(const void* p) {
    uint32_t a;
    asm("{ .reg .u64 t; cvta.to.shared.u64 t, %1; cvt.u32.u64 %0, t; }"
        : "=r"(a) : "l"(p));
    return a;
}

#define SWZ64(off)  ((off) ^ (((off) >> 3) & 0x30))   // 64B rows
#define SWZ128(off) ((off) ^ (((off) >> 3) & 0x70))   // 128B rows
#define SWZ256(off) ((off) ^ (((off) >> 4) & 0x70))   // 256B rows

#define CP_ASYNC16(smem, gptr) \
    asm volatile("cp.async.cg.shared.global [%0], [%1], 16;" \
        :: "r"((uint32_t)(smem)), "l"(gptr) : "memory")
#define CP_COMMIT() asm volatile("cp.async.commit_group;" ::: "memory")
#define CP_WAIT2()  asm volatile("cp.async.wait_group 2;" ::: "memory")

#define LDSM_X4(r, addr) \
    asm volatile("ldmatrix.sync.aligned.m8n8.x4.shared.b16 {%0,%1,%2,%3}, [%4];" \
        : "=r"((r)[0]), "=r"((r)[1]), "=r"((r)[2]), "=r"((r)[3]) \
        : "r"((uint32_t)(addr)))

__device__ __forceinline__ void mma_fp16(float* c, const uint32_t* a,
                                         uint32_t b0, uint32_t b1) {
    asm volatile(
        "mma.sync.aligned.m16n8k16.row.col.f32.f16.f16.f32 "
        "{%0,%1,%2,%3}, {%4,%5,%6,%7}, {%8,%9}, {%0,%1,%2,%3};"
        : "+f"(c[0]), "+f"(c[1]), "+f"(c[2]), "+f"(c[3])
        : "r"(a[0]), "r"(a[1]), "r"(a[2]), "r"(a[3]), "r"(b0), "r"(b1));
}

__device__ __forceinline__ uint32_t pack_h2(float a, float b) {
    __half2 t = __floats2half2_rn(a, b);
    return *(uint32_t*)&t;
}

// ------------------------------- scratch ----------------------------------
__device__ __half g_wq[(size_t)KD * KD];
__device__ __half g_wk[(size_t)KD * KD];
__device__ __half g_wv[(size_t)KD * KD];
__device__ __half g_wo[(size_t)KD * KD];
__device__ __half g_wu[(size_t)KDFF * KD];
__device__ __half g_wd[(size_t)KD * KDFF];
__device__ __half g_hh[(size_t)KM * KD];
__device__ __half g_qq[(size_t)KM * KD];
__device__ __half g_kk[(size_t)KM * KD];
__device__ __half g_vv[(size_t)KM * KD];
__device__ __half g_oo[(size_t)KM * KD];
__device__ __half g_uu[(size_t)KM * KDFF];

// ---------------------------------------------------------------------------
// fp32 -> fp16 convert
// ---------------------------------------------------------------------------
__global__ __launch_bounds__(256) void cvt_kernel(
    const float* __restrict__ src, __half* __restrict__ dst, int n4)
{
    int i = blockIdx.x * 256 + threadIdx.x;
    if (i >= n4) return;
    float4 v = ((const float4*)src)[i];
    __half h[4] = {__float2half_rn(v.x), __float2half_rn(v.y),
                   __float2half_rn(v.z), __float2half_rn(v.w)};
    ((uint2*)dst)[i] = *(uint2*)h;
}

// ---------------------------------------------------------------------------
// RMSNorm -> fp16
// ---------------------------------------------------------------------------
__global__ __launch_bounds__(256) void rmsnorm_kernel(
    const float* __restrict__ x, const float* __restrict__ w,
    __half* __restrict__ y)
{
    int row = blockIdx.x;
    const float* xr = x + (size_t)row * KD;
    float s = 0.f;
    #pragma unroll
    for (int i = threadIdx.x; i < KD; i += 256) { float v = xr[i]; s += v * v; }
    __shared__ float red[256];
    red[threadIdx.x] = s;
    __syncthreads();
    #pragma unroll
    for (int st = 128; st > 0; st >>= 1) {
        if (threadIdx.x < st) red[threadIdx.x] += red[threadIdx.x + st];
        __syncthreads();
    }
    float inv = rsqrtf(red[0] * (1.0f / KD) + 1e-8f);
    #pragma unroll
    for (int i = threadIdx.x; i < KD; i += 256)
        y[(size_t)row * KD + i] = __float2half_rn(xr[i] * inv * w[i]);
}

// ---------------------------------------------------------------------------
// fp16 GEMM: C[M,N] = A[M,K] @ Bw[N,K]^T, 128x128 tile, K-chunk 32,
// 3-stage cp.async, 2 CTAs/SM. Warp tile 64x32 (2x4 warps).
// EPI: 0 fp32 C, 1 GELU->fp16, 2 C = R + acc (fp32), 3 fp16
// ---------------------------------------------------------------------------
#define TM 128
#define TN 128
#define TKC 32
#define ABUF 8192u
#define BBUF 8192u
#define STAGE (ABUF + BBUF)          // 16384
#define GEMM_SMEM (3u * STAGE)       // 49152

#define GEMM_MAINLOOP(AP, BP, bmE, bnE, KE, NCE)                                \
    auto load_stage = [&](int c, int s) {                                       \
        const int kc = c * TKC;                                                 \
        const uint32_t base = sb + (uint32_t)s * STAGE;                         \
        _Pragma("unroll")                                                       \
        for (int i = 0; i < 2; i++) {                                           \
            int chunk = i * 256 + tid;                                          \
            int r = chunk >> 2, cc = chunk & 3;                                 \
            uint32_t so = SWZ64((uint32_t)(r * 64 + cc * 16));                  \
            CP_ASYNC16(base + so, (AP) + (size_t)((bmE) + r) * (KE) + kc + cc * 8); \
        }                                                                       \
        _Pragma("unroll")                                                       \
        for (int i = 0; i < 2; i++) {                                           \
            int chunk = i * 256 + tid;                                          \
            int r = chunk >> 2, cc = chunk & 3;                                 \
            uint32_t so = SWZ64((uint32_t)(r * 64 + cc * 16));                  \
            CP_ASYNC16(base + ABUF + so, (BP) + (size_t)((bnE) + r) * (KE) + kc + cc * 8); \
        }                                                                       \
        CP_COMMIT();                                                            \
    };                                                                          \
    load_stage(0, 0);                                                           \
    load_stage(1, 1);                                                           \
    _Pragma("unroll 1")                                                         \
    for (int c = 0; c < (NCE); c++) {                                           \
        const int s = c % 3;                                                    \
        __syncthreads();                                                        \
        if (c + 2 < (NCE)) load_stage(c + 2, (c + 2) % 3);                      \
        else               CP_COMMIT();                                         \
        CP_WAIT2();                                                             \
        __syncthreads();                                                        \
        const uint32_t sA = sb + (uint32_t)s * STAGE;                           \
        const uint32_t sB = sA + ABUF;                                          \
        _Pragma("unroll")                                                       \
        for (int h = 0; h < 2; h++) {                                           \
            uint32_t af[4][4], bf[2][4];                                        \
            _Pragma("unroll")                                                   \
            for (int mi = 0; mi < 4; mi++) {                                    \
                int m = wm * 64 + mi * 16 + rowA;                               \
                uint32_t off = SWZ64((uint32_t)(m * 64 + (h * 2 + kA) * 16));   \
                LDSM_X4(af[mi], sA + off);                                      \
            }                                                                   \
            _Pragma("unroll")                                                   \
            for (int nj = 0; nj < 2; nj++) {                                    \
                int n = wn * 32 + nj * 16 + rowB;                               \
                uint32_t off = SWZ64((uint32_t)(n * 64 + (h * 2 + kB) * 16));   \
                LDSM_X4(bf[nj], sB + off);                                      \
            }                                                                   \
            _Pragma("unroll")                                                   \
            for (int mi = 0; mi < 4; mi++)                                      \
                _Pragma("unroll")                                               \
                for (int nj = 0; nj < 2; nj++)                                  \
                    _Pragma("unroll")                                           \
                    for (int hf = 0; hf < 2; hf++)                              \
                        mma_fp16(acc[mi][nj*2+hf], af[mi],                      \
                                 bf[nj][hf*2], bf[nj][hf*2+1]);                 \
        }                                                                       \
    }

template<int EPI>
__global__ __launch_bounds__(256, 2) void gemm_mma_kernel(
    const __half* __restrict__ A, const __half* __restrict__ Bw,
    float* __restrict__ C, const float* __restrict__ R,
    __half* __restrict__ Ch, int N, int K)
{
    extern __shared__ char smem[];
    const uint32_t sb = smem_u32(smem);
    const int tid  = threadIdx.x;
    const int wid  = tid >> 5;
    const int lane = tid & 31;
    const int wm   = wid & 1;
    const int wn   = wid >> 1;
    const int bm   = blockIdx.y * TM;
    const int bn   = blockIdx.x * TN;
    const int NC   = K / TKC;

    const int mat  = lane >> 3;
    const int rin  = lane & 7;
    const int rowA = (mat & 1) * 8 + rin;
    const int kA   = mat >> 1;
    const int rowB = (mat >> 1) * 8 + rin;
    const int kB   = mat & 1;

    float acc[4][4][4];
    #pragma unroll
    for (int i = 0; i < 4; i++)
        #pragma unroll
        for (int j = 0; j < 4; j++)
            #pragma unroll
            for (int t = 0; t < 4; t++) acc[i][j][t] = 0.f;

    GEMM_MAINLOOP(A, Bw, bm, bn, K, NC)

    #pragma unroll
    for (int mi = 0; mi < 4; mi++) {
        const int row0 = bm + wm * 64 + mi * 16 + (lane >> 2);
        #pragma unroll
        for (int f = 0; f < 4; f++) {
            const int n0 = bn + wn * 32 + f * 8 + (lane & 3) * 2;
            float* cc = acc[mi][f];
            #pragma unroll
            for (int hrow = 0; hrow < 2; hrow++) {
                const int row = row0 + hrow * 8;
                float v0 = cc[hrow * 2 + 0];
                float v1 = cc[hrow * 2 + 1];
                const size_t idx = (size_t)row * N + n0;
                if (EPI == 1 || EPI == 3) {
                    if (EPI == 1) {
                        v0 = 0.5f * v0 * (1.0f + erff(v0 * 0.70710678118654752f));
                        v1 = 0.5f * v1 * (1.0f + erff(v1 * 0.70710678118654752f));
                    }
                    *(uint32_t*)(Ch + idx) = pack_h2(v0, v1);
                } else {
                    if (EPI == 2) {
                        float2 rv = *(const float2*)(R + idx);
                        v0 += rv.x; v1 += rv.y;
                    }
                    float2 ov; ov.x = v0; ov.y = v1;
                    *(float2*)(C + idx) = ov;
                }
            }
        }
    }
}

// ---------------------------------------------------------------------------
// Fused QKV GEMM
// ---------------------------------------------------------------------------
struct QKVPtrs {
    const __half* b[3];
    __half* c[3];
};

__global__ __launch_bounds__(256, 2) void gemm_qkv_kernel(
    const __half* __restrict__ A, QKVPtrs p)
{
    extern __shared__ char smem[];
    const uint32_t sb = smem_u32(smem);
    const int tid  = threadIdx.x;
    const int wid  = tid >> 5;
    const int lane = tid & 31;
    const int wm   = wid & 1;
    const int wn   = wid >> 1;
    const int which = blockIdx.x >> 4;
    const int bm   = blockIdx.y * TM;
    const int bn   = (blockIdx.x & 15) * TN;
    const int NC   = KD / TKC;

    const __half* __restrict__ Bw = p.b[which];
    __half* __restrict__ Ch = p.c[which];

    const int mat  = lane >> 3;
    const int rin  = lane & 7;
    const int rowA = (mat & 1) * 8 + rin;
    const int kA   = mat >> 1;
    const int rowB = (mat >> 1) * 8 + rin;
    const int kB   = mat & 1;

    float acc[4][4][4];
    #pragma unroll
    for (int i = 0; i < 4; i++)
        #pragma unroll
        for (int j = 0; j < 4; j++)
            #pragma unroll
            for (int t = 0; t < 4; t++) acc[i][j][t] = 0.f;

    GEMM_MAINLOOP(A, Bw, bm, bn, KD, NC)

    #pragma unroll
    for (int mi = 0; mi < 4; mi++) {
        const int row0 = bm + wm * 64 + mi * 16 + (lane >> 2);
        #pragma unroll
        for (int f = 0; f < 4; f++) {
            const int n0 = bn + wn * 32 + f * 8 + (lane & 3) * 2;
            float* cc = acc[mi][f];
            #pragma unroll
            for (int hrow = 0; hrow < 2; hrow++) {
                const int row = row0 + hrow * 8;
                const size_t idx = (size_t)row * KD + n0;
                *(uint32_t*)(Ch + idx) = pack_h2(cc[hrow*2+0], cc[hrow*2+1]);
            }
        }
    }
}

// ---------------------------------------------------------------------------
// fp16 tensor-core causal flash attention (FA2), reversed CTA order.
// SMEM: Q 16KB @0, K 16KB @16384, V^T 16KB @32768
// ---------------------------------------------------------------------------
#define AT_Q  0u
#define AT_K  16384u
#define AT_V  32768u
#define ATT_SMEM 49152u

__global__ __launch_bounds__(128, 2) void attn_mma_kernel(
    const __half* __restrict__ Qg, const __half* __restrict__ Kg,
    const __half* __restrict__ Vg, __half* __restrict__ Og)
{
    extern __shared__ char smem[];
    const uint32_t sb = smem_u32(smem);
    const int tid  = threadIdx.x;
    const int wid  = tid >> 5;
    const int lane = tid & 31;
    const int bh   = blockIdx.y;
    const int b    = bh >> 4;
    const int h    = bh & 15;
    const int qt   = gridDim.x - 1 - blockIdx.x;
    const int q0   = qt * 64;

    const int mat  = lane >> 3;
    const int rin  = lane & 7;
    const int rowA = (mat & 1) * 8 + rin;
    const int kA   = mat >> 1;
    const int rowB = (mat >> 1) * 8 + rin;
    const int kB   = mat & 1;

    const size_t hoff = (size_t)h * KDH;

    // load Q tile: 64 rows x 256B
    #pragma unroll
    for (int i = 0; i < 8; i++) {
        int idx = tid + i * 128;
        int r = idx >> 4, cc = idx & 15;
        uint32_t so = SWZ256((uint32_t)(r * 256 + cc * 16));
        size_t go = ((size_t)(b * KL + q0 + r)) * KD + hoff + cc * 8;
        *(uint4*)(smem + AT_Q + so) = *(const uint4*)(Qg + go);
    }

    float ofrag[16][4];
    #pragma unroll
    for (int g = 0; g < 16; g++)
        #pragma unroll
        for (int t = 0; t < 4; t++) ofrag[g][t] = 0.f;

    float mrow0 = -1e30f, mrow1 = -1e30f;
    float lrow0 = 0.f, lrow1 = 0.f;

    const float scale = 0.08838834764831845f;

    for (int kt = 0; kt <= qt; kt++) {
        const int k0 = kt * 64;
        __syncthreads();
        #pragma unroll
        for (int i = 0; i < 8; i++) {
            int idx = tid + i * 128;
            int r = idx >> 4, cc = idx & 15;
            uint32_t so = SWZ256((uint32_t)(r * 256 + cc * 16));
            size_t go = ((size_t)(b * KL + k0 + r)) * KD + hoff + cc * 8;
            *(uint4*)(smem + AT_K + so) = *(const uint4*)(Kg + go);
        }
        // V^T [dh=128][key=64], 128B rows
        #pragma unroll
        for (int i = 0; i < 16; i++) {
            int idx = tid + i * 128;
            int key = idx >> 5, d0 = (idx & 31) * 4;
            size_t go = ((size_t)(b * KL + k0 + key)) * KD + hoff + d0;
            uint2 v4 = *(const uint2*)(Vg + go);
            const __half* pv = (const __half*)&v4;
            #pragma unroll
            for (int d = 0; d < 4; d++) {
                uint32_t so = SWZ128((uint32_t)((d0 + d) * 128 + key * 2));
                *(__half*)(smem + AT_V + so) = pv[d];
            }
        }
        __syncthreads();

        float sf[8][4];
        #pragma unroll
        for (int f = 0; f < 8; f++)
            #pragma unroll
            for (int t = 0; t < 4; t++) sf[f][t] = 0.f;

        #pragma unroll
        for (int ks = 0; ks < 8; ks++) {
            uint32_t qf[4], kf[4][4];
            {
                uint32_t off = SWZ256((uint32_t)((wid * 16 + rowA) * 256 + ks * 32 + kA * 16));
                LDSM_X4(qf, sb + AT_Q + off);
            }
            #pragma unroll
            for (int nj = 0; nj < 4; nj++) {
                uint32_t off = SWZ256((uint32_t)((nj * 16 + rowB) * 256 + ks * 32 + kB * 16));
                LDSM_X4(kf[nj], sb + AT_K + off);
            }
            #pragma unroll
            for (int nj = 0; nj < 4; nj++)
                #pragma unroll
                for (int hf = 0; hf < 2; hf++)
                    mma_fp16(sf[nj*2+hf], qf, kf[nj][hf*2], kf[nj][hf*2+1]);
        }

        const int myrow = q0 + wid * 16 + (lane >> 2);
        #pragma unroll
        for (int f = 0; f < 8; f++) {
            #pragma unroll
            for (int t = 0; t < 4; t++) sf[f][t] *= scale;
            if (kt == qt) {
                int col = k0 + f * 8 + (lane & 3) * 2;
                if (col > myrow)     sf[f][0] = -1e30f;
                if (col + 1 > myrow) sf[f][1] = -1e30f;
                if (col > myrow + 8)     sf[f][2] = -1e30f;
                if (col + 1 > myrow + 8) sf[f][3] = -1e30f;
            }
        }

        float mx0 = -1e30f, mx1 = -1e30f;
        #pragma unroll
        for (int f = 0; f < 8; f++) {
            mx0 = fmaxf(mx0, fmaxf(sf[f][0], sf[f][1]));
            mx1 = fmaxf(mx1, fmaxf(sf[f][2], sf[f][3]));
        }
        #pragma unroll
        for (int d = 1; d <= 2; d <<= 1) {
            mx0 = fmaxf(mx0, __shfl_xor_sync(0xFFFFFFFFu, mx0, d));
            mx1 = fmaxf(mx1, __shfl_xor_sync(0xFFFFFFFFu, mx1, d));
        }
        float mnew0 = fmaxf(mrow0, mx0);
        float mnew1 = fmaxf(mrow1, mx1);
        float alpha0 = __expf(mrow0 - mnew0);
        float alpha1 = __expf(mrow1 - mnew1);
        mrow0 = mnew0; mrow1 = mnew1;

        float rs0 = 0.f, rs1 = 0.f;
        uint32_t pp[8][2];
        #pragma unroll
        for (int f = 0; f < 8; f++) {
            float p0 = __expf(sf[f][0] - mnew0);
            float p1 = __expf(sf[f][1] - mnew0);
            float p2 = __expf(sf[f][2] - mnew1);
            float p3 = __expf(sf[f][3] - mnew1);
            rs0 += p0 + p1; rs1 += p2 + p3;
            pp[f][0] = pack_h2(p0, p1);
            pp[f][1] = pack_h2(p2, p3);
        }
        #pragma unroll
        for (int d = 1; d <= 2; d <<= 1) {
            rs0 += __shfl_xor_sync(0xFFFFFFFFu, rs0, d);
            rs1 += __shfl_xor_sync(0xFFFFFFFFu, rs1, d);
        }
        lrow0 = lrow0 * alpha0 + rs0;
        lrow1 = lrow1 * alpha1 + rs1;

        #pragma unroll
        for (int g = 0; g < 16; g++) {
            ofrag[g][0] *= alpha0; ofrag[g][1] *= alpha0;
            ofrag[g][2] *= alpha1; ofrag[g][3] *= alpha1;
        }

        #pragma unroll
        for (int kk = 0; kk < 4; kk++) {
            uint32_t pa[4] = {pp[2*kk][0], pp[2*kk][1], pp[2*kk+1][0], pp[2*kk+1][1]};
            #pragma unroll
            for (int g = 0; g < 8; g++) {
                uint32_t vf[4];
                uint32_t off = SWZ128((uint32_t)((g * 16 + rowB) * 128 + kk * 32 + kB * 16));
                LDSM_X4(vf, sb + AT_V + off);
                mma_fp16(ofrag[g*2+0], pa, vf[0], vf[1]);
                mma_fp16(ofrag[g*2+1], pa, vf[2], vf[3]);
            }
        }
    }

    float inv0 = 1.0f / lrow0;
    float inv1 = 1.0f / lrow1;
    const int r0 = q0 + wid * 16 + (lane >> 2);
    #pragma unroll
    for (int g = 0; g < 16; g++) {
        int col = h * KDH + g * 8 + (lane & 3) * 2;
        size_t i0 = (size_t)(b * KL + r0) * KD + col;
        size_t i1 = (size_t)(b * KL + r0 + 8) * KD + col;
        *(uint32_t*)(Og + i0) = pack_h2(ofrag[g][0] * inv0, ofrag[g][1] * inv0);
        *(uint32_t*)(Og + i1) = pack_h2(ofrag[g][2] * inv1, ofrag[g][3] * inv1);
    }
}

// ---------------------------------------------------------------------------
// kernel_launch
// ---------------------------------------------------------------------------
extern "C" void kernel_launch(void* const* d_in, const int* in_sizes, int n_in,
                              void* d_out, int out_size)
{
    const float* x    = (const float*)d_in[0];
    const float* ln1  = (const float*)d_in[2];
    const float* wq   = (const float*)d_in[3];
    const float* wk   = (const float*)d_in[4];
    const float* wv   = (const float*)d_in[5];
    const float* wo   = (const float*)d_in[6];
    const float* ln2  = (const float*)d_in[7];
    const float* wup  = (const float*)d_in[8];
    const float* wdn  = (const float*)d_in[9];
    float* out = (float*)d_out;

    __half *wqh,*wkh,*wvh,*woh,*wuh,*wdh,*hh,*qq,*kk,*vv,*oo,*uu;
    cudaGetSymbolAddress((void**)&wqh, g_wq);
    cudaGetSymbolAddress((void**)&wkh, g_wk);
    cudaGetSymbolAddress((void**)&wvh, g_wv);
    cudaGetSymbolAddress((void**)&woh, g_wo);
    cudaGetSymbolAddress((void**)&wuh, g_wu);
    cudaGetSymbolAddress((void**)&wdh, g_wd);
    cudaGetSymbolAddress((void**)&hh, g_hh);
    cudaGetSymbolAddress((void**)&qq, g_qq);
    cudaGetSymbolAddress((void**)&kk, g_kk);
    cudaGetSymbolAddress((void**)&vv, g_vv);
    cudaGetSymbolAddress((void**)&oo, g_oo);
    cudaGetSymbolAddress((void**)&uu, g_uu);

    cudaFuncSetAttribute(gemm_mma_kernel<0>, cudaFuncAttributeMaxDynamicSharedMemorySize, GEMM_SMEM);
    cudaFuncSetAttribute(gemm_mma_kernel<1>, cudaFuncAttributeMaxDynamicSharedMemorySize, GEMM_SMEM);
    cudaFuncSetAttribute(gemm_mma_kernel<2>, cudaFuncAttributeMaxDynamicSharedMemorySize, GEMM_SMEM);
    cudaFuncSetAttribute(gemm_mma_kernel<3>, cudaFuncAttributeMaxDynamicSharedMemorySize, GEMM_SMEM);
    cudaFuncSetAttribute(gemm_qkv_kernel, cudaFuncAttributeMaxDynamicSharedMemorySize, GEMM_SMEM);
    cudaFuncSetAttribute(attn_mma_kernel, cudaFuncAttributeMaxDynamicSharedMemorySize, ATT_SMEM);

    dim3 blk(256);
    dim3 gqkv3(3 * (KD / TN), KM / TM);   // 48 x 32
    dim3 gd(KD / TN, KM / TM);            // 16 x 32
    dim3 gup(KDFF / TN, KM / TM);         // 64 x 32

    const int n4  = KD * KD / 4;
    const int g4  = (n4 + 255) / 256;
    const int n4f = KDFF * KD / 4;
    const int g4f = (n4f + 255) / 256;

    QKVPtrs p;
    p.b[0] = wqh; p.b[1] = wkh; p.b[2] = wvh;
    p.c[0] = qq;  p.c[1] = kk;  p.c[2] = vv;

    rmsnorm_kernel<<<KM, blk>>>(x, ln1, hh);
    cvt_kernel<<<g4, blk>>>(wq, wqh, n4);
    cvt_kernel<<<g4, blk>>>(wk, wkh, n4);
    cvt_kernel<<<g4, blk>>>(wv, wvh, n4);

    gemm_qkv_kernel<<<gqkv3, blk, GEMM_SMEM>>>(hh, p);
    dim3 gattn(KL / 64, KB * KH);
    attn_mma_kernel<<<gattn, dim3(128), ATT_SMEM>>>(qq, kk, vv, oo);

    cvt_kernel<<<g4, blk>>>(wo, woh, n4);
    cvt_kernel<<<g4f, blk>>>(wup, wuh, n4f);
    cvt_kernel<<<g4f, blk>>>(wdn, wdh, n4f);

    // out = x + o @ wo^T
    gemm_mma_kernel<2><<<gd, blk, GEMM_SMEM>>>(oo, woh, out, x, nullptr, KD, KD);

    // h = rmsnorm(out, ln2)
    rmsnorm_kernel<<<KM, blk>>>(out, ln2, hh);

    // u = gelu(h @ wup^T)
    gemm_mma_kernel<1><<<gup, blk, GEMM_SMEM>>>(hh, wuh, nullptr, nullptr, uu, KDFF, KD);

    // out = out + u @ wdn^T
    gemm_mma_kernel<2><<<gd, blk, GEMM_SMEM>>>(uu, wdh, out, out, nullptr, KD, KDFF);
}

// round 10
// speedup vs baseline: 2.5664x; 1.0491x over previous
#include <cuda_runtime.h>
#include <cuda_fp16.h>
#include <math.h>
#include <stdint.h>

// ---------------------------------------------------------------------------
// TransformerBlock  B=2, L=2048, D=2048, H=16, DH=128, DFF=8192
// Round 9: fp16 HMMA, K-chunk 64 (halved barrier density), SWZ128 tiles,
// 3-stage cp.async, 2 CTAs/SM.
// ---------------------------------------------------------------------------

#define KB   2
#define KL   2048
#define KD   2048
#define KH   16
#define KDH  128
#define KDFF 8192
#define KM   (KB * KL)   // 4096 rows

// ----------------------------- PTX helpers --------------------------------
__device__ __forceinline__ uint32_t smem_u32(const void* p) {
    uint32_t a;
    asm("{ .reg .u64 t; cvta.to.shared.u64 t, %1; cvt.u32.u64 %0, t; }"
        : "=r"(a) : "l"(p));
    return a;
}

#define SWZ128(off) ((off) ^ (((off) >> 3) & 0x70))   // 128B rows
#define SWZ256(off) ((off) ^ (((off) >> 4) & 0x70))   // 256B rows

#define CP_ASYNC16(smem, gptr) \
    asm volatile("cp.async.cg.shared.global [%0], [%1], 16;" \
        :: "r"((uint32_t)(smem)), "l"(gptr) : "memory")
#define CP_COMMIT() asm volatile("cp.async.commit_group;" ::: "memory")
#define CP_WAIT2()  asm volatile("cp.async.wait_group 2;" ::: "memory")

#define LDSM_X4(r, addr) \
    asm volatile("ldmatrix.sync.aligned.m8n8.x4.shared.b16 {%0,%1,%2,%3}, [%4];" \
        : "=r"((r)[0]), "=r"((r)[1]), "=r"((r)[2]), "=r"((r)[3]) \
        : "r"((uint32_t)(addr)))

__device__ __forceinline__ void mma_fp16(float* c, const uint32_t* a,
                                         uint32_t b0, uint32_t b1) {
    asm volatile(
        "mma.sync.aligned.m16n8k16.row.col.f32.f16.f16.f32 "
        "{%0,%1,%2,%3}, {%4,%5,%6,%7}, {%8,%9}, {%0,%1,%2,%3};"
        : "+f"(c[0]), "+f"(c[1]), "+f"(c[2]), "+f"(c[3])
        : "r"(a[0]), "r"(a[1]), "r"(a[2]), "r"(a[3]), "r"(b0), "r"(b1));
}

__device__ __forceinline__ uint32_t pack_h2(float a, float b) {
    __half2 t = __floats2half2_rn(a, b);
    return *(uint32_t*)&t;
}

// ------------------------------- scratch ----------------------------------
__device__ __half g_wq[(size_t)KD * KD];
__device__ __half g_wk[(size_t)KD * KD];
__device__ __half g_wv[(size_t)KD * KD];
__device__ __half g_wo[(size_t)KD * KD];
__device__ __half g_wu[(size_t)KDFF * KD];
__device__ __half g_wd[(size_t)KD * KDFF];
__device__ __half g_hh[(size_t)KM * KD];
__device__ __half g_qq[(size_t)KM * KD];
__device__ __half g_kk[(size_t)KM * KD];
__device__ __half g_vv[(size_t)KM * KD];
__device__ __half g_oo[(size_t)KM * KD];
__device__ __half g_uu[(size_t)KM * KDFF];

// ---------------------------------------------------------------------------
// fp32 -> fp16 convert
// ---------------------------------------------------------------------------
__global__ __launch_bounds__(256) void cvt_kernel(
    const float* __restrict__ src, __half* __restrict__ dst, int n4)
{
    int i = blockIdx.x * 256 + threadIdx.x;
    if (i >= n4) return;
    float4 v = ((const float4*)src)[i];
    __half h[4] = {__float2half_rn(v.x), __float2half_rn(v.y),
                   __float2half_rn(v.z), __float2half_rn(v.w)};
    ((uint2*)dst)[i] = *(uint2*)h;
}

// ---------------------------------------------------------------------------
// RMSNorm -> fp16
// ---------------------------------------------------------------------------
__global__ __launch_bounds__(256) void rmsnorm_kernel(
    const float* __restrict__ x, const float* __restrict__ w,
    __half* __restrict__ y)
{
    int row = blockIdx.x;
    const float* xr = x + (size_t)row * KD;
    float s = 0.f;
    #pragma unroll
    for (int i = threadIdx.x; i < KD; i += 256) { float v = xr[i]; s += v * v; }
    __shared__ float red[256];
    red[threadIdx.x] = s;
    __syncthreads();
    #pragma unroll
    for (int st = 128; st > 0; st >>= 1) {
        if (threadIdx.x < st) red[threadIdx.x] += red[threadIdx.x + st];
        __syncthreads();
    }
    float inv = rsqrtf(red[0] * (1.0f / KD) + 1e-8f);
    #pragma unroll
    for (int i = threadIdx.x; i < KD; i += 256)
        y[(size_t)row * KD + i] = __float2half_rn(xr[i] * inv * w[i]);
}

// ---------------------------------------------------------------------------
// fp16 GEMM: C[M,N] = A[M,K] @ Bw[N,K]^T, 128x128 tile, K-chunk 64,
// 3-stage cp.async (96KB), 2 CTAs/SM. Warp tile 64x32 (2x4 warps).
// EPI: 0 fp32 C, 1 GELU->fp16, 2 C = R + acc (fp32), 3 fp16
// ---------------------------------------------------------------------------
#define TM 128
#define TN 128
#define TKC 64
#define ABUF 16384u
#define BBUF 16384u
#define STAGE (ABUF + BBUF)          // 32768
#define GEMM_SMEM (3u * STAGE)       // 98304

#define GEMM_MAINLOOP(AP, BP, bmE, bnE, KE, NCE)                                \
    auto load_stage = [&](int c, int s) {                                       \
        const int kc = c * TKC;                                                 \
        const uint32_t base = sb + (uint32_t)s * STAGE;                         \
        _Pragma("unroll")                                                       \
        for (int i = 0; i < 4; i++) {                                           \
            int chunk = i * 256 + tid;      /* 0..1023 */                       \
            int r = chunk >> 3, cc = chunk & 7;                                 \
            uint32_t so = SWZ128((uint32_t)(r * 128 + cc * 16));                \
            CP_ASYNC16(base + so, (AP) + (size_t)((bmE) + r) * (KE) + kc + cc * 8); \
        }                                                                       \
        _Pragma("unroll")                                                       \
        for (int i = 0; i < 4; i++) {                                           \
            int chunk = i * 256 + tid;                                          \
            int r = chunk >> 3, cc = chunk & 7;                                 \
            uint32_t so = SWZ128((uint32_t)(r * 128 + cc * 16));                \
            CP_ASYNC16(base + ABUF + so, (BP) + (size_t)((bnE) + r) * (KE) + kc + cc * 8); \
        }                                                                       \
        CP_COMMIT();                                                            \
    };                                                                          \
    load_stage(0, 0);                                                           \
    load_stage(1, 1);                                                           \
    _Pragma("unroll 1")                                                         \
    for (int c = 0; c < (NCE); c++) {                                           \
        const int s = c % 3;                                                    \
        __syncthreads();                                                        \
        if (c + 2 < (NCE)) load_stage(c + 2, (c + 2) % 3);                      \
        else               CP_COMMIT();                                         \
        CP_WAIT2();                                                             \
        __syncthreads();                                                        \
        const uint32_t sA = sb + (uint32_t)s * STAGE;                           \
        const uint32_t sB = sA + ABUF;                                          \
        _Pragma("unroll")                                                       \
        for (int h = 0; h < 4; h++) {                                           \
            uint32_t af[4][4], bf[2][4];                                        \
            _Pragma("unroll")                                                   \
            for (int mi = 0; mi < 4; mi++) {                                    \
                int m = wm * 64 + mi * 16 + rowA;                               \
                uint32_t off = SWZ128((uint32_t)(m * 128 + (h * 2 + kA) * 16)); \
                LDSM_X4(af[mi], sA + off);                                      \
            }                                                                   \
            _Pragma("unroll")                                                   \
            for (int nj = 0; nj < 2; nj++) {                                    \
                int n = wn * 32 + nj * 16 + rowB;                               \
                uint32_t off = SWZ128((uint32_t)(n * 128 + (h * 2 + kB) * 16)); \
                LDSM_X4(bf[nj], sB + off);                                      \
            }                                                                   \
            _Pragma("unroll")                                                   \
            for (int mi = 0; mi < 4; mi++)                                      \
                _Pragma("unroll")                                               \
                for (int nj = 0; nj < 2; nj++)                                  \
                    _Pragma("unroll")                                           \
                    for (int hf = 0; hf < 2; hf++)                              \
                        mma_fp16(acc[mi][nj*2+hf], af[mi],                      \
                                 bf[nj][hf*2], bf[nj][hf*2+1]);                 \
        }                                                                       \
    }

template<int EPI>
__global__ __launch_bounds__(256, 2) void gemm_mma_kernel(
    const __half* __restrict__ A, const __half* __restrict__ Bw,
    float* __restrict__ C, const float* __restrict__ R,
    __half* __restrict__ Ch, int N, int K)
{
    extern __shared__ char smem[];
    const uint32_t sb = smem_u32(smem);
    const int tid  = threadIdx.x;
    const int wid  = tid >> 5;
    const int lane = tid & 31;
    const int wm   = wid & 1;
    const int wn   = wid >> 1;
    const int bm   = blockIdx.y * TM;
    const int bn   = blockIdx.x * TN;
    const int NC   = K / TKC;

    const int mat  = lane >> 3;
    const int rin  = lane & 7;
    const int rowA = (mat & 1) * 8 + rin;
    const int kA   = mat >> 1;
    const int rowB = (mat >> 1) * 8 + rin;
    const int kB   = mat & 1;

    float acc[4][4][4];
    #pragma unroll
    for (int i = 0; i < 4; i++)
        #pragma unroll
        for (int j = 0; j < 4; j++)
            #pragma unroll
            for (int t = 0; t < 4; t++) acc[i][j][t] = 0.f;

    GEMM_MAINLOOP(A, Bw, bm, bn, K, NC)

    #pragma unroll
    for (int mi = 0; mi < 4; mi++) {
        const int row0 = bm + wm * 64 + mi * 16 + (lane >> 2);
        #pragma unroll
        for (int f = 0; f < 4; f++) {
            const int n0 = bn + wn * 32 + f * 8 + (lane & 3) * 2;
            float* cc = acc[mi][f];
            #pragma unroll
            for (int hrow = 0; hrow < 2; hrow++) {
                const int row = row0 + hrow * 8;
                float v0 = cc[hrow * 2 + 0];
                float v1 = cc[hrow * 2 + 1];
                const size_t idx = (size_t)row * N + n0;
                if (EPI == 1 || EPI == 3) {
                    if (EPI == 1) {
                        v0 = 0.5f * v0 * (1.0f + erff(v0 * 0.70710678118654752f));
                        v1 = 0.5f * v1 * (1.0f + erff(v1 * 0.70710678118654752f));
                    }
                    *(uint32_t*)(Ch + idx) = pack_h2(v0, v1);
                } else {
                    if (EPI == 2) {
                        float2 rv = *(const float2*)(R + idx);
                        v0 += rv.x; v1 += rv.y;
                    }
                    float2 ov; ov.x = v0; ov.y = v1;
                    *(float2*)(C + idx) = ov;
                }
            }
        }
    }
}

// ---------------------------------------------------------------------------
// Fused QKV GEMM
// ---------------------------------------------------------------------------
struct QKVPtrs {
    const __half* b[3];
    __half* c[3];
};

__global__ __launch_bounds__(256, 2) void gemm_qkv_kernel(
    const __half* __restrict__ A, QKVPtrs p)
{
    extern __shared__ char smem[];
    const uint32_t sb = smem_u32(smem);
    const int tid  = threadIdx.x;
    const int wid  = tid >> 5;
    const int lane = tid & 31;
    const int wm   = wid & 1;
    const int wn   = wid >> 1;
    const int which = blockIdx.x >> 4;
    const int bm   = blockIdx.y * TM;
    const int bn   = (blockIdx.x & 15) * TN;
    const int NC   = KD / TKC;

    const __half* __restrict__ Bw = p.b[which];
    __half* __restrict__ Ch = p.c[which];

    const int mat  = lane >> 3;
    const int rin  = lane & 7;
    const int rowA = (mat & 1) * 8 + rin;
    const int kA   = mat >> 1;
    const int rowB = (mat >> 1) * 8 + rin;
    const int kB   = mat & 1;

    float acc[4][4][4];
    #pragma unroll
    for (int i = 0; i < 4; i++)
        #pragma unroll
        for (int j = 0; j < 4; j++)
            #pragma unroll
            for (int t = 0; t < 4; t++) acc[i][j][t] = 0.f;

    GEMM_MAINLOOP(A, Bw, bm, bn, KD, NC)

    #pragma unroll
    for (int mi = 0; mi < 4; mi++) {
        const int row0 = bm + wm * 64 + mi * 16 + (lane >> 2);
        #pragma unroll
        for (int f = 0; f < 4; f++) {
            const int n0 = bn + wn * 32 + f * 8 + (lane & 3) * 2;
            float* cc = acc[mi][f];
            #pragma unroll
            for (int hrow = 0; hrow < 2; hrow++) {
                const int row = row0 + hrow * 8;
                const size_t idx = (size_t)row * KD + n0;
                *(uint32_t*)(Ch + idx) = pack_h2(cc[hrow*2+0], cc[hrow*2+1]);
            }
        }
    }
}

// ---------------------------------------------------------------------------
// fp16 tensor-core causal flash attention (FA2), reversed CTA order.
// SMEM: Q 16KB @0, K 16KB @16384, V^T 16KB @32768
// ---------------------------------------------------------------------------
#define AT_Q  0u
#define AT_K  16384u
#define AT_V  32768u
#define ATT_SMEM 49152u

__global__ __launch_bounds__(128, 2) void attn_mma_kernel(
    const __half* __restrict__ Qg, const __half* __restrict__ Kg,
    const __half* __restrict__ Vg, __half* __restrict__ Og)
{
    extern __shared__ char smem[];
    const uint32_t sb = smem_u32(smem);
    const int tid  = threadIdx.x;
    const int wid  = tid >> 5;
    const int lane = tid & 31;
    const int bh   = blockIdx.y;
    const int b    = bh >> 4;
    const int h    = bh & 15;
    const int qt   = gridDim.x - 1 - blockIdx.x;
    const int q0   = qt * 64;

    const int mat  = lane >> 3;
    const int rin  = lane & 7;
    const int rowA = (mat & 1) * 8 + rin;
    const int kA   = mat >> 1;
    const int rowB = (mat >> 1) * 8 + rin;
    const int kB   = mat & 1;

    const size_t hoff = (size_t)h * KDH;

    #pragma unroll
    for (int i = 0; i < 8; i++) {
        int idx = tid + i * 128;
        int r = idx >> 4, cc = idx & 15;
        uint32_t so = SWZ256((uint32_t)(r * 256 + cc * 16));
        size_t go = ((size_t)(b * KL + q0 + r)) * KD + hoff + cc * 8;
        *(uint4*)(smem + AT_Q + so) = *(const uint4*)(Qg + go);
    }

    float ofrag[16][4];
    #pragma unroll
    for (int g = 0; g < 16; g++)
        #pragma unroll
        for (int t = 0; t < 4; t++) ofrag[g][t] = 0.f;

    float mrow0 = -1e30f, mrow1 = -1e30f;
    float lrow0 = 0.f, lrow1 = 0.f;

    const float scale = 0.08838834764831845f;

    for (int kt = 0; kt <= qt; kt++) {
        const int k0 = kt * 64;
        __syncthreads();
        #pragma unroll
        for (int i = 0; i < 8; i++) {
            int idx = tid + i * 128;
            int r = idx >> 4, cc = idx & 15;
            uint32_t so = SWZ256((uint32_t)(r * 256 + cc * 16));
            size_t go = ((size_t)(b * KL + k0 + r)) * KD + hoff + cc * 8;
            *(uint4*)(smem + AT_K + so) = *(const uint4*)(Kg + go);
        }
        #pragma unroll
        for (int i = 0; i < 16; i++) {
            int idx = tid + i * 128;
            int key = idx >> 5, d0 = (idx & 31) * 4;
            size_t go = ((size_t)(b * KL + k0 + key)) * KD + hoff + d0;
            uint2 v4 = *(const uint2*)(Vg + go);
            const __half* pv = (const __half*)&v4;
            #pragma unroll
            for (int d = 0; d < 4; d++) {
                uint32_t so = SWZ128((uint32_t)((d0 + d) * 128 + key * 2));
                *(__half*)(smem + AT_V + so) = pv[d];
            }
        }
        __syncthreads();

        float sf[8][4];
        #pragma unroll
        for (int f = 0; f < 8; f++)
            #pragma unroll
            for (int t = 0; t < 4; t++) sf[f][t] = 0.f;

        #pragma unroll
        for (int ks = 0; ks < 8; ks++) {
            uint32_t qf[4], kf[4][4];
            {
                uint32_t off = SWZ256((uint32_t)((wid * 16 + rowA) * 256 + ks * 32 + kA * 16));
                LDSM_X4(qf, sb + AT_Q + off);
            }
            #pragma unroll
            for (int nj = 0; nj < 4; nj++) {
                uint32_t off = SWZ256((uint32_t)((nj * 16 + rowB) * 256 + ks * 32 + kB * 16));
                LDSM_X4(kf[nj], sb + AT_K + off);
            }
            #pragma unroll
            for (int nj = 0; nj < 4; nj++)
                #pragma unroll
                for (int hf = 0; hf < 2; hf++)
                    mma_fp16(sf[nj*2+hf], qf, kf[nj][hf*2], kf[nj][hf*2+1]);
        }

        const int myrow = q0 + wid * 16 + (lane >> 2);
        #pragma unroll
        for (int f = 0; f < 8; f++) {
            #pragma unroll
            for (int t = 0; t < 4; t++) sf[f][t] *= scale;
            if (kt == qt) {
                int col = k0 + f * 8 + (lane & 3) * 2;
                if (col > myrow)     sf[f][0] = -1e30f;
                if (col + 1 > myrow) sf[f][1] = -1e30f;
                if (col > myrow + 8)     sf[f][2] = -1e30f;
                if (col + 1 > myrow + 8) sf[f][3] = -1e30f;
            }
        }

        float mx0 = -1e30f, mx1 = -1e30f;
        #pragma unroll
        for (int f = 0; f < 8; f++) {
            mx0 = fmaxf(mx0, fmaxf(sf[f][0], sf[f][1]));
            mx1 = fmaxf(mx1, fmaxf(sf[f][2], sf[f][3]));
        }
        #pragma unroll
        for (int d = 1; d <= 2; d <<= 1) {
            mx0 = fmaxf(mx0, __shfl_xor_sync(0xFFFFFFFFu, mx0, d));
            mx1 = fmaxf(mx1, __shfl_xor_sync(0xFFFFFFFFu, mx1, d));
        }
        float mnew0 = fmaxf(mrow0, mx0);
        float mnew1 = fmaxf(mrow1, mx1);
        float alpha0 = __expf(mrow0 - mnew0);
        float alpha1 = __expf(mrow1 - mnew1);
        mrow0 = mnew0; mrow1 = mnew1;

        float rs0 = 0.f, rs1 = 0.f;
        uint32_t pp[8][2];
        #pragma unroll
        for (int f = 0; f < 8; f++) {
            float p0 = __expf(sf[f][0] - mnew0);
            float p1 = __expf(sf[f][1] - mnew0);
            float p2 = __expf(sf[f][2] - mnew1);
            float p3 = __expf(sf[f][3] - mnew1);
            rs0 += p0 + p1; rs1 += p2 + p3;
            pp[f][0] = pack_h2(p0, p1);
            pp[f][1] = pack_h2(p2, p3);
        }
        #pragma unroll
        for (int d = 1; d <= 2; d <<= 1) {
            rs0 += __shfl_xor_sync(0xFFFFFFFFu, rs0, d);
            rs1 += __shfl_xor_sync(0xFFFFFFFFu, rs1, d);
        }
        lrow0 = lrow0 * alpha0 + rs0;
        lrow1 = lrow1 * alpha1 + rs1;

        #pragma unroll
        for (int g = 0; g < 16; g++) {
            ofrag[g][0] *= alpha0; ofrag[g][1] *= alpha0;
            ofrag[g][2] *= alpha1; ofrag[g][3] *= alpha1;
        }

        #pragma unroll
        for (int kk = 0; kk < 4; kk++) {
            uint32_t pa[4] = {pp[2*kk][0], pp[2*kk][1], pp[2*kk+1][0], pp[2*kk+1][1]};
            #pragma unroll
            for (int g = 0; g < 8; g++) {
                uint32_t vf[4];
                uint32_t off = SWZ128((uint32_t)((g * 16 + rowB) * 128 + kk * 32 + kB * 16));
                LDSM_X4(vf, sb + AT_V + off);
                mma_fp16(ofrag[g*2+0], pa, vf[0], vf[1]);
                mma_fp16(ofrag[g*2+1], pa, vf[2], vf[3]);
            }
        }
    }

    float inv0 = 1.0f / lrow0;
    float inv1 = 1.0f / lrow1;
    const int r0 = q0 + wid * 16 + (lane >> 2);
    #pragma unroll
    for (int g = 0; g < 16; g++) {
        int col = h * KDH + g * 8 + (lane & 3) * 2;
        size_t i0 = (size_t)(b * KL + r0) * KD + col;
        size_t i1 = (size_t)(b * KL + r0 + 8) * KD + col;
        *(uint32_t*)(Og + i0) = pack_h2(ofrag[g][0] * inv0, ofrag[g][1] * inv0);
        *(uint32_t*)(Og + i1) = pack_h2(ofrag[g][2] * inv1, ofrag[g][3] * inv1);
    }
}

// ---------------------------------------------------------------------------
// kernel_launch
// ---------------------------------------------------------------------------
extern "C" void kernel_launch(void* const* d_in, const int* in_sizes, int n_in,
                              void* d_out, int out_size)
{
    const float* x    = (const float*)d_in[0];
    const float* ln1  = (const float*)d_in[2];
    const float* wq   = (const float*)d_in[3];
    const float* wk   = (const float*)d_in[4];
    const float* wv   = (const float*)d_in[5];
    const float* wo   = (const float*)d_in[6];
    const float* ln2  = (const float*)d_in[7];
    const float* wup  = (const float*)d_in[8];
    const float* wdn  = (const float*)d_in[9];
    float* out = (float*)d_out;

    __half *wqh,*wkh,*wvh,*woh,*wuh,*wdh,*hh,*qq,*kk,*vv,*oo,*uu;
    cudaGetSymbolAddress((void**)&wqh, g_wq);
    cudaGetSymbolAddress((void**)&wkh, g_wk);
    cudaGetSymbolAddress((void**)&wvh, g_wv);
    cudaGetSymbolAddress((void**)&woh, g_wo);
    cudaGetSymbolAddress((void**)&wuh, g_wu);
    cudaGetSymbolAddress((void**)&wdh, g_wd);
    cudaGetSymbolAddress((void**)&hh, g_hh);
    cudaGetSymbolAddress((void**)&qq, g_qq);
    cudaGetSymbolAddress((void**)&kk, g_kk);
    cudaGetSymbolAddress((void**)&vv, g_vv);
    cudaGetSymbolAddress((void**)&oo, g_oo);
    cudaGetSymbolAddress((void**)&uu, g_uu);

    cudaFuncSetAttribute(gemm_mma_kernel<0>, cudaFuncAttributeMaxDynamicSharedMemorySize, GEMM_SMEM);
    cudaFuncSetAttribute(gemm_mma_kernel<1>, cudaFuncAttributeMaxDynamicSharedMemorySize, GEMM_SMEM);
    cudaFuncSetAttribute(gemm_mma_kernel<2>, cudaFuncAttributeMaxDynamicSharedMemorySize, GEMM_SMEM);
    cudaFuncSetAttribute(gemm_mma_kernel<3>, cudaFuncAttributeMaxDynamicSharedMemorySize, GEMM_SMEM);
    cudaFuncSetAttribute(gemm_qkv_kernel, cudaFuncAttributeMaxDynamicSharedMemorySize, GEMM_SMEM);
    cudaFuncSetAttribute(attn_mma_kernel, cudaFuncAttributeMaxDynamicSharedMemorySize, ATT_SMEM);

    dim3 blk(256);
    dim3 gqkv3(3 * (KD / TN), KM / TM);   // 48 x 32
    dim3 gd(KD / TN, KM / TM);            // 16 x 32
    dim3 gup(KDFF / TN, KM / TM);         // 64 x 32

    const int n4  = KD * KD / 4;
    const int g4  = (n4 + 255) / 256;
    const int n4f = KDFF * KD / 4;
    const int g4f = (n4f + 255) / 256;

    QKVPtrs p;
    p.b[0] = wqh; p.b[1] = wkh; p.b[2] = wvh;
    p.c[0] = qq;  p.c[1] = kk;  p.c[2] = vv;

    rmsnorm_kernel<<<KM, blk>>>(x, ln1, hh);
    cvt_kernel<<<g4, blk>>>(wq, wqh, n4);
    cvt_kernel<<<g4, blk>>>(wk, wkh, n4);
    cvt_kernel<<<g4, blk>>>(wv, wvh, n4);

    gemm_qkv_kernel<<<gqkv3, blk, GEMM_SMEM>>>(hh, p);
    dim3 gattn(KL / 64, KB * KH);
    attn_mma_kernel<<<gattn, dim3(128), ATT_SMEM>>>(qq, kk, vv, oo);

    cvt_kernel<<<g4, blk>>>(wo, woh, n4);
    cvt_kernel<<<g4f, blk>>>(wup, wuh, n4f);
    cvt_kernel<<<g4f, blk>>>(wdn, wdh, n4f);

    // out = x + o @ wo^T
    gemm_mma_kernel<2><<<gd, blk, GEMM_SMEM>>>(oo, woh, out, x, nullptr, KD, KD);

    // h = rmsnorm(out, ln2)
    rmsnorm_kernel<<<KM, blk>>>(out, ln2, hh);

    // u = gelu(h @ wup^T)
    gemm_mma_kernel<1><<<gup, blk, GEMM_SMEM>>>(hh, wuh, nullptr, nullptr, uu, KDFF, KD);

    // out = out + u @ wdn^T
    gemm_mma_kernel<2><<<gd, blk, GEMM_SMEM>>>(uu, wdh, out, out, nullptr, KD, KDFF);
}

// round 11
// speedup vs baseline: 2.6095x; 1.0168x over previous
#include <cuda_runtime.h>
#include <cuda_fp16.h>
#include <math.h>
#include <stdint.h>

// ---------------------------------------------------------------------------
// TransformerBlock  B=2, L=2048, D=2048, H=16, DH=128, DFF=8192
// Round 10: R9 compute kernels + dual-stream graph fork/join so weight
// conversions overlap rmsnorm / QKV GEMM / attention; 4x-work cvt kernel.
// ---------------------------------------------------------------------------

#define KB   2
#define KL   2048
#define KD   2048
#define KH   16
#define KDH  128
#define KDFF 8192
#define KM   (KB * KL)   // 4096 rows

// ----------------------------- PTX helpers --------------------------------
__device__ __forceinline__ uint32_t smem_u32(const void* p) {
    uint32_t a;
    asm("{ .reg .u64 t; cvta.to.shared.u64 t, %1; cvt.u32.u64 %0, t; }"
        : "=r"(a) : "l"(p));
    return a;
}

#define SWZ128(off) ((off) ^ (((off) >> 3) & 0x70))   // 128B rows
#define SWZ256(off) ((off) ^ (((off) >> 4) & 0x70))   // 256B rows

#define CP_ASYNC16(smem, gptr) \
    asm volatile("cp.async.cg.shared.global [%0], [%1], 16;" \
        :: "r"((uint32_t)(smem)), "l"(gptr) : "memory")
#define CP_COMMIT() asm volatile("cp.async.commit_group;" ::: "memory")
#define CP_WAIT2()  asm volatile("cp.async.wait_group 2;" ::: "memory")

#define LDSM_X4(r, addr) \
    asm volatile("ldmatrix.sync.aligned.m8n8.x4.shared.b16 {%0,%1,%2,%3}, [%4];" \
        : "=r"((r)[0]), "=r"((r)[1]), "=r"((r)[2]), "=r"((r)[3]) \
        : "r"((uint32_t)(addr)))

__device__ __forceinline__ void mma_fp16(float* c, const uint32_t* a,
                                         uint32_t b0, uint32_t b1) {
    asm volatile(
        "mma.sync.aligned.m16n8k16.row.col.f32.f16.f16.f32 "
        "{%0,%1,%2,%3}, {%4,%5,%6,%7}, {%8,%9}, {%0,%1,%2,%3};"
        : "+f"(c[0]), "+f"(c[1]), "+f"(c[2]), "+f"(c[3])
        : "r"(a[0]), "r"(a[1]), "r"(a[2]), "r"(a[3]), "r"(b0), "r"(b1));
}

__device__ __forceinline__ uint32_t pack_h2(float a, float b) {
    __half2 t = __floats2half2_rn(a, b);
    return *(uint32_t*)&t;
}

// ------------------------------- scratch ----------------------------------
__device__ __half g_wq[(size_t)KD * KD];
__device__ __half g_wk[(size_t)KD * KD];
__device__ __half g_wv[(size_t)KD * KD];
__device__ __half g_wo[(size_t)KD * KD];
__device__ __half g_wu[(size_t)KDFF * KD];
__device__ __half g_wd[(size_t)KD * KDFF];
__device__ __half g_hh[(size_t)KM * KD];
__device__ __half g_qq[(size_t)KM * KD];
__device__ __half g_kk[(size_t)KM * KD];
__device__ __half g_vv[(size_t)KM * KD];
__device__ __half g_oo[(size_t)KM * KD];
__device__ __half g_uu[(size_t)KM * KDFF];

// ---------------------------------------------------------------------------
// fp32 -> fp16 convert, 4 float4 per thread (n4 must be multiple of 1024)
// ---------------------------------------------------------------------------
__global__ __launch_bounds__(256) void cvt_kernel(
    const float* __restrict__ src, __half* __restrict__ dst, int n4)
{
    int base = blockIdx.x * 1024 + threadIdx.x;
    #pragma unroll
    for (int j = 0; j < 4; j++) {
        int i = base + j * 256;
        if (i >= n4) return;
        float4 v = ((const float4*)src)[i];
        __half h[4] = {__float2half_rn(v.x), __float2half_rn(v.y),
                       __float2half_rn(v.z), __float2half_rn(v.w)};
        ((uint2*)dst)[i] = *(uint2*)h;
    }
}

// ---------------------------------------------------------------------------
// RMSNorm -> fp16
// ---------------------------------------------------------------------------
__global__ __launch_bounds__(256) void rmsnorm_kernel(
    const float* __restrict__ x, const float* __restrict__ w,
    __half* __restrict__ y)
{
    int row = blockIdx.x;
    const float* xr = x + (size_t)row * KD;
    float s = 0.f;
    #pragma unroll
    for (int i = threadIdx.x; i < KD; i += 256) { float v = xr[i]; s += v * v; }
    __shared__ float red[256];
    red[threadIdx.x] = s;
    __syncthreads();
    #pragma unroll
    for (int st = 128; st > 0; st >>= 1) {
        if (threadIdx.x < st) red[threadIdx.x] += red[threadIdx.x + st];
        __syncthreads();
    }
    float inv = rsqrtf(red[0] * (1.0f / KD) + 1e-8f);
    #pragma unroll
    for (int i = threadIdx.x; i < KD; i += 256)
        y[(size_t)row * KD + i] = __float2half_rn(xr[i] * inv * w[i]);
}

// ---------------------------------------------------------------------------
// fp16 GEMM: C[M,N] = A[M,K] @ Bw[N,K]^T, 128x128 tile, K-chunk 64,
// 3-stage cp.async (96KB), 2 CTAs/SM. Warp tile 64x32 (2x4 warps).
// ---------------------------------------------------------------------------
#define TM 128
#define TN 128
#define TKC 64
#define ABUF 16384u
#define BBUF 16384u
#define STAGE (ABUF + BBUF)          // 32768
#define GEMM_SMEM (3u * STAGE)       // 98304

#define GEMM_MAINLOOP(AP, BP, bmE, bnE, KE, NCE)                                \
    auto load_stage = [&](int c, int s) {                                       \
        const int kc = c * TKC;                                                 \
        const uint32_t base = sb + (uint32_t)s * STAGE;                         \
        _Pragma("unroll")                                                       \
        for (int i = 0; i < 4; i++) {                                           \
            int chunk = i * 256 + tid;      /* 0..1023 */                       \
            int r = chunk >> 3, cc = chunk & 7;                                 \
            uint32_t so = SWZ128((uint32_t)(r * 128 + cc * 16));                \
            CP_ASYNC16(base + so, (AP) + (size_t)((bmE) + r) * (KE) + kc + cc * 8); \
        }                                                                       \
        _Pragma("unroll")                                                       \
        for (int i = 0; i < 4; i++) {                                           \
            int chunk = i * 256 + tid;                                          \
            int r = chunk >> 3, cc = chunk & 7;                                 \
            uint32_t so = SWZ128((uint32_t)(r * 128 + cc * 16));                \
            CP_ASYNC16(base + ABUF + so, (BP) + (size_t)((bnE) + r) * (KE) + kc + cc * 8); \
        }                                                                       \
        CP_COMMIT();                                                            \
    };                                                                          \
    load_stage(0, 0);                                                           \
    load_stage(1, 1);                                                           \
    _Pragma("unroll 1")                                                         \
    for (int c = 0; c < (NCE); c++) {                                           \
        const int s = c % 3;                                                    \
        __syncthreads();                                                        \
        if (c + 2 < (NCE)) load_stage(c + 2, (c + 2) % 3);                      \
        else               CP_COMMIT();                                         \
        CP_WAIT2();                                                             \
        __syncthreads();                                                        \
        const uint32_t sA = sb + (uint32_t)s * STAGE;                           \
        const uint32_t sB = sA + ABUF;                                          \
        _Pragma("unroll")                                                       \
        for (int h = 0; h < 4; h++) {                                           \
            uint32_t af[4][4], bf[2][4];                                        \
            _Pragma("unroll")                                                   \
            for (int mi = 0; mi < 4; mi++) {                                    \
                int m = wm * 64 + mi * 16 + rowA;                               \
                uint32_t off = SWZ128((uint32_t)(m * 128 + (h * 2 + kA) * 16)); \
                LDSM_X4(af[mi], sA + off);                                      \
            }                                                                   \
            _Pragma("unroll")                                                   \
            for (int nj = 0; nj < 2; nj++) {                                    \
                int n = wn * 32 + nj * 16 + rowB;                               \
                uint32_t off = SWZ128((uint32_t)(n * 128 + (h * 2 + kB) * 16)); \
                LDSM_X4(bf[nj], sB + off);                                      \
            }                                                                   \
            _Pragma("unroll")                                                   \
            for (int mi = 0; mi < 4; mi++)                                      \
                _Pragma("unroll")                                               \
                for (int nj = 0; nj < 2; nj++)                                  \
                    _Pragma("unroll")                                           \
                    for (int hf = 0; hf < 2; hf++)                              \
                        mma_fp16(acc[mi][nj*2+hf], af[mi],                      \
                                 bf[nj][hf*2], bf[nj][hf*2+1]);                 \
        }                                                                       \
    }

template<int EPI>
__global__ __launch_bounds__(256, 2) void gemm_mma_kernel(
    const __half* __restrict__ A, const __half* __restrict__ Bw,
    float* __restrict__ C, const float* __restrict__ R,
    __half* __restrict__ Ch, int N, int K)
{
    extern __shared__ char smem[];
    const uint32_t sb = smem_u32(smem);
    const int tid  = threadIdx.x;
    const int wid  = tid >> 5;
    const int lane = tid & 31;
    const int wm   = wid & 1;
    const int wn   = wid >> 1;
    const int bm   = blockIdx.y * TM;
    const int bn   = blockIdx.x * TN;
    const int NC   = K / TKC;

    const int mat  = lane >> 3;
    const int rin  = lane & 7;
    const int rowA = (mat & 1) * 8 + rin;
    const int kA   = mat >> 1;
    const int rowB = (mat >> 1) * 8 + rin;
    const int kB   = mat & 1;

    float acc[4][4][4];
    #pragma unroll
    for (int i = 0; i < 4; i++)
        #pragma unroll
        for (int j = 0; j < 4; j++)
            #pragma unroll
            for (int t = 0; t < 4; t++) acc[i][j][t] = 0.f;

    GEMM_MAINLOOP(A, Bw, bm, bn, K, NC)

    #pragma unroll
    for (int mi = 0; mi < 4; mi++) {
        const int row0 = bm + wm * 64 + mi * 16 + (lane >> 2);
        #pragma unroll
        for (int f = 0; f < 4; f++) {
            const int n0 = bn + wn * 32 + f * 8 + (lane & 3) * 2;
            float* cc = acc[mi][f];
            #pragma unroll
            for (int hrow = 0; hrow < 2; hrow++) {
                const int row = row0 + hrow * 8;
                float v0 = cc[hrow * 2 + 0];
                float v1 = cc[hrow * 2 + 1];
                const size_t idx = (size_t)row * N + n0;
                if (EPI == 1 || EPI == 3) {
                    if (EPI == 1) {
                        v0 = 0.5f * v0 * (1.0f + erff(v0 * 0.70710678118654752f));
                        v1 = 0.5f * v1 * (1.0f + erff(v1 * 0.70710678118654752f));
                    }
                    *(uint32_t*)(Ch + idx) = pack_h2(v0, v1);
                } else {
                    if (EPI == 2) {
                        float2 rv = *(const float2*)(R + idx);
                        v0 += rv.x; v1 += rv.y;
                    }
                    float2 ov; ov.x = v0; ov.y = v1;
                    *(float2*)(C + idx) = ov;
                }
            }
        }
    }
}

// ---------------------------------------------------------------------------
// Fused QKV GEMM
// ---------------------------------------------------------------------------
struct QKVPtrs {
    const __half* b[3];
    __half* c[3];
};

__global__ __launch_bounds__(256, 2) void gemm_qkv_kernel(
    const __half* __restrict__ A, QKVPtrs p)
{
    extern __shared__ char smem[];
    const uint32_t sb = smem_u32(smem);
    const int tid  = threadIdx.x;
    const int wid  = tid >> 5;
    const int lane = tid & 31;
    const int wm   = wid & 1;
    const int wn   = wid >> 1;
    const int which = blockIdx.x >> 4;
    const int bm   = blockIdx.y * TM;
    const int bn   = (blockIdx.x & 15) * TN;
    const int NC   = KD / TKC;

    const __half* __restrict__ Bw = p.b[which];
    __half* __restrict__ Ch = p.c[which];

    const int mat  = lane >> 3;
    const int rin  = lane & 7;
    const int rowA = (mat & 1) * 8 + rin;
    const int kA   = mat >> 1;
    const int rowB = (mat >> 1) * 8 + rin;
    const int kB   = mat & 1;

    float acc[4][4][4];
    #pragma unroll
    for (int i = 0; i < 4; i++)
        #pragma unroll
        for (int j = 0; j < 4; j++)
            #pragma unroll
            for (int t = 0; t < 4; t++) acc[i][j][t] = 0.f;

    GEMM_MAINLOOP(A, Bw, bm, bn, KD, NC)

    #pragma unroll
    for (int mi = 0; mi < 4; mi++) {
        const int row0 = bm + wm * 64 + mi * 16 + (lane >> 2);
        #pragma unroll
        for (int f = 0; f < 4; f++) {
            const int n0 = bn + wn * 32 + f * 8 + (lane & 3) * 2;
            float* cc = acc[mi][f];
            #pragma unroll
            for (int hrow = 0; hrow < 2; hrow++) {
                const int row = row0 + hrow * 8;
                const size_t idx = (size_t)row * KD + n0;
                *(uint32_t*)(Ch + idx) = pack_h2(cc[hrow*2+0], cc[hrow*2+1]);
            }
        }
    }
}

// ---------------------------------------------------------------------------
// fp16 tensor-core causal flash attention (FA2), reversed CTA order.
// ---------------------------------------------------------------------------
#define AT_Q  0u
#define AT_K  16384u
#define AT_V  32768u
#define ATT_SMEM 49152u

__global__ __launch_bounds__(128, 2) void attn_mma_kernel(
    const __half* __restrict__ Qg, const __half* __restrict__ Kg,
    const __half* __restrict__ Vg, __half* __restrict__ Og)
{
    extern __shared__ char smem[];
    const uint32_t sb = smem_u32(smem);
    const int tid  = threadIdx.x;
    const int wid  = tid >> 5;
    const int lane = tid & 31;
    const int bh   = blockIdx.y;
    const int b    = bh >> 4;
    const int h    = bh & 15;
    const int qt   = gridDim.x - 1 - blockIdx.x;
    const int q0   = qt * 64;

    const int mat  = lane >> 3;
    const int rin  = lane & 7;
    const int rowA = (mat & 1) * 8 + rin;
    const int kA   = mat >> 1;
    const int rowB = (mat >> 1) * 8 + rin;
    const int kB   = mat & 1;

    const size_t hoff = (size_t)h * KDH;

    #pragma unroll
    for (int i = 0; i < 8; i++) {
        int idx = tid + i * 128;
        int r = idx >> 4, cc = idx & 15;
        uint32_t so = SWZ256((uint32_t)(r * 256 + cc * 16));
        size_t go = ((size_t)(b * KL + q0 + r)) * KD + hoff + cc * 8;
        *(uint4*)(smem + AT_Q + so) = *(const uint4*)(Qg + go);
    }

    float ofrag[16][4];
    #pragma unroll
    for (int g = 0; g < 16; g++)
        #pragma unroll
        for (int t = 0; t < 4; t++) ofrag[g][t] = 0.f;

    float mrow0 = -1e30f, mrow1 = -1e30f;
    float lrow0 = 0.f, lrow1 = 0.f;

    const float scale = 0.08838834764831845f;

    for (int kt = 0; kt <= qt; kt++) {
        const int k0 = kt * 64;
        __syncthreads();
        #pragma unroll
        for (int i = 0; i < 8; i++) {
            int idx = tid + i * 128;
            int r = idx >> 4, cc = idx & 15;
            uint32_t so = SWZ256((uint32_t)(r * 256 + cc * 16));
            size_t go = ((size_t)(b * KL + k0 + r)) * KD + hoff + cc * 8;
            *(uint4*)(smem + AT_K + so) = *(const uint4*)(Kg + go);
        }
        #pragma unroll
        for (int i = 0; i < 16; i++) {
            int idx = tid + i * 128;
            int key = idx >> 5, d0 = (idx & 31) * 4;
            size_t go = ((size_t)(b * KL + k0 + key)) * KD + hoff + d0;
            uint2 v4 = *(const uint2*)(Vg + go);
            const __half* pv = (const __half*)&v4;
            #pragma unroll
            for (int d = 0; d < 4; d++) {
                uint32_t so = SWZ128((uint32_t)((d0 + d) * 128 + key * 2));
                *(__half*)(smem + AT_V + so) = pv[d];
            }
        }
        __syncthreads();

        float sf[8][4];
        #pragma unroll
        for (int f = 0; f < 8; f++)
            #pragma unroll
            for (int t = 0; t < 4; t++) sf[f][t] = 0.f;

        #pragma unroll
        for (int ks = 0; ks < 8; ks++) {
            uint32_t qf[4], kf[4][4];
            {
                uint32_t off = SWZ256((uint32_t)((wid * 16 + rowA) * 256 + ks * 32 + kA * 16));
                LDSM_X4(qf, sb + AT_Q + off);
            }
            #pragma unroll
            for (int nj = 0; nj < 4; nj++) {
                uint32_t off = SWZ256((uint32_t)((nj * 16 + rowB) * 256 + ks * 32 + kB * 16));
                LDSM_X4(kf[nj], sb + AT_K + off);
            }
            #pragma unroll
            for (int nj = 0; nj < 4; nj++)
                #pragma unroll
                for (int hf = 0; hf < 2; hf++)
                    mma_fp16(sf[nj*2+hf], qf, kf[nj][hf*2], kf[nj][hf*2+1]);
        }

        const int myrow = q0 + wid * 16 + (lane >> 2);
        #pragma unroll
        for (int f = 0; f < 8; f++) {
            #pragma unroll
            for (int t = 0; t < 4; t++) sf[f][t] *= scale;
            if (kt == qt) {
                int col = k0 + f * 8 + (lane & 3) * 2;
                if (col > myrow)     sf[f][0] = -1e30f;
                if (col + 1 > myrow) sf[f][1] = -1e30f;
                if (col > myrow + 8)     sf[f][2] = -1e30f;
                if (col + 1 > myrow + 8) sf[f][3] = -1e30f;
            }
        }

        float mx0 = -1e30f, mx1 = -1e30f;
        #pragma unroll
        for (int f = 0; f < 8; f++) {
            mx0 = fmaxf(mx0, fmaxf(sf[f][0], sf[f][1]));
            mx1 = fmaxf(mx1, fmaxf(sf[f][2], sf[f][3]));
        }
        #pragma unroll
        for (int d = 1; d <= 2; d <<= 1) {
            mx0 = fmaxf(mx0, __shfl_xor_sync(0xFFFFFFFFu, mx0, d));
            mx1 = fmaxf(mx1, __shfl_xor_sync(0xFFFFFFFFu, mx1, d));
        }
        float mnew0 = fmaxf(mrow0, mx0);
        float mnew1 = fmaxf(mrow1, mx1);
        float alpha0 = __expf(mrow0 - mnew0);
        float alpha1 = __expf(mrow1 - mnew1);
        mrow0 = mnew0; mrow1 = mnew1;

        float rs0 = 0.f, rs1 = 0.f;
        uint32_t pp[8][2];
        #pragma unroll
        for (int f = 0; f < 8; f++) {
            float p0 = __expf(sf[f][0] - mnew0);
            float p1 = __expf(sf[f][1] - mnew0);
            float p2 = __expf(sf[f][2] - mnew1);
            float p3 = __expf(sf[f][3] - mnew1);
            rs0 += p0 + p1; rs1 += p2 + p3;
            pp[f][0] = pack_h2(p0, p1);
            pp[f][1] = pack_h2(p2, p3);
        }
        #pragma unroll
        for (int d = 1; d <= 2; d <<= 1) {
            rs0 += __shfl_xor_sync(0xFFFFFFFFu, rs0, d);
            rs1 += __shfl_xor_sync(0xFFFFFFFFu, rs1, d);
        }
        lrow0 = lrow0 * alpha0 + rs0;
        lrow1 = lrow1 * alpha1 + rs1;

        #pragma unroll
        for (int g = 0; g < 16; g++) {
            ofrag[g][0] *= alpha0; ofrag[g][1] *= alpha0;
            ofrag[g][2] *= alpha1; ofrag[g][3] *= alpha1;
        }

        #pragma unroll
        for (int kk = 0; kk < 4; kk++) {
            uint32_t pa[4] = {pp[2*kk][0], pp[2*kk][1], pp[2*kk+1][0], pp[2*kk+1][1]};
            #pragma unroll
            for (int g = 0; g < 8; g++) {
                uint32_t vf[4];
                uint32_t off = SWZ128((uint32_t)((g * 16 + rowB) * 128 + kk * 32 + kB * 16));
                LDSM_X4(vf, sb + AT_V + off);
                mma_fp16(ofrag[g*2+0], pa, vf[0], vf[1]);
                mma_fp16(ofrag[g*2+1], pa, vf[2], vf[3]);
            }
        }
    }

    float inv0 = 1.0f / lrow0;
    float inv1 = 1.0f / lrow1;
    const int r0 = q0 + wid * 16 + (lane >> 2);
    #pragma unroll
    for (int g = 0; g < 16; g++) {
        int col = h * KDH + g * 8 + (lane & 3) * 2;
        size_t i0 = (size_t)(b * KL + r0) * KD + col;
        size_t i1 = (size_t)(b * KL + r0 + 8) * KD + col;
        *(uint32_t*)(Og + i0) = pack_h2(ofrag[g][0] * inv0, ofrag[g][1] * inv0);
        *(uint32_t*)(Og + i1) = pack_h2(ofrag[g][2] * inv1, ofrag[g][3] * inv1);
    }
}

// ---------------------------------------------------------------------------
// kernel_launch — dual-stream fork/join (graph-capturable event pattern)
// ---------------------------------------------------------------------------
extern "C" void kernel_launch(void* const* d_in, const int* in_sizes, int n_in,
                              void* d_out, int out_size)
{
    const float* x    = (const float*)d_in[0];
    const float* ln1  = (const float*)d_in[2];
    const float* wq   = (const float*)d_in[3];
    const float* wk   = (const float*)d_in[4];
    const float* wv   = (const float*)d_in[5];
    const float* wo   = (const float*)d_in[6];
    const float* ln2  = (const float*)d_in[7];
    const float* wup  = (const float*)d_in[8];
    const float* wdn  = (const float*)d_in[9];
    float* out = (float*)d_out;

    __half *wqh,*wkh,*wvh,*woh,*wuh,*wdh,*hh,*qq,*kk,*vv,*oo,*uu;
    cudaGetSymbolAddress((void**)&wqh, g_wq);
    cudaGetSymbolAddress((void**)&wkh, g_wk);
    cudaGetSymbolAddress((void**)&wvh, g_wv);
    cudaGetSymbolAddress((void**)&woh, g_wo);
    cudaGetSymbolAddress((void**)&wuh, g_wu);
    cudaGetSymbolAddress((void**)&wdh, g_wd);
    cudaGetSymbolAddress((void**)&hh, g_hh);
    cudaGetSymbolAddress((void**)&qq, g_qq);
    cudaGetSymbolAddress((void**)&kk, g_kk);
    cudaGetSymbolAddress((void**)&vv, g_vv);
    cudaGetSymbolAddress((void**)&oo, g_oo);
    cudaGetSymbolAddress((void**)&uu, g_uu);

    cudaFuncSetAttribute(gemm_mma_kernel<0>, cudaFuncAttributeMaxDynamicSharedMemorySize, GEMM_SMEM);
    cudaFuncSetAttribute(gemm_mma_kernel<1>, cudaFuncAttributeMaxDynamicSharedMemorySize, GEMM_SMEM);
    cudaFuncSetAttribute(gemm_mma_kernel<2>, cudaFuncAttributeMaxDynamicSharedMemorySize, GEMM_SMEM);
    cudaFuncSetAttribute(gemm_mma_kernel<3>, cudaFuncAttributeMaxDynamicSharedMemorySize, GEMM_SMEM);
    cudaFuncSetAttribute(gemm_qkv_kernel, cudaFuncAttributeMaxDynamicSharedMemorySize, GEMM_SMEM);
    cudaFuncSetAttribute(attn_mma_kernel, cudaFuncAttributeMaxDynamicSharedMemorySize, ATT_SMEM);

    dim3 blk(256);
    dim3 gqkv3(3 * (KD / TN), KM / TM);   // 48 x 32
    dim3 gd(KD / TN, KM / TM);            // 16 x 32
    dim3 gup(KDFF / TN, KM / TM);         // 64 x 32

    const int n4  = KD * KD / 4;
    const int g4  = n4 / 1024;
    const int n4f = KDFF * KD / 4;
    const int g4f = n4f / 1024;

    QKVPtrs p;
    p.b[0] = wqh; p.b[1] = wkh; p.b[2] = wvh;
    p.c[0] = qq;  p.c[1] = kk;  p.c[2] = vv;

    // second stream + fork/join events (host objects only; created per call,
    // intentionally not destroyed so captured graph nodes stay valid)
    cudaStream_t s2;
    cudaStreamCreateWithFlags(&s2, cudaStreamNonBlocking);
    cudaEvent_t eF1, eJ1, eF2, eJ2;
    cudaEventCreateWithFlags(&eF1, cudaEventDisableTiming);
    cudaEventCreateWithFlags(&eJ1, cudaEventDisableTiming);
    cudaEventCreateWithFlags(&eF2, cudaEventDisableTiming);
    cudaEventCreateWithFlags(&eJ2, cudaEventDisableTiming);

    // ---- fork 1: rmsnorm on main, qkv weight cvts on s2 ----
    cudaEventRecord(eF1, 0);
    cudaStreamWaitEvent(s2, eF1, 0);

    rmsnorm_kernel<<<KM, blk>>>(x, ln1, hh);
    cvt_kernel<<<g4, blk, 0, s2>>>(wq, wqh, n4);
    cvt_kernel<<<g4, blk, 0, s2>>>(wk, wkh, n4);
    cvt_kernel<<<g4, blk, 0, s2>>>(wv, wvh, n4);

    cudaEventRecord(eJ1, s2);
    cudaStreamWaitEvent(0, eJ1, 0);

    // ---- fork 2: qkv GEMM + attention on main, remaining cvts on s2 ----
    cudaEventRecord(eF2, 0);
    cudaStreamWaitEvent(s2, eF2, 0);

    gemm_qkv_kernel<<<gqkv3, blk, GEMM_SMEM>>>(hh, p);
    dim3 gattn(KL / 64, KB * KH);
    attn_mma_kernel<<<gattn, dim3(128), ATT_SMEM>>>(qq, kk, vv, oo);

    cvt_kernel<<<g4, blk, 0, s2>>>(wo, woh, n4);
    cvt_kernel<<<g4f, blk, 0, s2>>>(wup, wuh, n4f);
    cvt_kernel<<<g4f, blk, 0, s2>>>(wdn, wdh, n4f);

    cudaEventRecord(eJ2, s2);
    cudaStreamWaitEvent(0, eJ2, 0);

    // ---- tail on main stream ----
    // out = x + o @ wo^T
    gemm_mma_kernel<2><<<gd, blk, GEMM_SMEM>>>(oo, woh, out, x, nullptr, KD, KD);

    // h = rmsnorm(out, ln2)
    rmsnorm_kernel<<<KM, blk>>>(out, ln2, hh);

    // u = gelu(h @ wup^T)
    gemm_mma_kernel<1><<<gup, blk, GEMM_SMEM>>>(hh, wuh, nullptr, nullptr, uu, KDFF, KD);

    // out = out + u @ wdn^T
    gemm_mma_kernel<2><<<gd, blk, GEMM_SMEM>>>(uu, wdh, out, out, nullptr, KD, KDFF);
}

// round 12
// speedup vs baseline: 2.6755x; 1.0253x over previous
#include <cuda_runtime.h>
#include <cuda_fp16.h>
#include <math.h>
#include <stdint.h>

// ---------------------------------------------------------------------------
// TransformerBlock  B=2, L=2048, D=2048, H=16, DH=128, DFF=8192
// Round 11: warp tile 64x32 -> 64x64 (4 warps / 128 threads per 128x128 CTA,
// occ 2). Halves LDSM traffic per MMA; SMEM port no longer co-binding.
// ---------------------------------------------------------------------------

#define KB   2
#define KL   2048
#define KD   2048
#define KH   16
#define KDH  128
#define KDFF 8192
#define KM   (KB * KL)   // 4096 rows

// ----------------------------- PTX helpers --------------------------------
__device__ __forceinline__ uint32_t smem_u32(const void* p) {
    uint32_t a;
    asm("{ .reg .u64 t; cvta.to.shared.u64 t, %1; cvt.u32.u64 %0, t; }"
        : "=r"(a) : "l"(p));
    return a;
}

#define SWZ128(off) ((off) ^ (((off) >> 3) & 0x70))   // 128B rows
#define SWZ256(off) ((off) ^ (((off) >> 4) & 0x70))   // 256B rows

#define CP_ASYNC16(smem, gptr) \
    asm volatile("cp.async.cg.shared.global [%0], [%1], 16;" \
        :: "r"((uint32_t)(smem)), "l"(gptr) : "memory")
#define CP_COMMIT() asm volatile("cp.async.commit_group;" ::: "memory")
#define CP_WAIT2()  asm volatile("cp.async.wait_group 2;" ::: "memory")

#define LDSM_X4(r, addr) \
    asm volatile("ldmatrix.sync.aligned.m8n8.x4.shared.b16 {%0,%1,%2,%3}, [%4];" \
        : "=r"((r)[0]), "=r"((r)[1]), "=r"((r)[2]), "=r"((r)[3]) \
        : "r"((uint32_t)(addr)))

__device__ __forceinline__ void mma_fp16(float* c, const uint32_t* a,
                                         uint32_t b0, uint32_t b1) {
    asm volatile(
        "mma.sync.aligned.m16n8k16.row.col.f32.f16.f16.f32 "
        "{%0,%1,%2,%3}, {%4,%5,%6,%7}, {%8,%9}, {%0,%1,%2,%3};"
        : "+f"(c[0]), "+f"(c[1]), "+f"(c[2]), "+f"(c[3])
        : "r"(a[0]), "r"(a[1]), "r"(a[2]), "r"(a[3]), "r"(b0), "r"(b1));
}

__device__ __forceinline__ uint32_t pack_h2(float a, float b) {
    __half2 t = __floats2half2_rn(a, b);
    return *(uint32_t*)&t;
}

// ------------------------------- scratch ----------------------------------
__device__ __half g_wq[(size_t)KD * KD];
__device__ __half g_wk[(size_t)KD * KD];
__device__ __half g_wv[(size_t)KD * KD];
__device__ __half g_wo[(size_t)KD * KD];
__device__ __half g_wu[(size_t)KDFF * KD];
__device__ __half g_wd[(size_t)KD * KDFF];
__device__ __half g_hh[(size_t)KM * KD];
__device__ __half g_qq[(size_t)KM * KD];
__device__ __half g_kk[(size_t)KM * KD];
__device__ __half g_vv[(size_t)KM * KD];
__device__ __half g_oo[(size_t)KM * KD];
__device__ __half g_uu[(size_t)KM * KDFF];

// ---------------------------------------------------------------------------
// fp32 -> fp16 convert, 4 float4 per thread
// ---------------------------------------------------------------------------
__global__ __launch_bounds__(256) void cvt_kernel(
    const float* __restrict__ src, __half* __restrict__ dst, int n4)
{
    int base = blockIdx.x * 1024 + threadIdx.x;
    #pragma unroll
    for (int j = 0; j < 4; j++) {
        int i = base + j * 256;
        if (i >= n4) return;
        float4 v = ((const float4*)src)[i];
        __half h[4] = {__float2half_rn(v.x), __float2half_rn(v.y),
                       __float2half_rn(v.z), __float2half_rn(v.w)};
        ((uint2*)dst)[i] = *(uint2*)h;
    }
}

// ---------------------------------------------------------------------------
// RMSNorm -> fp16
// ---------------------------------------------------------------------------
__global__ __launch_bounds__(256) void rmsnorm_kernel(
    const float* __restrict__ x, const float* __restrict__ w,
    __half* __restrict__ y)
{
    int row = blockIdx.x;
    const float* xr = x + (size_t)row * KD;
    float s = 0.f;
    #pragma unroll
    for (int i = threadIdx.x; i < KD; i += 256) { float v = xr[i]; s += v * v; }
    __shared__ float red[256];
    red[threadIdx.x] = s;
    __syncthreads();
    #pragma unroll
    for (int st = 128; st > 0; st >>= 1) {
        if (threadIdx.x < st) red[threadIdx.x] += red[threadIdx.x + st];
        __syncthreads();
    }
    float inv = rsqrtf(red[0] * (1.0f / KD) + 1e-8f);
    #pragma unroll
    for (int i = threadIdx.x; i < KD; i += 256)
        y[(size_t)row * KD + i] = __float2half_rn(xr[i] * inv * w[i]);
}

// ---------------------------------------------------------------------------
// fp16 GEMM: C[M,N] = A[M,K] @ Bw[N,K]^T
// 128x128 CTA tile, 128 threads (4 warps, 2x2 of 64x64 warp tiles),
// K-chunk 64, 3-stage cp.async (96KB), 2 CTAs/SM.
// ---------------------------------------------------------------------------
#define TM 128
#define TN 128
#define TKC 64
#define ABUF 16384u
#define BBUF 16384u
#define STAGE (ABUF + BBUF)          // 32768
#define GEMM_SMEM (3u * STAGE)       // 98304
#define GTHREADS 128

#define GEMM_MAINLOOP(AP, BP, bmE, bnE, KE, NCE)                                \
    auto load_stage = [&](int c, int s) {                                       \
        const int kc = c * TKC;                                                 \
        const uint32_t base = sb + (uint32_t)s * STAGE;                         \
        _Pragma("unroll")                                                       \
        for (int i = 0; i < 8; i++) {                                           \
            int chunk = i * 128 + tid;      /* 0..1023 */                       \
            int r = chunk >> 3, cc = chunk & 7;                                 \
            uint32_t so = SWZ128((uint32_t)(r * 128 + cc * 16));                \
            CP_ASYNC16(base + so, (AP) + (size_t)((bmE) + r) * (KE) + kc + cc * 8); \
        }                                                                       \
        _Pragma("unroll")                                                       \
        for (int i = 0; i < 8; i++) {                                           \
            int chunk = i * 128 + tid;                                          \
            int r = chunk >> 3, cc = chunk & 7;                                 \
            uint32_t so = SWZ128((uint32_t)(r * 128 + cc * 16));                \
            CP_ASYNC16(base + ABUF + so, (BP) + (size_t)((bnE) + r) * (KE) + kc + cc * 8); \
        }                                                                       \
        CP_COMMIT();                                                            \
    };                                                                          \
    load_stage(0, 0);                                                           \
    load_stage(1, 1);                                                           \
    _Pragma("unroll 1")                                                         \
    for (int c = 0; c < (NCE); c++) {                                           \
        const int s = c % 3;                                                    \
        __syncthreads();                                                        \
        if (c + 2 < (NCE)) load_stage(c + 2, (c + 2) % 3);                      \
        else               CP_COMMIT();                                         \
        CP_WAIT2();                                                             \
        __syncthreads();                                                        \
        const uint32_t sA = sb + (uint32_t)s * STAGE;                           \
        const uint32_t sB = sA + ABUF;                                          \
        _Pragma("unroll")                                                       \
        for (int h = 0; h < 4; h++) {                                           \
            uint32_t af[4][4], bf[4][4];                                        \
            _Pragma("unroll")                                                   \
            for (int mi = 0; mi < 4; mi++) {                                    \
                int m = wm * 64 + mi * 16 + rowA;                               \
                uint32_t off = SWZ128((uint32_t)(m * 128 + (h * 2 + kA) * 16)); \
                LDSM_X4(af[mi], sA + off);                                      \
            }                                                                   \
            _Pragma("unroll")                                                   \
            for (int nj = 0; nj < 4; nj++) {                                    \
                int n = wn * 64 + nj * 16 + rowB;                               \
                uint32_t off = SWZ128((uint32_t)(n * 128 + (h * 2 + kB) * 16)); \
                LDSM_X4(bf[nj], sB + off);                                      \
            }                                                                   \
            _Pragma("unroll")                                                   \
            for (int mi = 0; mi < 4; mi++)                                      \
                _Pragma("unroll")                                               \
                for (int nj = 0; nj < 4; nj++)                                  \
                    _Pragma("unroll")                                           \
                    for (int hf = 0; hf < 2; hf++)                              \
                        mma_fp16(acc[mi][nj*2+hf], af[mi],                      \
                                 bf[nj][hf*2], bf[nj][hf*2+1]);                 \
        }                                                                       \
    }

template<int EPI>
__global__ __launch_bounds__(GTHREADS, 2) void gemm_mma_kernel(
    const __half* __restrict__ A, const __half* __restrict__ Bw,
    float* __restrict__ C, const float* __restrict__ R,
    __half* __restrict__ Ch, int N, int K)
{
    extern __shared__ char smem[];
    const uint32_t sb = smem_u32(smem);
    const int tid  = threadIdx.x;
    const int wid  = tid >> 5;
    const int lane = tid & 31;
    const int wm   = wid & 1;        // 0..1
    const int wn   = wid >> 1;       // 0..1
    const int bm   = blockIdx.y * TM;
    const int bn   = blockIdx.x * TN;
    const int NC   = K / TKC;

    const int mat  = lane >> 3;
    const int rin  = lane & 7;
    const int rowA = (mat & 1) * 8 + rin;
    const int kA   = mat >> 1;
    const int rowB = (mat >> 1) * 8 + rin;
    const int kB   = mat & 1;

    float acc[4][8][4];
    #pragma unroll
    for (int i = 0; i < 4; i++)
        #pragma unroll
        for (int j = 0; j < 8; j++)
            #pragma unroll
            for (int t = 0; t < 4; t++) acc[i][j][t] = 0.f;

    GEMM_MAINLOOP(A, Bw, bm, bn, K, NC)

    #pragma unroll
    for (int mi = 0; mi < 4; mi++) {
        const int row0 = bm + wm * 64 + mi * 16 + (lane >> 2);
        #pragma unroll
        for (int f = 0; f < 8; f++) {
            const int n0 = bn + wn * 64 + f * 8 + (lane & 3) * 2;
            float* cc = acc[mi][f];
            #pragma unroll
            for (int hrow = 0; hrow < 2; hrow++) {
                const int row = row0 + hrow * 8;
                float v0 = cc[hrow * 2 + 0];
                float v1 = cc[hrow * 2 + 1];
                const size_t idx = (size_t)row * N + n0;
                if (EPI == 1 || EPI == 3) {
                    if (EPI == 1) {
                        v0 = 0.5f * v0 * (1.0f + erff(v0 * 0.70710678118654752f));
                        v1 = 0.5f * v1 * (1.0f + erff(v1 * 0.70710678118654752f));
                    }
                    *(uint32_t*)(Ch + idx) = pack_h2(v0, v1);
                } else {
                    if (EPI == 2) {
                        float2 rv = *(const float2*)(R + idx);
                        v0 += rv.x; v1 += rv.y;
                    }
                    float2 ov; ov.x = v0; ov.y = v1;
                    *(float2*)(C + idx) = ov;
                }
            }
        }
    }
}

// ---------------------------------------------------------------------------
// Fused QKV GEMM
// ---------------------------------------------------------------------------
struct QKVPtrs {
    const __half* b[3];
    __half* c[3];
};

__global__ __launch_bounds__(GTHREADS, 2) void gemm_qkv_kernel(
    const __half* __restrict__ A, QKVPtrs p)
{
    extern __shared__ char smem[];
    const uint32_t sb = smem_u32(smem);
    const int tid  = threadIdx.x;
    const int wid  = tid >> 5;
    const int lane = tid & 31;
    const int wm   = wid & 1;
    const int wn   = wid >> 1;
    const int which = blockIdx.x >> 4;
    const int bm   = blockIdx.y * TM;
    const int bn   = (blockIdx.x & 15) * TN;
    const int NC   = KD / TKC;

    const __half* __restrict__ Bw = p.b[which];
    __half* __restrict__ Ch = p.c[which];

    const int mat  = lane >> 3;
    const int rin  = lane & 7;
    const int rowA = (mat & 1) * 8 + rin;
    const int kA   = mat >> 1;
    const int rowB = (mat >> 1) * 8 + rin;
    const int kB   = mat & 1;

    float acc[4][8][4];
    #pragma unroll
    for (int i = 0; i < 4; i++)
        #pragma unroll
        for (int j = 0; j < 8; j++)
            #pragma unroll
            for (int t = 0; t < 4; t++) acc[i][j][t] = 0.f;

    GEMM_MAINLOOP(A, Bw, bm, bn, KD, NC)

    #pragma unroll
    for (int mi = 0; mi < 4; mi++) {
        const int row0 = bm + wm * 64 + mi * 16 + (lane >> 2);
        #pragma unroll
        for (int f = 0; f < 8; f++) {
            const int n0 = bn + wn * 64 + f * 8 + (lane & 3) * 2;
            float* cc = acc[mi][f];
            #pragma unroll
            for (int hrow = 0; hrow < 2; hrow++) {
                const int row = row0 + hrow * 8;
                const size_t idx = (size_t)row * KD + n0;
                *(uint32_t*)(Ch + idx) = pack_h2(cc[hrow*2+0], cc[hrow*2+1]);
            }
        }
    }
}

// ---------------------------------------------------------------------------
// fp16 tensor-core causal flash attention (FA2), reversed CTA order.
// ---------------------------------------------------------------------------
#define AT_Q  0u
#define AT_K  16384u
#define AT_V  32768u
#define ATT_SMEM 49152u

__global__ __launch_bounds__(128, 2) void attn_mma_kernel(
    const __half* __restrict__ Qg, const __half* __restrict__ Kg,
    const __half* __restrict__ Vg, __half* __restrict__ Og)
{
    extern __shared__ char smem[];
    const uint32_t sb = smem_u32(smem);
    const int tid  = threadIdx.x;
    const int wid  = tid >> 5;
    const int lane = tid & 31;
    const int bh   = blockIdx.y;
    const int b    = bh >> 4;
    const int h    = bh & 15;
    const int qt   = gridDim.x - 1 - blockIdx.x;
    const int q0   = qt * 64;

    const int mat  = lane >> 3;
    const int rin  = lane & 7;
    const int rowA = (mat & 1) * 8 + rin;
    const int kA   = mat >> 1;
    const int rowB = (mat >> 1) * 8 + rin;
    const int kB   = mat & 1;

    const size_t hoff = (size_t)h * KDH;

    #pragma unroll
    for (int i = 0; i < 8; i++) {
        int idx = tid + i * 128;
        int r = idx >> 4, cc = idx & 15;
        uint32_t so = SWZ256((uint32_t)(r * 256 + cc * 16));
        size_t go = ((size_t)(b * KL + q0 + r)) * KD + hoff + cc * 8;
        *(uint4*)(smem + AT_Q + so) = *(const uint4*)(Qg + go);
    }

    float ofrag[16][4];
    #pragma unroll
    for (int g = 0; g < 16; g++)
        #pragma unroll
        for (int t = 0; t < 4; t++) ofrag[g][t] = 0.f;

    float mrow0 = -1e30f, mrow1 = -1e30f;
    float lrow0 = 0.f, lrow1 = 0.f;

    const float scale = 0.08838834764831845f;

    for (int kt = 0; kt <= qt; kt++) {
        const int k0 = kt * 64;
        __syncthreads();
        #pragma unroll
        for (int i = 0; i < 8; i++) {
            int idx = tid + i * 128;
            int r = idx >> 4, cc = idx & 15;
            uint32_t so = SWZ256((uint32_t)(r * 256 + cc * 16));
            size_t go = ((size_t)(b * KL + k0 + r)) * KD + hoff + cc * 8;
            *(uint4*)(smem + AT_K + so) = *(const uint4*)(Kg + go);
        }
        #pragma unroll
        for (int i = 0; i < 16; i++) {
            int idx = tid + i * 128;
            int key = idx >> 5, d0 = (idx & 31) * 4;
            size_t go = ((size_t)(b * KL + k0 + key)) * KD + hoff + d0;
            uint2 v4 = *(const uint2*)(Vg + go);
            const __half* pv = (const __half*)&v4;
            #pragma unroll
            for (int d = 0; d < 4; d++) {
                uint32_t so = SWZ128((uint32_t)((d0 + d) * 128 + key * 2));
                *(__half*)(smem + AT_V + so) = pv[d];
            }
        }
        __syncthreads();

        float sf[8][4];
        #pragma unroll
        for (int f = 0; f < 8; f++)
            #pragma unroll
            for (int t = 0; t < 4; t++) sf[f][t] = 0.f;

        #pragma unroll
        for (int ks = 0; ks < 8; ks++) {
            uint32_t qf[4], kf[4][4];
            {
                uint32_t off = SWZ256((uint32_t)((wid * 16 + rowA) * 256 + ks * 32 + kA * 16));
                LDSM_X4(qf, sb + AT_Q + off);
            }
            #pragma unroll
            for (int nj = 0; nj < 4; nj++) {
                uint32_t off = SWZ256((uint32_t)((nj * 16 + rowB) * 256 + ks * 32 + kB * 16));
                LDSM_X4(kf[nj], sb + AT_K + off);
            }
            #pragma unroll
            for (int nj = 0; nj < 4; nj++)
                #pragma unroll
                for (int hf = 0; hf < 2; hf++)
                    mma_fp16(sf[nj*2+hf], qf, kf[nj][hf*2], kf[nj][hf*2+1]);
        }

        const int myrow = q0 + wid * 16 + (lane >> 2);
        #pragma unroll
        for (int f = 0; f < 8; f++) {
            #pragma unroll
            for (int t = 0; t < 4; t++) sf[f][t] *= scale;
            if (kt == qt) {
                int col = k0 + f * 8 + (lane & 3) * 2;
                if (col > myrow)     sf[f][0] = -1e30f;
                if (col + 1 > myrow) sf[f][1] = -1e30f;
                if (col > myrow + 8)     sf[f][2] = -1e30f;
                if (col + 1 > myrow + 8) sf[f][3] = -1e30f;
            }
        }

        float mx0 = -1e30f, mx1 = -1e30f;
        #pragma unroll
        for (int f = 0; f < 8; f++) {
            mx0 = fmaxf(mx0, fmaxf(sf[f][0], sf[f][1]));
            mx1 = fmaxf(mx1, fmaxf(sf[f][2], sf[f][3]));
        }
        #pragma unroll
        for (int d = 1; d <= 2; d <<= 1) {
            mx0 = fmaxf(mx0, __shfl_xor_sync(0xFFFFFFFFu, mx0, d));
            mx1 = fmaxf(mx1, __shfl_xor_sync(0xFFFFFFFFu, mx1, d));
        }
        float mnew0 = fmaxf(mrow0, mx0);
        float mnew1 = fmaxf(mrow1, mx1);
        float alpha0 = __expf(mrow0 - mnew0);
        float alpha1 = __expf(mrow1 - mnew1);
        mrow0 = mnew0; mrow1 = mnew1;

        float rs0 = 0.f, rs1 = 0.f;
        uint32_t pp[8][2];
        #pragma unroll
        for (int f = 0; f < 8; f++) {
            float p0 = __expf(sf[f][0] - mnew0);
            float p1 = __expf(sf[f][1] - mnew0);
            float p2 = __expf(sf[f][2] - mnew1);
            float p3 = __expf(sf[f][3] - mnew1);
            rs0 += p0 + p1; rs1 += p2 + p3;
            pp[f][0] = pack_h2(p0, p1);
            pp[f][1] = pack_h2(p2, p3);
        }
        #pragma unroll
        for (int d = 1; d <= 2; d <<= 1) {
            rs0 += __shfl_xor_sync(0xFFFFFFFFu, rs0, d);
            rs1 += __shfl_xor_sync(0xFFFFFFFFu, rs1, d);
        }
        lrow0 = lrow0 * alpha0 + rs0;
        lrow1 = lrow1 * alpha1 + rs1;

        #pragma unroll
        for (int g = 0; g < 16; g++) {
            ofrag[g][0] *= alpha0; ofrag[g][1] *= alpha0;
            ofrag[g][2] *= alpha1; ofrag[g][3] *= alpha1;
        }

        #pragma unroll
        for (int kk = 0; kk < 4; kk++) {
            uint32_t pa[4] = {pp[2*kk][0], pp[2*kk][1], pp[2*kk+1][0], pp[2*kk+1][1]};
            #pragma unroll
            for (int g = 0; g < 8; g++) {
                uint32_t vf[4];
                uint32_t off = SWZ128((uint32_t)((g * 16 + rowB) * 128 + kk * 32 + kB * 16));
                LDSM_X4(vf, sb + AT_V + off);
                mma_fp16(ofrag[g*2+0], pa, vf[0], vf[1]);
                mma_fp16(ofrag[g*2+1], pa, vf[2], vf[3]);
            }
        }
    }

    float inv0 = 1.0f / lrow0;
    float inv1 = 1.0f / lrow1;
    const int r0 = q0 + wid * 16 + (lane >> 2);
    #pragma unroll
    for (int g = 0; g < 16; g++) {
        int col = h * KDH + g * 8 + (lane & 3) * 2;
        size_t i0 = (size_t)(b * KL + r0) * KD + col;
        size_t i1 = (size_t)(b * KL + r0 + 8) * KD + col;
        *(uint32_t*)(Og + i0) = pack_h2(ofrag[g][0] * inv0, ofrag[g][1] * inv0);
        *(uint32_t*)(Og + i1) = pack_h2(ofrag[g][2] * inv1, ofrag[g][3] * inv1);
    }
}

// ---------------------------------------------------------------------------
// kernel_launch — dual-stream fork/join
// ---------------------------------------------------------------------------
extern "C" void kernel_launch(void* const* d_in, const int* in_sizes, int n_in,
                              void* d_out, int out_size)
{
    const float* x    = (const float*)d_in[0];
    const float* ln1  = (const float*)d_in[2];
    const float* wq   = (const float*)d_in[3];
    const float* wk   = (const float*)d_in[4];
    const float* wv   = (const float*)d_in[5];
    const float* wo   = (const float*)d_in[6];
    const float* ln2  = (const float*)d_in[7];
    const float* wup  = (const float*)d_in[8];
    const float* wdn  = (const float*)d_in[9];
    float* out = (float*)d_out;

    __half *wqh,*wkh,*wvh,*woh,*wuh,*wdh,*hh,*qq,*kk,*vv,*oo,*uu;
    cudaGetSymbolAddress((void**)&wqh, g_wq);
    cudaGetSymbolAddress((void**)&wkh, g_wk);
    cudaGetSymbolAddress((void**)&wvh, g_wv);
    cudaGetSymbolAddress((void**)&woh, g_wo);
    cudaGetSymbolAddress((void**)&wuh, g_wu);
    cudaGetSymbolAddress((void**)&wdh, g_wd);
    cudaGetSymbolAddress((void**)&hh, g_hh);
    cudaGetSymbolAddress((void**)&qq, g_qq);
    cudaGetSymbolAddress((void**)&kk, g_kk);
    cudaGetSymbolAddress((void**)&vv, g_vv);
    cudaGetSymbolAddress((void**)&oo, g_oo);
    cudaGetSymbolAddress((void**)&uu, g_uu);

    cudaFuncSetAttribute(gemm_mma_kernel<0>, cudaFuncAttributeMaxDynamicSharedMemorySize, GEMM_SMEM);
    cudaFuncSetAttribute(gemm_mma_kernel<1>, cudaFuncAttributeMaxDynamicSharedMemorySize, GEMM_SMEM);
    cudaFuncSetAttribute(gemm_mma_kernel<2>, cudaFuncAttributeMaxDynamicSharedMemorySize, GEMM_SMEM);
    cudaFuncSetAttribute(gemm_mma_kernel<3>, cudaFuncAttributeMaxDynamicSharedMemorySize, GEMM_SMEM);
    cudaFuncSetAttribute(gemm_qkv_kernel, cudaFuncAttributeMaxDynamicSharedMemorySize, GEMM_SMEM);
    cudaFuncSetAttribute(attn_mma_kernel, cudaFuncAttributeMaxDynamicSharedMemorySize, ATT_SMEM);

    dim3 blk(256);
    dim3 gblk(GTHREADS);
    dim3 gqkv3(3 * (KD / TN), KM / TM);   // 48 x 32
    dim3 gd(KD / TN, KM / TM);            // 16 x 32
    dim3 gup(KDFF / TN, KM / TM);         // 64 x 32

    const int n4  = KD * KD / 4;
    const int g4  = n4 / 1024;
    const int n4f = KDFF * KD / 4;
    const int g4f = n4f / 1024;

    QKVPtrs p;
    p.b[0] = wqh; p.b[1] = wkh; p.b[2] = wvh;
    p.c[0] = qq;  p.c[1] = kk;  p.c[2] = vv;

    cudaStream_t s2;
    cudaStreamCreateWithFlags(&s2, cudaStreamNonBlocking);
    cudaEvent_t eF1, eJ1, eF2, eJ2;
    cudaEventCreateWithFlags(&eF1, cudaEventDisableTiming);
    cudaEventCreateWithFlags(&eJ1, cudaEventDisableTiming);
    cudaEventCreateWithFlags(&eF2, cudaEventDisableTiming);
    cudaEventCreateWithFlags(&eJ2, cudaEventDisableTiming);

    // ---- fork 1: rmsnorm on main, qkv weight cvts on s2 ----
    cudaEventRecord(eF1, 0);
    cudaStreamWaitEvent(s2, eF1, 0);

    rmsnorm_kernel<<<KM, blk>>>(x, ln1, hh);
    cvt_kernel<<<g4, blk, 0, s2>>>(wq, wqh, n4);
    cvt_kernel<<<g4, blk, 0, s2>>>(wk, wkh, n4);
    cvt_kernel<<<g4, blk, 0, s2>>>(wv, wvh, n4);

    cudaEventRecord(eJ1, s2);
    cudaStreamWaitEvent(0, eJ1, 0);

    // ---- fork 2: qkv GEMM + attention on main, remaining cvts on s2 ----
    cudaEventRecord(eF2, 0);
    cudaStreamWaitEvent(s2, eF2, 0);

    gemm_qkv_kernel<<<gqkv3, gblk, GEMM_SMEM>>>(hh, p);
    dim3 gattn(KL / 64, KB * KH);
    attn_mma_kernel<<<gattn, dim3(128), ATT_SMEM>>>(qq, kk, vv, oo);

    cvt_kernel<<<g4, blk, 0, s2>>>(wo, woh, n4);
    cvt_kernel<<<g4f, blk, 0, s2>>>(wup, wuh, n4f);
    cvt_kernel<<<g4f, blk, 0, s2>>>(wdn, wdh, n4f);

    cudaEventRecord(eJ2, s2);
    cudaStreamWaitEvent(0, eJ2, 0);

    // ---- tail on main stream ----
    gemm_mma_kernel<2><<<gd, gblk, GEMM_SMEM>>>(oo, woh, out, x, nullptr, KD, KD);
    rmsnorm_kernel<<<KM, blk>>>(out, ln2, hh);
    gemm_mma_kernel<1><<<gup, gblk, GEMM_SMEM>>>(hh, wuh, nullptr, nullptr, uu, KDFF, KD);
    gemm_mma_kernel<2><<<gd, gblk, GEMM_SMEM>>>(uu, wdh, out, out, nullptr, KD, KDFF);
}

// round 13
// speedup vs baseline: 3.3578x; 1.2550x over previous
#include <cuda_runtime.h>
#include <cuda_fp16.h>
#include <math.h>
#include <stdint.h>

// ---------------------------------------------------------------------------
// TransformerBlock  B=2, L=2048, D=2048, H=16, DH=128, DFF=8192
// Round 12: attention — ldmatrix.trans for V (kills scalar transpose STS) and
// 2-stage cp.async K/V pipeline. GEMMs unchanged from R11.
// ---------------------------------------------------------------------------

#define KB   2
#define KL   2048
#define KD   2048
#define KH   16
#define KDH  128
#define KDFF 8192
#define KM   (KB * KL)   // 4096 rows

// ----------------------------- PTX helpers --------------------------------
__device__ __forceinline__ uint32_t smem_u32(const void* p) {
    uint32_t a;
    asm("{ .reg .u64 t; cvta.to.shared.u64 t, %1; cvt.u32.u64 %0, t; }"
        : "=r"(a) : "l"(p));
    return a;
}

#define SWZ128(off) ((off) ^ (((off) >> 3) & 0x70))   // 128B rows
#define SWZ256(off) ((off) ^ (((off) >> 4) & 0x70))   // 256B rows

#define CP_ASYNC16(smem, gptr) \
    asm volatile("cp.async.cg.shared.global [%0], [%1], 16;" \
        :: "r"((uint32_t)(smem)), "l"(gptr) : "memory")
#define CP_COMMIT() asm volatile("cp.async.commit_group;" ::: "memory")
#define CP_WAIT2()  asm volatile("cp.async.wait_group 2;" ::: "memory")
#define CP_WAIT1()  asm volatile("cp.async.wait_group 1;" ::: "memory")

#define LDSM_X4(r, addr) \
    asm volatile("ldmatrix.sync.aligned.m8n8.x4.shared.b16 {%0,%1,%2,%3}, [%4];" \
        : "=r"((r)[0]), "=r"((r)[1]), "=r"((r)[2]), "=r"((r)[3]) \
        : "r"((uint32_t)(addr)))

#define LDSM_X4_T(r, addr) \
    asm volatile("ldmatrix.sync.aligned.m8n8.x4.trans.shared.b16 {%0,%1,%2,%3}, [%4];" \
        : "=r"((r)[0]), "=r"((r)[1]), "=r"((r)[2]), "=r"((r)[3]) \
        : "r"((uint32_t)(addr)))

__device__ __forceinline__ void mma_fp16(float* c, const uint32_t* a,
                                         uint32_t b0, uint32_t b1) {
    asm volatile(
        "mma.sync.aligned.m16n8k16.row.col.f32.f16.f16.f32 "
        "{%0,%1,%2,%3}, {%4,%5,%6,%7}, {%8,%9}, {%0,%1,%2,%3};"
        : "+f"(c[0]), "+f"(c[1]), "+f"(c[2]), "+f"(c[3])
        : "r"(a[0]), "r"(a[1]), "r"(a[2]), "r"(a[3]), "r"(b0), "r"(b1));
}

__device__ __forceinline__ uint32_t pack_h2(float a, float b) {
    __half2 t = __floats2half2_rn(a, b);
    return *(uint32_t*)&t;
}

// ------------------------------- scratch ----------------------------------
__device__ __half g_wq[(size_t)KD * KD];
__device__ __half g_wk[(size_t)KD * KD];
__device__ __half g_wv[(size_t)KD * KD];
__device__ __half g_wo[(size_t)KD * KD];
__device__ __half g_wu[(size_t)KDFF * KD];
__device__ __half g_wd[(size_t)KD * KDFF];
__device__ __half g_hh[(size_t)KM * KD];
__device__ __half g_qq[(size_t)KM * KD];
__device__ __half g_kk[(size_t)KM * KD];
__device__ __half g_vv[(size_t)KM * KD];
__device__ __half g_oo[(size_t)KM * KD];
__device__ __half g_uu[(size_t)KM * KDFF];

// ---------------------------------------------------------------------------
// fp32 -> fp16 convert, 4 float4 per thread
// ---------------------------------------------------------------------------
__global__ __launch_bounds__(256) void cvt_kernel(
    const float* __restrict__ src, __half* __restrict__ dst, int n4)
{
    int base = blockIdx.x * 1024 + threadIdx.x;
    #pragma unroll
    for (int j = 0; j < 4; j++) {
        int i = base + j * 256;
        if (i >= n4) return;
        float4 v = ((const float4*)src)[i];
        __half h[4] = {__float2half_rn(v.x), __float2half_rn(v.y),
                       __float2half_rn(v.z), __float2half_rn(v.w)};
        ((uint2*)dst)[i] = *(uint2*)h;
    }
}

// ---------------------------------------------------------------------------
// RMSNorm -> fp16
// ---------------------------------------------------------------------------
__global__ __launch_bounds__(256) void rmsnorm_kernel(
    const float* __restrict__ x, const float* __restrict__ w,
    __half* __restrict__ y)
{
    int row = blockIdx.x;
    const float* xr = x + (size_t)row * KD;
    float s = 0.f;
    #pragma unroll
    for (int i = threadIdx.x; i < KD; i += 256) { float v = xr[i]; s += v * v; }
    __shared__ float red[256];
    red[threadIdx.x] = s;
    __syncthreads();
    #pragma unroll
    for (int st = 128; st > 0; st >>= 1) {
        if (threadIdx.x < st) red[threadIdx.x] += red[threadIdx.x + st];
        __syncthreads();
    }
    float inv = rsqrtf(red[0] * (1.0f / KD) + 1e-8f);
    #pragma unroll
    for (int i = threadIdx.x; i < KD; i += 256)
        y[(size_t)row * KD + i] = __float2half_rn(xr[i] * inv * w[i]);
}

// ---------------------------------------------------------------------------
// fp16 GEMM (unchanged from R11): 128x128 CTA, 4 warps (64x64 warp tiles),
// K-chunk 64, 3-stage cp.async, 2 CTAs/SM.
// ---------------------------------------------------------------------------
#define TM 128
#define TN 128
#define TKC 64
#define ABUF 16384u
#define BBUF 16384u
#define STAGE (ABUF + BBUF)          // 32768
#define GEMM_SMEM (3u * STAGE)       // 98304
#define GTHREADS 128

#define GEMM_MAINLOOP(AP, BP, bmE, bnE, KE, NCE)                                \
    auto load_stage = [&](int c, int s) {                                       \
        const int kc = c * TKC;                                                 \
        const uint32_t base = sb + (uint32_t)s * STAGE;                         \
        _Pragma("unroll")                                                       \
        for (int i = 0; i < 8; i++) {                                           \
            int chunk = i * 128 + tid;      /* 0..1023 */                       \
            int r = chunk >> 3, cc = chunk & 7;                                 \
            uint32_t so = SWZ128((uint32_t)(r * 128 + cc * 16));                \
            CP_ASYNC16(base + so, (AP) + (size_t)((bmE) + r) * (KE) + kc + cc * 8); \
        }                                                                       \
        _Pragma("unroll")                                                       \
        for (int i = 0; i < 8; i++) {                                           \
            int chunk = i * 128 + tid;                                          \
            int r = chunk >> 3, cc = chunk & 7;                                 \
            uint32_t so = SWZ128((uint32_t)(r * 128 + cc * 16));                \
            CP_ASYNC16(base + ABUF + so, (BP) + (size_t)((bnE) + r) * (KE) + kc + cc * 8); \
        }                                                                       \
        CP_COMMIT();                                                            \
    };                                                                          \
    load_stage(0, 0);                                                           \
    load_stage(1, 1);                                                           \
    _Pragma("unroll 1")                                                         \
    for (int c = 0; c < (NCE); c++) {                                           \
        const int s = c % 3;                                                    \
        __syncthreads();                                                        \
        if (c + 2 < (NCE)) load_stage(c + 2, (c + 2) % 3);                      \
        else               CP_COMMIT();                                         \
        CP_WAIT2();                                                             \
        __syncthreads();                                                        \
        const uint32_t sA = sb + (uint32_t)s * STAGE;                           \
        const uint32_t sB = sA + ABUF;                                          \
        _Pragma("unroll")                                                       \
        for (int h = 0; h < 4; h++) {                                           \
            uint32_t af[4][4], bf[4][4];                                        \
            _Pragma("unroll")                                                   \
            for (int mi = 0; mi < 4; mi++) {                                    \
                int m = wm * 64 + mi * 16 + rowA;                               \
                uint32_t off = SWZ128((uint32_t)(m * 128 + (h * 2 + kA) * 16)); \
                LDSM_X4(af[mi], sA + off);                                      \
            }                                                                   \
            _Pragma("unroll")                                                   \
            for (int nj = 0; nj < 4; nj++) {                                    \
                int n = wn * 64 + nj * 16 + rowB;                               \
                uint32_t off = SWZ128((uint32_t)(n * 128 + (h * 2 + kB) * 16)); \
                LDSM_X4(bf[nj], sB + off);                                      \
            }                                                                   \
            _Pragma("unroll")                                                   \
            for (int mi = 0; mi < 4; mi++)                                      \
                _Pragma("unroll")                                               \
                for (int nj = 0; nj < 4; nj++)                                  \
                    _Pragma("unroll")                                           \
                    for (int hf = 0; hf < 2; hf++)                              \
                        mma_fp16(acc[mi][nj*2+hf], af[mi],                      \
                                 bf[nj][hf*2], bf[nj][hf*2+1]);                 \
        }                                                                       \
    }

template<int EPI>
__global__ __launch_bounds__(GTHREADS, 2) void gemm_mma_kernel(
    const __half* __restrict__ A, const __half* __restrict__ Bw,
    float* __restrict__ C, const float* __restrict__ R,
    __half* __restrict__ Ch, int N, int K)
{
    extern __shared__ char smem[];
    const uint32_t sb = smem_u32(smem);
    const int tid  = threadIdx.x;
    const int wid  = tid >> 5;
    const int lane = tid & 31;
    const int wm   = wid & 1;
    const int wn   = wid >> 1;
    const int bm   = blockIdx.y * TM;
    const int bn   = blockIdx.x * TN;
    const int NC   = K / TKC;

    const int mat  = lane >> 3;
    const int rin  = lane & 7;
    const int rowA = (mat & 1) * 8 + rin;
    const int kA   = mat >> 1;
    const int rowB = (mat >> 1) * 8 + rin;
    const int kB   = mat & 1;

    float acc[4][8][4];
    #pragma unroll
    for (int i = 0; i < 4; i++)
        #pragma unroll
        for (int j = 0; j < 8; j++)
            #pragma unroll
            for (int t = 0; t < 4; t++) acc[i][j][t] = 0.f;

    GEMM_MAINLOOP(A, Bw, bm, bn, K, NC)

    #pragma unroll
    for (int mi = 0; mi < 4; mi++) {
        const int row0 = bm + wm * 64 + mi * 16 + (lane >> 2);
        #pragma unroll
        for (int f = 0; f < 8; f++) {
            const int n0 = bn + wn * 64 + f * 8 + (lane & 3) * 2;
            float* cc = acc[mi][f];
            #pragma unroll
            for (int hrow = 0; hrow < 2; hrow++) {
                const int row = row0 + hrow * 8;
                float v0 = cc[hrow * 2 + 0];
                float v1 = cc[hrow * 2 + 1];
                const size_t idx = (size_t)row * N + n0;
                if (EPI == 1 || EPI == 3) {
                    if (EPI == 1) {
                        v0 = 0.5f * v0 * (1.0f + erff(v0 * 0.70710678118654752f));
                        v1 = 0.5f * v1 * (1.0f + erff(v1 * 0.70710678118654752f));
                    }
                    *(uint32_t*)(Ch + idx) = pack_h2(v0, v1);
                } else {
                    if (EPI == 2) {
                        float2 rv = *(const float2*)(R + idx);
                        v0 += rv.x; v1 += rv.y;
                    }
                    float2 ov; ov.x = v0; ov.y = v1;
                    *(float2*)(C + idx) = ov;
                }
            }
        }
    }
}

// ---------------------------------------------------------------------------
// Fused QKV GEMM
// ---------------------------------------------------------------------------
struct QKVPtrs {
    const __half* b[3];
    __half* c[3];
};

__global__ __launch_bounds__(GTHREADS, 2) void gemm_qkv_kernel(
    const __half* __restrict__ A, QKVPtrs p)
{
    extern __shared__ char smem[];
    const uint32_t sb = smem_u32(smem);
    const int tid  = threadIdx.x;
    const int wid  = tid >> 5;
    const int lane = tid & 31;
    const int wm   = wid & 1;
    const int wn   = wid >> 1;
    const int which = blockIdx.x >> 4;
    const int bm   = blockIdx.y * TM;
    const int bn   = (blockIdx.x & 15) * TN;
    const int NC   = KD / TKC;

    const __half* __restrict__ Bw = p.b[which];
    __half* __restrict__ Ch = p.c[which];

    const int mat  = lane >> 3;
    const int rin  = lane & 7;
    const int rowA = (mat & 1) * 8 + rin;
    const int kA   = mat >> 1;
    const int rowB = (mat >> 1) * 8 + rin;
    const int kB   = mat & 1;

    float acc[4][8][4];
    #pragma unroll
    for (int i = 0; i < 4; i++)
        #pragma unroll
        for (int j = 0; j < 8; j++)
            #pragma unroll
            for (int t = 0; t < 4; t++) acc[i][j][t] = 0.f;

    GEMM_MAINLOOP(A, Bw, bm, bn, KD, NC)

    #pragma unroll
    for (int mi = 0; mi < 4; mi++) {
        const int row0 = bm + wm * 64 + mi * 16 + (lane >> 2);
        #pragma unroll
        for (int f = 0; f < 8; f++) {
            const int n0 = bn + wn * 64 + f * 8 + (lane & 3) * 2;
            float* cc = acc[mi][f];
            #pragma unroll
            for (int hrow = 0; hrow < 2; hrow++) {
                const int row = row0 + hrow * 8;
                const size_t idx = (size_t)row * KD + n0;
                *(uint32_t*)(Ch + idx) = pack_h2(cc[hrow*2+0], cc[hrow*2+1]);
            }
        }
    }
}

// ---------------------------------------------------------------------------
// fp16 causal flash attention: 2-stage cp.async K/V pipeline, V via
// ldmatrix.trans (row-major V, no explicit transpose). Reversed CTA order.
// SMEM: Q 16KB @0; stage p at 16K + p*32K: K 16KB, V 16KB.
// ---------------------------------------------------------------------------
#define AT_Q   0u
#define AT_KV  16384u
#define KVSTG  32768u
#define ATT_SMEM (16384u + 2u * KVSTG)   // 81920

__global__ __launch_bounds__(128, 2) void attn_mma_kernel(
    const __half* __restrict__ Qg, const __half* __restrict__ Kg,
    const __half* __restrict__ Vg, __half* __restrict__ Og)
{
    extern __shared__ char smem[];
    const uint32_t sb = smem_u32(smem);
    const int tid  = threadIdx.x;
    const int wid  = tid >> 5;
    const int lane = tid & 31;
    const int bh   = blockIdx.y;
    const int b    = bh >> 4;
    const int h    = bh & 15;
    const int qt   = gridDim.x - 1 - blockIdx.x;
    const int q0   = qt * 64;

    const int mat  = lane >> 3;
    const int rin  = lane & 7;
    const int rowA = (mat & 1) * 8 + rin;
    const int kA   = mat >> 1;
    const int rowB = (mat >> 1) * 8 + rin;
    const int kB   = mat & 1;

    const size_t hoff = (size_t)h * KDH;

    // Q tile: 64 rows x 256B (regular vectorized copy)
    #pragma unroll
    for (int i = 0; i < 8; i++) {
        int idx = tid + i * 128;
        int r = idx >> 4, cc = idx & 15;
        uint32_t so = SWZ256((uint32_t)(r * 256 + cc * 16));
        size_t go = ((size_t)(b * KL + q0 + r)) * KD + hoff + cc * 8;
        *(uint4*)(smem + AT_Q + so) = *(const uint4*)(Qg + go);
    }

    // cp.async loader for one K/V stage (no commit inside)
    auto load_kv = [&](int kt, int p) {
        const int k0 = kt * 64;
        const uint32_t kb = sb + AT_KV + (uint32_t)p * KVSTG;
        #pragma unroll
        for (int i = 0; i < 8; i++) {
            int idx = tid + i * 128;
            int r = idx >> 4, cc = idx & 15;
            uint32_t so = SWZ256((uint32_t)(r * 256 + cc * 16));
            size_t go = ((size_t)(b * KL + k0 + r)) * KD + hoff + cc * 8;
            CP_ASYNC16(kb + so,          Kg + go);
            CP_ASYNC16(kb + 16384u + so, Vg + go);
        }
    };

    float ofrag[16][4];
    #pragma unroll
    for (int g = 0; g < 16; g++)
        #pragma unroll
        for (int t = 0; t < 4; t++) ofrag[g][t] = 0.f;

    float mrow0 = -1e30f, mrow1 = -1e30f;
    float lrow0 = 0.f, lrow1 = 0.f;

    const float scale = 0.08838834764831845f;

    load_kv(0, 0);
    CP_COMMIT();

    for (int kt = 0; kt <= qt; kt++) {
        const int p = kt & 1;
        if (kt < qt) load_kv(kt + 1, p ^ 1);
        CP_COMMIT();
        CP_WAIT1();        // tile kt resident
        __syncthreads();   // visible to all warps; also fences compute(kt-1)

        const uint32_t sK = sb + AT_KV + (uint32_t)p * KVSTG;
        const uint32_t sV = sK + 16384u;
        const int k0 = kt * 64;

        // S = Q K^T
        float sf[8][4];
        #pragma unroll
        for (int f = 0; f < 8; f++)
            #pragma unroll
            for (int t = 0; t < 4; t++) sf[f][t] = 0.f;

        #pragma unroll
        for (int ks = 0; ks < 8; ks++) {
            uint32_t qf[4], kf[4][4];
            {
                uint32_t off = SWZ256((uint32_t)((wid * 16 + rowA) * 256 + ks * 32 + kA * 16));
                LDSM_X4(qf, sb + AT_Q + off);
            }
            #pragma unroll
            for (int nj = 0; nj < 4; nj++) {
                uint32_t off = SWZ256((uint32_t)((nj * 16 + rowB) * 256 + ks * 32 + kB * 16));
                LDSM_X4(kf[nj], sK + off);
            }
            #pragma unroll
            for (int nj = 0; nj < 4; nj++)
                #pragma unroll
                for (int hf = 0; hf < 2; hf++)
                    mma_fp16(sf[nj*2+hf], qf, kf[nj][hf*2], kf[nj][hf*2+1]);
        }

        const int myrow = q0 + wid * 16 + (lane >> 2);
        #pragma unroll
        for (int f = 0; f < 8; f++) {
            #pragma unroll
            for (int t = 0; t < 4; t++) sf[f][t] *= scale;
            if (kt == qt) {
                int col = k0 + f * 8 + (lane & 3) * 2;
                if (col > myrow)     sf[f][0] = -1e30f;
                if (col + 1 > myrow) sf[f][1] = -1e30f;
                if (col > myrow + 8)     sf[f][2] = -1e30f;
                if (col + 1 > myrow + 8) sf[f][3] = -1e30f;
            }
        }

        float mx0 = -1e30f, mx1 = -1e30f;
        #pragma unroll
        for (int f = 0; f < 8; f++) {
            mx0 = fmaxf(mx0, fmaxf(sf[f][0], sf[f][1]));
            mx1 = fmaxf(mx1, fmaxf(sf[f][2], sf[f][3]));
        }
        #pragma unroll
        for (int d = 1; d <= 2; d <<= 1) {
            mx0 = fmaxf(mx0, __shfl_xor_sync(0xFFFFFFFFu, mx0, d));
            mx1 = fmaxf(mx1, __shfl_xor_sync(0xFFFFFFFFu, mx1, d));
        }
        float mnew0 = fmaxf(mrow0, mx0);
        float mnew1 = fmaxf(mrow1, mx1);
        float alpha0 = __expf(mrow0 - mnew0);
        float alpha1 = __expf(mrow1 - mnew1);
        mrow0 = mnew0; mrow1 = mnew1;

        float rs0 = 0.f, rs1 = 0.f;
        uint32_t pp[8][2];
        #pragma unroll
        for (int f = 0; f < 8; f++) {
            float p0 = __expf(sf[f][0] - mnew0);
            float p1 = __expf(sf[f][1] - mnew0);
            float p2 = __expf(sf[f][2] - mnew1);
            float p3 = __expf(sf[f][3] - mnew1);
            rs0 += p0 + p1; rs1 += p2 + p3;
            pp[f][0] = pack_h2(p0, p1);
            pp[f][1] = pack_h2(p2, p3);
        }
        #pragma unroll
        for (int d = 1; d <= 2; d <<= 1) {
            rs0 += __shfl_xor_sync(0xFFFFFFFFu, rs0, d);
            rs1 += __shfl_xor_sync(0xFFFFFFFFu, rs1, d);
        }
        lrow0 = lrow0 * alpha0 + rs0;
        lrow1 = lrow1 * alpha1 + rs1;

        #pragma unroll
        for (int g = 0; g < 16; g++) {
            ofrag[g][0] *= alpha0; ofrag[g][1] *= alpha0;
            ofrag[g][2] *= alpha1; ofrag[g][3] *= alpha1;
        }

        // O += P V using ldmatrix.trans on row-major V [key][dh]
        #pragma unroll
        for (int kk = 0; kk < 4; kk++) {
            uint32_t pa[4] = {pp[2*kk][0], pp[2*kk][1], pp[2*kk+1][0], pp[2*kk+1][1]};
            #pragma unroll
            for (int g = 0; g < 8; g++) {
                uint32_t vf[4];
                // matrix m: key = kk*16 + (m&1)*8 + rin ; dh bytes g*32 + (m>>1)*16
                uint32_t off = SWZ256((uint32_t)(
                    (kk * 16 + (mat & 1) * 8 + rin) * 256 + g * 32 + (mat >> 1) * 16));
                LDSM_X4_T(vf, sV + off);
                mma_fp16(ofrag[g*2+0], pa, vf[0], vf[1]);
                mma_fp16(ofrag[g*2+1], pa, vf[2], vf[3]);
            }
        }
        __syncthreads();   // all warps done with stage p before it is refilled
    }

    float inv0 = 1.0f / lrow0;
    float inv1 = 1.0f / lrow1;
    const int r0 = q0 + wid * 16 + (lane >> 2);
    #pragma unroll
    for (int g = 0; g < 16; g++) {
        int col = h * KDH + g * 8 + (lane & 3) * 2;
        size_t i0 = (size_t)(b * KL + r0) * KD + col;
        size_t i1 = (size_t)(b * KL + r0 + 8) * KD + col;
        *(uint32_t*)(Og + i0) = pack_h2(ofrag[g][0] * inv0, ofrag[g][1] * inv0);
        *(uint32_t*)(Og + i1) = pack_h2(ofrag[g][2] * inv1, ofrag[g][3] * inv1);
    }
}

// ---------------------------------------------------------------------------
// kernel_launch — dual-stream fork/join
// ---------------------------------------------------------------------------
extern "C" void kernel_launch(void* const* d_in, const int* in_sizes, int n_in,
                              void* d_out, int out_size)
{
    const float* x    = (const float*)d_in[0];
    const float* ln1  = (const float*)d_in[2];
    const float* wq   = (const float*)d_in[3];
    const float* wk   = (const float*)d_in[4];
    const float* wv   = (const float*)d_in[5];
    const float* wo   = (const float*)d_in[6];
    const float* ln2  = (const float*)d_in[7];
    const float* wup  = (const float*)d_in[8];
    const float* wdn  = (const float*)d_in[9];
    float* out = (float*)d_out;

    __half *wqh,*wkh,*wvh,*woh,*wuh,*wdh,*hh,*qq,*kk,*vv,*oo,*uu;
    cudaGetSymbolAddress((void**)&wqh, g_wq);
    cudaGetSymbolAddress((void**)&wkh, g_wk);
    cudaGetSymbolAddress((void**)&wvh, g_wv);
    cudaGetSymbolAddress((void**)&woh, g_wo);
    cudaGetSymbolAddress((void**)&wuh, g_wu);
    cudaGetSymbolAddress((void**)&wdh, g_wd);
    cudaGetSymbolAddress((void**)&hh, g_hh);
    cudaGetSymbolAddress((void**)&qq, g_qq);
    cudaGetSymbolAddress((void**)&kk, g_kk);
    cudaGetSymbolAddress((void**)&vv, g_vv);
    cudaGetSymbolAddress((void**)&oo, g_oo);
    cudaGetSymbolAddress((void**)&uu, g_uu);

    cudaFuncSetAttribute(gemm_mma_kernel<0>, cudaFuncAttributeMaxDynamicSharedMemorySize, GEMM_SMEM);
    cudaFuncSetAttribute(gemm_mma_kernel<1>, cudaFuncAttributeMaxDynamicSharedMemorySize, GEMM_SMEM);
    cudaFuncSetAttribute(gemm_mma_kernel<2>, cudaFuncAttributeMaxDynamicSharedMemorySize, GEMM_SMEM);
    cudaFuncSetAttribute(gemm_mma_kernel<3>, cudaFuncAttributeMaxDynamicSharedMemorySize, GEMM_SMEM);
    cudaFuncSetAttribute(gemm_qkv_kernel, cudaFuncAttributeMaxDynamicSharedMemorySize, GEMM_SMEM);
    cudaFuncSetAttribute(attn_mma_kernel, cudaFuncAttributeMaxDynamicSharedMemorySize, ATT_SMEM);

    dim3 blk(256);
    dim3 gblk(GTHREADS);
    dim3 gqkv3(3 * (KD / TN), KM / TM);   // 48 x 32
    dim3 gd(KD / TN, KM / TM);            // 16 x 32
    dim3 gup(KDFF / TN, KM / TM);         // 64 x 32

    const int n4  = KD * KD / 4;
    const int g4  = n4 / 1024;
    const int n4f = KDFF * KD / 4;
    const int g4f = n4f / 1024;

    QKVPtrs p;
    p.b[0] = wqh; p.b[1] = wkh; p.b[2] = wvh;
    p.c[0] = qq;  p.c[1] = kk;  p.c[2] = vv;

    cudaStream_t s2;
    cudaStreamCreateWithFlags(&s2, cudaStreamNonBlocking);
    cudaEvent_t eF1, eJ1, eF2, eJ2;
    cudaEventCreateWithFlags(&eF1, cudaEventDisableTiming);
    cudaEventCreateWithFlags(&eJ1, cudaEventDisableTiming);
    cudaEventCreateWithFlags(&eF2, cudaEventDisableTiming);
    cudaEventCreateWithFlags(&eJ2, cudaEventDisableTiming);

    // ---- fork 1: rmsnorm on main, qkv weight cvts on s2 ----
    cudaEventRecord(eF1, 0);
    cudaStreamWaitEvent(s2, eF1, 0);

    rmsnorm_kernel<<<KM, blk>>>(x, ln1, hh);
    cvt_kernel<<<g4, blk, 0, s2>>>(wq, wqh, n4);
    cvt_kernel<<<g4, blk, 0, s2>>>(wk, wkh, n4);
    cvt_kernel<<<g4, blk, 0, s2>>>(wv, wvh, n4);

    cudaEventRecord(eJ1, s2);
    cudaStreamWaitEvent(0, eJ1, 0);

    // ---- fork 2: qkv GEMM + attention on main, remaining cvts on s2 ----
    cudaEventRecord(eF2, 0);
    cudaStreamWaitEvent(s2, eF2, 0);

    gemm_qkv_kernel<<<gqkv3, gblk, GEMM_SMEM>>>(hh, p);
    dim3 gattn(KL / 64, KB * KH);
    attn_mma_kernel<<<gattn, dim3(128), ATT_SMEM>>>(qq, kk, vv, oo);

    cvt_kernel<<<g4, blk, 0, s2>>>(wo, woh, n4);
    cvt_kernel<<<g4f, blk, 0, s2>>>(wup, wuh, n4f);
    cvt_kernel<<<g4f, blk, 0, s2>>>(wdn, wdh, n4f);

    cudaEventRecord(eJ2, s2);
    cudaStreamWaitEvent(0, eJ2, 0);

    // ---- tail on main stream ----
    gemm_mma_kernel<2><<<gd, gblk, GEMM_SMEM>>>(oo, woh, out, x, nullptr, KD, KD);
    rmsnorm_kernel<<<KM, blk>>>(out, ln2, hh);
    gemm_mma_kernel<1><<<gup, gblk, GEMM_SMEM>>>(hh, wuh, nullptr, nullptr, uu, KDFF, KD);
    gemm_mma_kernel<2><<<gd, gblk, GEMM_SMEM>>>(uu, wdh, out, out, nullptr, KD, KDFF);
}